// round 7
// baseline (speedup 1.0000x reference)
#include <cuda_runtime.h>
#include <cuda_fp16.h>
#include <math.h>

// N=50000, E=800000, IN=128, H=8, EMB=32, OUT=16, EF=7
#define MAXN 50000
#define MAXE 800000
#define INF_DIM 128
#define NCOLS 256          // wcat cols: WqA(64) | WkA(64) | Wv(128)

typedef unsigned long long u64t;

__device__ __forceinline__ u64t dup2(float x) {
    u64t r; asm("mov.b64 %0, {%1, %1};" : "=l"(r) : "f"(x)); return r;
}
__device__ __forceinline__ u64t pk2(float2 f) {
    u64t r; asm("mov.b64 %0, {%1, %2};" : "=l"(r) : "f"(f.x), "f"(f.y)); return r;
}
__device__ __forceinline__ u64t ffma2(u64t a, u64t b, u64t c) {
    u64t d; asm("fma.rn.f32x2 %0, %1, %2, %3;" : "=l"(d) : "l"(a), "l"(b), "l"(c)); return d;
}
__device__ __forceinline__ u64t fmul2(u64t a, u64t b) {
    u64t d; asm("mul.rn.f32x2 %0, %1, %2;" : "=l"(d) : "l"(a), "l"(b)); return d;
}
__device__ __forceinline__ float2 unpack2(u64t a) {
    float2 f; asm("mov.b64 {%0, %1}, %2;" : "=f"(f.x), "=f"(f.y) : "l"(a)); return f;
}

// -------- device scratch --------
__device__ int    g_deg[MAXN];
__device__ int    g_cnt[MAXN];
__device__ int    g_offs[MAXN + 1];
__device__ int    g_bsum[64];
__device__ int    g_bbase[64];
__device__ int    g_done;
__device__ int    g_ssrc[MAXE];                        // CSR-permuted src
__device__ float  g_ebond[(size_t)MAXE * 8];           // CSR-permuted bond(7)+1.0
__device__ __half g_aqh[(size_t)MAXN * 64];            // Aq fp16, head-major [N][H][8]
__device__ __half g_akh[(size_t)MAXN * 64];            // Ak fp16, head-major
__device__ __half g_vh [(size_t)MAXN * 128];           // v  fp16 [N][128]
__device__ float  g_wcat[INF_DIM * NCOLS];
__device__ float  g_wefc8[8 * 128];

// ---------------- kernel 1: degree count + weight prep (fused, independent) ----------------
__global__ void deg_prep_kernel(const int* __restrict__ dst, int E,
                                const float* __restrict__ Wq, const float* __restrict__ Wk,
                                const float* __restrict__ Wv, const float* __restrict__ Wek,
                                const float* __restrict__ bek, const float* __restrict__ Wefc,
                                const float* __restrict__ befc)
{
    int idx = blockIdx.x * blockDim.x + threadIdx.x;
    if (idx < E) atomicAdd(&g_deg[dst[idx]], 1);

    if (idx < INF_DIM * NCOLS) {
        int i = idx >> 8;
        int c = idx & 255;
        float r;
        if (c < 128) {
            const float* Wx = (c < 64) ? Wq : Wk;
            int cc = c & 63;
            int h = cc >> 3, f = cc & 7;
            const float* ekrow = (f < 7) ? (Wek + f * 256) : bek;
            float acc = 0.f;
            #pragma unroll
            for (int m = 0; m < 32; ++m)
                acc = fmaf(Wx[i * 256 + h * 32 + m], ekrow[h * 32 + m], acc);
            r = acc;
        } else {
            r = Wv[i * 128 + (c - 128)];
        }
        g_wcat[idx] = r;
    }
    if (idx < 8 * 128) {
        int f = idx >> 7, c = idx & 127;
        g_wefc8[idx] = (f < 7) ? Wefc[f * 128 + c] : befc[c];
    }
}

// ---------------- kernel 2: one-pass scan ----------------
// 49 blocks: local scan -> g_offs (local-exclusive) + g_bsum; block 0 spins
// for all publishes, then computes g_bbase + g_offs[n]. Also zeroes g_cnt.
__global__ void scan1p_kernel(int n, int nblocks)
{
    __shared__ int wsum[32];
    int t = threadIdx.x, lane = t & 31, wid = t >> 5;
    int i = blockIdx.x * 1024 + t;
    int v = (i < n) ? g_deg[i] : 0;
    if (i < n) g_cnt[i] = 0;
    int x = v;
    #pragma unroll
    for (int d = 1; d < 32; d <<= 1) {
        int y = __shfl_up_sync(0xffffffffu, x, d);
        if (lane >= d) x += y;
    }
    if (lane == 31) wsum[wid] = x;
    __syncthreads();
    if (wid == 0) {
        int y = wsum[lane];
        #pragma unroll
        for (int d = 1; d < 32; d <<= 1) {
            int z = __shfl_up_sync(0xffffffffu, y, d);
            if (lane >= d) y += z;
        }
        wsum[lane] = y;
    }
    __syncthreads();
    int excl = ((wid > 0) ? wsum[wid - 1] : 0) + (x - v);
    if (i < n) g_offs[i] = excl;
    if (t == 1023) {
        g_bsum[blockIdx.x] = wsum[31];
        __threadfence();
        atomicAdd(&g_done, 1);
    }

    if (blockIdx.x == 0) {
        if (t == 0) {
            while (*(volatile int*)&g_done < nblocks) { }
        }
        __syncthreads();
        __threadfence();
        // exclusive scan of g_bsum[0..nblocks) using the first two warps
        __shared__ int bs[64];
        if (t < 64) bs[t] = (t < nblocks) ? g_bsum[t] : 0;
        __syncthreads();
        if (t < 64) {
            int vv = bs[t];
            int xx = vv;
            #pragma unroll
            for (int d = 1; d < 32; d <<= 1) {
                int y = __shfl_up_sync(0xffffffffu, xx, d);
                if (lane >= d) xx += y;
            }
            // add warp0 total to warp1
            __shared__ int w0tot;
            if (t == 31) w0tot = xx;
            __syncthreads();
            if (t >= 32) xx += w0tot;
            if (t < nblocks) g_bbase[t] = xx - vv;
        }
        if (t == 0) g_offs[n] = g_bsum[n >> 10];  // end(last) = bsum+bbase = E
    }
}

// ---------------- kernel 3: GEMM + scatter fused (block-parallel) ----------------
#define GBM 128
#define GBN 128
#define GBK 16
#define NGEMMB 782   // 2 * ceil(50000/128)
__global__ void __launch_bounds__(256) gemm_scatter_kernel(
    const float* __restrict__ A, int M,
    const int* __restrict__ src, const int* __restrict__ dst,
    const float* __restrict__ bond, int E)
{
    if (blockIdx.x >= NGEMMB) {
        // ---- scatter part ----
        int e = (blockIdx.x - NGEMMB) * 256 + threadIdx.x;
        if (e >= E) return;
        int d = dst[e];
        int p = g_offs[d] + g_bbase[d >> 10] + atomicAdd(&g_cnt[d], 1);
        g_ssrc[p] = src[e];
        const float* bp = bond + (size_t)e * 7;
        float b0 = __ldg(bp + 0), b1 = __ldg(bp + 1), b2 = __ldg(bp + 2), b3 = __ldg(bp + 3);
        float b4 = __ldg(bp + 4), b5 = __ldg(bp + 5), b6 = __ldg(bp + 6);
        *(float4*)&g_ebond[(size_t)p * 8]     = make_float4(b0, b1, b2, b3);
        *(float4*)&g_ebond[(size_t)p * 8 + 4] = make_float4(b4, b5, b6, 1.0f);
        return;
    }

    // ---- GEMM part: C[M,256] = A[M,128] @ g_wcat, fp16 epilogue ----
    __shared__ float As[GBK][GBM];
    __shared__ float Bs[GBK][GBN];
    int tid = threadIdx.x;
    int brow = (blockIdx.x >> 1) * GBM;
    int bcol = (blockIdx.x & 1) * GBN;
    int ty = tid >> 4, tx = tid & 15;
    u64t acc2[4][8];
    #pragma unroll
    for (int m = 0; m < 4; ++m)
        #pragma unroll
        for (int j = 0; j < 8; ++j) acc2[m][j] = 0ull;

    for (int k0 = 0; k0 < INF_DIM; k0 += GBK) {
        #pragma unroll
        for (int i = 0; i < 2; ++i) {
            int q = tid * 2 + i;
            int r = q >> 2;
            int kq = (q & 3) * 4;
            int gr = brow + r;
            float4 a4 = (gr < M) ? *(const float4*)(&A[(size_t)gr * INF_DIM + k0 + kq])
                                 : make_float4(0.f, 0.f, 0.f, 0.f);
            As[kq + 0][r] = a4.x; As[kq + 1][r] = a4.y;
            As[kq + 2][r] = a4.z; As[kq + 3][r] = a4.w;
        }
        #pragma unroll
        for (int i = 0; i < 2; ++i) {
            int q = tid + i * 256;
            int kk = q >> 5;
            int c = (q & 31) * 4;
            *(float4*)(&Bs[kk][c]) = *(const float4*)(&g_wcat[(k0 + kk) * NCOLS + bcol + c]);
        }
        __syncthreads();
        #pragma unroll
        for (int kk = 0; kk < GBK; ++kk) {
            u64t ar2[4];
            ulonglong2 au0 = *(ulonglong2*)&As[kk][ty * 8];
            ulonglong2 au1 = *(ulonglong2*)&As[kk][ty * 8 + 4];
            ar2[0] = au0.x; ar2[1] = au0.y; ar2[2] = au1.x; ar2[3] = au1.y;
            float br[8];
            *(float4*)&br[0] = *(float4*)&Bs[kk][tx * 8];
            *(float4*)&br[4] = *(float4*)&Bs[kk][tx * 8 + 4];
            u64t brd[8];
            #pragma unroll
            for (int j = 0; j < 8; ++j) brd[j] = dup2(br[j]);
            #pragma unroll
            for (int m = 0; m < 4; ++m)
                #pragma unroll
                for (int j = 0; j < 8; ++j)
                    acc2[m][j] = ffma2(ar2[m], brd[j], acc2[m][j]);
        }
        __syncthreads();
    }

    // fp16 epilogue. col routing: [0,64)->aqh, [64,128)->akh, [128,256)->vh
    int gcol = bcol + tx * 8;
    __half* dsth; int cstart; int stride;
    if (gcol < 64)        { dsth = g_aqh; cstart = gcol;       stride = 64; }
    else if (gcol < 128)  { dsth = g_akh; cstart = gcol - 64;  stride = 64; }
    else                  { dsth = g_vh;  cstart = gcol - 128; stride = 128; }

    #pragma unroll
    for (int m = 0; m < 4; ++m) {
        int gr0 = brow + ty * 8 + 2 * m;
        float2 c0 = unpack2(acc2[m][0]), c1 = unpack2(acc2[m][1]);
        float2 c2 = unpack2(acc2[m][2]), c3 = unpack2(acc2[m][3]);
        float2 c4 = unpack2(acc2[m][4]), c5 = unpack2(acc2[m][5]);
        float2 c6 = unpack2(acc2[m][6]), c7 = unpack2(acc2[m][7]);
        if (gr0 < M) {
            __half2 h0 = __floats2half2_rn(c0.x, c1.x);
            __half2 h1 = __floats2half2_rn(c2.x, c3.x);
            __half2 h2 = __floats2half2_rn(c4.x, c5.x);
            __half2 h3 = __floats2half2_rn(c6.x, c7.x);
            uint4 o;
            o.x = *(unsigned*)&h0; o.y = *(unsigned*)&h1;
            o.z = *(unsigned*)&h2; o.w = *(unsigned*)&h3;
            *(uint4*)(dsth + (size_t)gr0 * stride + cstart) = o;
        }
        if (gr0 + 1 < M) {
            __half2 h0 = __floats2half2_rn(c0.y, c1.y);
            __half2 h1 = __floats2half2_rn(c2.y, c3.y);
            __half2 h2 = __floats2half2_rn(c4.y, c5.y);
            __half2 h3 = __floats2half2_rn(c6.y, c7.y);
            uint4 o;
            o.x = *(unsigned*)&h0; o.y = *(unsigned*)&h1;
            o.z = *(unsigned*)&h2; o.w = *(unsigned*)&h3;
            *(uint4*)(dsth + (size_t)(gr0 + 1) * stride + cstart) = o;
        }
    }
}

// ---------------- kernel 4: fused edge attention + aggregation ----------------
// One warp per dst node. Lane l: head h=l>>2, channels ch=4l..4l+3.
// Shfl-free logit (each lane reads its head's full 8 aq values, 16B fp16).
// Depth-1 prefetch on gathers, depth-2 on the src index.
__global__ void __launch_bounds__(256) edge_attn_kernel(
    const float* __restrict__ bias, float* __restrict__ out, int n)
{
    int warp = blockIdx.x * 8 + (threadIdx.x >> 5);
    if (warp >= n) return;
    int l = threadIdx.x & 31;
    int h = l >> 2;
    int ch = 4 * l;
    int start = g_offs[warp]     + g_bbase[warp >> 10];
    int end   = g_offs[warp + 1] + g_bbase[(warp + 1) >> 10];

    // ak for this head: 8 fp16 -> fp32 (once per warp)
    float ak0, ak1, ak2, ak3, ak4, ak5, ak6, ak7;
    {
        uint4 a = *(const uint4*)(g_akh + (size_t)warp * 64 + h * 8);
        float2 f0 = __half22float2(*(__half2*)&a.x);
        float2 f1 = __half22float2(*(__half2*)&a.y);
        float2 f2 = __half22float2(*(__half2*)&a.z);
        float2 f3 = __half22float2(*(__half2*)&a.w);
        ak0 = f0.x; ak1 = f0.y; ak2 = f1.x; ak3 = f1.y;
        ak4 = f2.x; ak5 = f2.y; ak6 = f3.x; ak7 = f3.y;
    }

    u64t wef2[8][2];   // packed channel pairs per bond-feature row (row 7 = befc)
    #pragma unroll
    for (int f = 0; f < 8; ++f) {
        ulonglong2 w = *(const ulonglong2*)(&g_wefc8[f * 128 + ch]);
        wef2[f][0] = w.x; wef2[f][1] = w.y;
    }

    float denom = 0.f;
    u64t a2[2] = {0ull, 0ull};

    int deg = end - start;
    if (deg > 0) {
        int s_c = __ldg(&g_ssrc[start]);
        int s_nn = (deg > 1) ? __ldg(&g_ssrc[start + 1]) : 0;
        uint4  aq_n = *(const uint4*)(g_aqh + (size_t)s_c * 64 + h * 8);
        uint2  v_n  = *(const uint2*)(g_vh  + (size_t)s_c * 128 + ch);
        float4 bx_n = *(const float4*)&g_ebond[(size_t)start * 8];
        float4 by_n = *(const float4*)&g_ebond[(size_t)start * 8 + 4];

        for (int p = 0; p < deg; ++p) {
            uint4 aqr = aq_n; uint2 vr = v_n;
            float4 bx = bx_n, by = by_n;
            int s_pf = s_nn;
            if (p + 1 < deg) {
                aq_n = *(const uint4*)(g_aqh + (size_t)s_pf * 64 + h * 8);
                v_n  = *(const uint2*)(g_vh  + (size_t)s_pf * 128 + ch);
                bx_n = *(const float4*)&g_ebond[(size_t)(start + p + 1) * 8];
                by_n = *(const float4*)&g_ebond[(size_t)(start + p + 1) * 8 + 4];
            }
            if (p + 2 < deg) s_nn = __ldg(&g_ssrc[start + p + 2]);

            // logit: sum_f bond_f * (aq_f + ak_f), f=7 slot has bond=1
            float2 q0 = __half22float2(*(__half2*)&aqr.x);
            float2 q1 = __half22float2(*(__half2*)&aqr.y);
            float2 q2 = __half22float2(*(__half2*)&aqr.z);
            float2 q3 = __half22float2(*(__half2*)&aqr.w);
            float pA = (q3.y + ak7);
            pA = fmaf(bx.x, q0.x + ak0, pA);
            pA = fmaf(bx.z, q1.x + ak2, pA);
            pA = fmaf(by.x, q2.x + ak4, pA);
            float pB = 0.f;
            pB = fmaf(bx.y, q0.y + ak1, pB);
            pB = fmaf(bx.w, q1.y + ak3, pB);
            pB = fmaf(by.y, q2.y + ak5, pB);
            pB = fmaf(by.z, q3.x + ak6, pB);
            float w = __expf(pA + pB);
            denom += w;

            // ef = bond @ Wefc + befc (packed channel pairs, FFMA2)
            u64t d0 = dup2(bx.x), d1 = dup2(bx.y), d2 = dup2(bx.z), d3 = dup2(bx.w);
            u64t d4 = dup2(by.x), d5 = dup2(by.y), d6 = dup2(by.z);
            u64t ef0 = wef2[7][0], ef1 = wef2[7][1];
            ef0 = ffma2(d0, wef2[0][0], ef0); ef1 = ffma2(d0, wef2[0][1], ef1);
            ef0 = ffma2(d1, wef2[1][0], ef0); ef1 = ffma2(d1, wef2[1][1], ef1);
            ef0 = ffma2(d2, wef2[2][0], ef0); ef1 = ffma2(d2, wef2[2][1], ef1);
            ef0 = ffma2(d3, wef2[3][0], ef0); ef1 = ffma2(d3, wef2[3][1], ef1);
            ef0 = ffma2(d4, wef2[4][0], ef0); ef1 = ffma2(d4, wef2[4][1], ef1);
            ef0 = ffma2(d5, wef2[5][0], ef0); ef1 = ffma2(d5, wef2[5][1], ef1);
            ef0 = ffma2(d6, wef2[6][0], ef0); ef1 = ffma2(d6, wef2[6][1], ef1);

            // acc += (w * v) * ef   (v fp16 -> fp32)
            float2 v01 = __half22float2(*(__half2*)&vr.x);
            float2 v23 = __half22float2(*(__half2*)&vr.y);
            u64t wd = dup2(w);
            a2[0] = ffma2(fmul2(wd, pk2(v01)), ef0, a2[0]);
            a2[1] = ffma2(fmul2(wd, pk2(v23)), ef1, a2[1]);
        }
    }

    float4 b4 = *(const float4*)(&bias[ch]);
    float4 r;
    if (deg > 0) {
        float inv = 1.0f / denom;
        float2 lo = unpack2(a2[0]), hi = unpack2(a2[1]);
        r.x = fmaf(lo.x, inv, b4.x);
        r.y = fmaf(lo.y, inv, b4.y);
        r.z = fmaf(hi.x, inv, b4.z);
        r.w = fmaf(hi.y, inv, b4.w);
    } else {
        r = b4;
    }
    *(float4*)(&out[(size_t)warp * 128 + ch]) = r;
}

// ---------------- host launcher ----------------
extern "C" void kernel_launch(void* const* d_in, const int* in_sizes, int n_in,
                              void* d_out, int out_size)
{
    const float* feat = (const float*)d_in[0];
    const float* bond = (const float*)d_in[1];
    const int*   src  = (const int*)d_in[2];
    const int*   dst  = (const int*)d_in[3];
    const float* Wq   = (const float*)d_in[4];
    const float* Wk   = (const float*)d_in[5];
    const float* Wv   = (const float*)d_in[6];
    const float* Wek  = (const float*)d_in[7];
    const float* bek  = (const float*)d_in[8];
    const float* Wefc = (const float*)d_in[9];
    const float* befc = (const float*)d_in[10];
    const float* bias = (const float*)d_in[11];
    float* out = (float*)d_out;

    int N = in_sizes[0] / INF_DIM;   // 50000
    int E = in_sizes[2];             // 800000
    int nb = (N + 1023) / 1024;      // 49

    void* deg_ptr = nullptr; void* done_ptr = nullptr;
    cudaGetSymbolAddress(&deg_ptr, g_deg);
    cudaGetSymbolAddress(&done_ptr, g_done);
    cudaMemsetAsync(deg_ptr, 0, (size_t)N * sizeof(int));
    cudaMemsetAsync(done_ptr, 0, sizeof(int));

    // kernel 1: degree count + weight prep
    deg_prep_kernel<<<(E + 255) / 256, 256>>>(dst, E, Wq, Wk, Wv, Wek, bek, Wefc, befc);
    // kernel 2: one-pass scan
    scan1p_kernel<<<nb, 1024>>>(N, nb);
    // kernel 3: GEMM (blocks 0..781) + scatter (remaining blocks)
    int nscatterb = (E + 255) / 256;
    gemm_scatter_kernel<<<NGEMMB + nscatterb, 256>>>(feat, N, src, dst, bond, E);
    // kernel 4: fused edge attention + softmax + aggregation  (ncu profiles this one)
    edge_attn_kernel<<<(N + 7) / 8, 256>>>(bias, out, N);
}

// round 8
// speedup vs baseline: 1.3816x; 1.3816x over previous
#include <cuda_runtime.h>
#include <cuda_fp16.h>
#include <math.h>

// N=50000, E=800000, IN=128, H=8, EMB=32, OUT=16, EF=7
#define MAXN 50000
#define MAXE 800000
#define INF_DIM 128
#define NCOLS 256          // wcat cols: WqA(64) | WkA(64) | Wv(128)

typedef unsigned long long u64t;

__device__ __forceinline__ u64t dup2(float x) {
    u64t r; asm("mov.b64 %0, {%1, %1};" : "=l"(r) : "f"(x)); return r;
}
__device__ __forceinline__ u64t pk2(float2 f) {
    u64t r; asm("mov.b64 %0, {%1, %2};" : "=l"(r) : "f"(f.x), "f"(f.y)); return r;
}
__device__ __forceinline__ u64t ffma2(u64t a, u64t b, u64t c) {
    u64t d; asm("fma.rn.f32x2 %0, %1, %2, %3;" : "=l"(d) : "l"(a), "l"(b), "l"(c)); return d;
}
__device__ __forceinline__ u64t fmul2(u64t a, u64t b) {
    u64t d; asm("mul.rn.f32x2 %0, %1, %2;" : "=l"(d) : "l"(a), "l"(b)); return d;
}
__device__ __forceinline__ float2 unpack2(u64t a) {
    float2 f; asm("mov.b64 {%0, %1}, %2;" : "=f"(f.x), "=f"(f.y) : "l"(a)); return f;
}

// -------- device scratch --------
// g_dcz: [0,MAXN)=deg, [MAXN,2MAXN)=cnt, [2MAXN]=done flag  (one memset)
__device__ int    g_dcz[2 * MAXN + 1];
__device__ int    g_offs[MAXN + 1];
__device__ int    g_bsum[64];
__device__ int    g_bbase[64];
__device__ int    g_ssrc[MAXE];                        // CSR-permuted src
__device__ float  g_ebond[(size_t)MAXE * 8];           // CSR-permuted bond(7)+1.0
__device__ __half g_aqh[(size_t)MAXN * 64];            // Aq fp16, head-major [N][H][8]
__device__ __half g_akh[(size_t)MAXN * 64];            // Ak fp16, head-major
__device__ __half g_vh [(size_t)MAXN * 128];           // v  fp16 [N][128]
__device__ float  g_wcat[INF_DIM * NCOLS];

// ---------------- kernel 1: degree count + wcat prep (fused, independent) ----------------
__global__ void deg_prep_kernel(const int* __restrict__ dst, int E,
                                const float* __restrict__ Wq, const float* __restrict__ Wk,
                                const float* __restrict__ Wv, const float* __restrict__ Wek,
                                const float* __restrict__ bek)
{
    int idx = blockIdx.x * blockDim.x + threadIdx.x;
    if (idx < E) atomicAdd(&g_dcz[dst[idx]], 1);

    if (idx < INF_DIM * NCOLS) {
        int i = idx >> 8;
        int c = idx & 255;
        float r;
        if (c < 128) {
            const float* Wx = (c < 64) ? Wq : Wk;
            int cc = c & 63;
            int h = cc >> 3, f = cc & 7;
            const float* ekrow = (f < 7) ? (Wek + f * 256) : bek;
            float acc = 0.f;
            #pragma unroll
            for (int m = 0; m < 32; ++m)
                acc = fmaf(Wx[i * 256 + h * 32 + m], ekrow[h * 32 + m], acc);
            r = acc;
        } else {
            r = Wv[i * 128 + (c - 128)];
        }
        g_wcat[idx] = r;
    }
}

// ---------------- kernel 2 (side stream): GEMM, fp16 epilogue ----------------
#define GBM 128
#define GBN 128
#define GBK 16
__global__ void __launch_bounds__(256) sgemm_kernel(const float* __restrict__ A, int M)
{
    __shared__ float As[GBK][GBM];
    __shared__ float Bs[GBK][GBN];
    int tid = threadIdx.x;
    int brow = (blockIdx.x >> 1) * GBM;
    int bcol = (blockIdx.x & 1) * GBN;
    int ty = tid >> 4, tx = tid & 15;
    u64t acc2[4][8];
    #pragma unroll
    for (int m = 0; m < 4; ++m)
        #pragma unroll
        for (int j = 0; j < 8; ++j) acc2[m][j] = 0ull;

    for (int k0 = 0; k0 < INF_DIM; k0 += GBK) {
        #pragma unroll
        for (int i = 0; i < 2; ++i) {
            int q = tid * 2 + i;
            int r = q >> 2;
            int kq = (q & 3) * 4;
            int gr = brow + r;
            float4 a4 = (gr < M) ? *(const float4*)(&A[(size_t)gr * INF_DIM + k0 + kq])
                                 : make_float4(0.f, 0.f, 0.f, 0.f);
            As[kq + 0][r] = a4.x; As[kq + 1][r] = a4.y;
            As[kq + 2][r] = a4.z; As[kq + 3][r] = a4.w;
        }
        #pragma unroll
        for (int i = 0; i < 2; ++i) {
            int q = tid + i * 256;
            int kk = q >> 5;
            int c = (q & 31) * 4;
            *(float4*)(&Bs[kk][c]) = *(const float4*)(&g_wcat[(k0 + kk) * NCOLS + bcol + c]);
        }
        __syncthreads();
        #pragma unroll
        for (int kk = 0; kk < GBK; ++kk) {
            u64t ar2[4];
            ulonglong2 au0 = *(ulonglong2*)&As[kk][ty * 8];
            ulonglong2 au1 = *(ulonglong2*)&As[kk][ty * 8 + 4];
            ar2[0] = au0.x; ar2[1] = au0.y; ar2[2] = au1.x; ar2[3] = au1.y;
            float br[8];
            *(float4*)&br[0] = *(float4*)&Bs[kk][tx * 8];
            *(float4*)&br[4] = *(float4*)&Bs[kk][tx * 8 + 4];
            u64t brd[8];
            #pragma unroll
            for (int j = 0; j < 8; ++j) brd[j] = dup2(br[j]);
            #pragma unroll
            for (int m = 0; m < 4; ++m)
                #pragma unroll
                for (int j = 0; j < 8; ++j)
                    acc2[m][j] = ffma2(ar2[m], brd[j], acc2[m][j]);
        }
        __syncthreads();
    }

    // fp16 epilogue: [0,64)->aqh, [64,128)->akh, [128,256)->vh
    int gcol = bcol + tx * 8;
    __half* dsth; int cstart; int stride;
    if (gcol < 64)        { dsth = g_aqh; cstart = gcol;       stride = 64; }
    else if (gcol < 128)  { dsth = g_akh; cstart = gcol - 64;  stride = 64; }
    else                  { dsth = g_vh;  cstart = gcol - 128; stride = 128; }

    #pragma unroll
    for (int m = 0; m < 4; ++m) {
        int gr0 = brow + ty * 8 + 2 * m;
        float2 c0 = unpack2(acc2[m][0]), c1 = unpack2(acc2[m][1]);
        float2 c2 = unpack2(acc2[m][2]), c3 = unpack2(acc2[m][3]);
        float2 c4 = unpack2(acc2[m][4]), c5 = unpack2(acc2[m][5]);
        float2 c6 = unpack2(acc2[m][6]), c7 = unpack2(acc2[m][7]);
        if (gr0 < M) {
            __half2 h0 = __floats2half2_rn(c0.x, c1.x);
            __half2 h1 = __floats2half2_rn(c2.x, c3.x);
            __half2 h2 = __floats2half2_rn(c4.x, c5.x);
            __half2 h3 = __floats2half2_rn(c6.x, c7.x);
            uint4 o;
            o.x = *(unsigned*)&h0; o.y = *(unsigned*)&h1;
            o.z = *(unsigned*)&h2; o.w = *(unsigned*)&h3;
            *(uint4*)(dsth + (size_t)gr0 * stride + cstart) = o;
        }
        if (gr0 + 1 < M) {
            __half2 h0 = __floats2half2_rn(c0.y, c1.y);
            __half2 h1 = __floats2half2_rn(c2.y, c3.y);
            __half2 h2 = __floats2half2_rn(c4.y, c5.y);
            __half2 h3 = __floats2half2_rn(c6.y, c7.y);
            uint4 o;
            o.x = *(unsigned*)&h0; o.y = *(unsigned*)&h1;
            o.z = *(unsigned*)&h2; o.w = *(unsigned*)&h3;
            *(uint4*)(dsth + (size_t)(gr0 + 1) * stride + cstart) = o;
        }
    }
}

// ---------------- kernel 3: one-pass scan ----------------
__global__ void scan1p_kernel(int n, int nblocks)
{
    __shared__ int wsum[32];
    int t = threadIdx.x, lane = t & 31, wid = t >> 5;
    int i = blockIdx.x * 1024 + t;
    int v = (i < n) ? g_dcz[i] : 0;
    int x = v;
    #pragma unroll
    for (int d = 1; d < 32; d <<= 1) {
        int y = __shfl_up_sync(0xffffffffu, x, d);
        if (lane >= d) x += y;
    }
    if (lane == 31) wsum[wid] = x;
    __syncthreads();
    if (wid == 0) {
        int y = wsum[lane];
        #pragma unroll
        for (int d = 1; d < 32; d <<= 1) {
            int z = __shfl_up_sync(0xffffffffu, y, d);
            if (lane >= d) y += z;
        }
        wsum[lane] = y;
    }
    __syncthreads();
    int excl = ((wid > 0) ? wsum[wid - 1] : 0) + (x - v);
    if (i < n) g_offs[i] = excl;
    if (t == 1023) {
        g_bsum[blockIdx.x] = wsum[31];
        __threadfence();
        atomicAdd(&g_dcz[2 * MAXN], 1);
    }

    if (blockIdx.x == 0) {
        if (t == 0) {
            while (*(volatile int*)&g_dcz[2 * MAXN] < nblocks) { }
        }
        __syncthreads();
        __threadfence();
        __shared__ int bs[64];
        __shared__ int w0tot;
        if (t < 64) bs[t] = (t < nblocks) ? g_bsum[t] : 0;
        __syncthreads();
        if (t < 64) {
            int vv = bs[t];
            int xx = vv;
            #pragma unroll
            for (int d = 1; d < 32; d <<= 1) {
                int y = __shfl_up_sync(0xffffffffu, xx, d);
                if (lane >= d) xx += y;
            }
            if (t == 31) w0tot = xx;
            __syncthreads();
            if (t >= 32) xx += w0tot;
            if (t < nblocks) g_bbase[t] = xx - vv;
        }
        if (t == 0) g_offs[n] = g_bsum[n >> 10];  // end(last) = bsum+bbase = E
    }
}

// ---------------- kernel 4: scatter (CSR permute src + bond) ----------------
__global__ void scatter_kernel(const int* __restrict__ src, const int* __restrict__ dst,
                               const float* __restrict__ bond, int E)
{
    int e = blockIdx.x * blockDim.x + threadIdx.x;
    if (e >= E) return;
    int d = dst[e];
    int p = g_offs[d] + g_bbase[d >> 10] + atomicAdd(&g_dcz[MAXN + d], 1);
    g_ssrc[p] = src[e];
    const float* bp = bond + (size_t)e * 7;
    float b0 = __ldg(bp + 0), b1 = __ldg(bp + 1), b2 = __ldg(bp + 2), b3 = __ldg(bp + 3);
    float b4 = __ldg(bp + 4), b5 = __ldg(bp + 5), b6 = __ldg(bp + 6);
    *(float4*)&g_ebond[(size_t)p * 8]     = make_float4(b0, b1, b2, b3);
    *(float4*)&g_ebond[(size_t)p * 8 + 4] = make_float4(b4, b5, b6, 1.0f);
}

// ---------------- kernel 5: fused edge attention + aggregation ----------------
// One warp per dst node. Lane l: head h=l>>2, pair jj=l&3, channels ch=4l..4l+3.
// Shfl logit (lane owns bond-feature pair 2jj,2jj+1; slot 7 is bias, bond=1).
// No software pipeline: TLP via 4 blocks/SM.
__global__ void __launch_bounds__(256, 4) edge_attn_kernel(
    const float* __restrict__ Wefc, const float* __restrict__ befc,
    const float* __restrict__ bias, float* __restrict__ out, int n)
{
    int warp = blockIdx.x * 8 + (threadIdx.x >> 5);
    if (warp >= n) return;
    int l = threadIdx.x & 31;
    int h = l >> 2, jj = l & 3;
    int ch = 4 * l;
    int start = g_offs[warp]     + g_bbase[warp >> 10];
    int end   = g_offs[warp + 1] + g_bbase[(warp + 1) >> 10];

    // ak pair for this lane (features 2jj,2jj+1 of head h of dst node)
    float2 akp = __half22float2(*(const __half2*)(g_akh + (size_t)warp * 64 + h * 8 + 2 * jj));

    // wef: per-lane channel pairs, rows 0..6 = Wefc, row 7 = befc
    u64t wef2[8][2];
    #pragma unroll
    for (int f = 0; f < 7; ++f) {
        ulonglong2 w = *(const ulonglong2*)(&Wefc[f * 128 + ch]);
        wef2[f][0] = w.x; wef2[f][1] = w.y;
    }
    {
        ulonglong2 w = *(const ulonglong2*)(&befc[ch]);
        wef2[7][0] = w.x; wef2[7][1] = w.y;
    }

    float denom = 0.f;
    u64t a2[2] = {0ull, 0ull};

    for (int p = start; p < end; ++p) {
        int s = __ldg(&g_ssrc[p]);
        float4 bx = *(const float4*)&g_ebond[(size_t)p * 8];
        float4 by = *(const float4*)&g_ebond[(size_t)p * 8 + 4];
        float2 q  = __half22float2(*(const __half2*)(g_aqh + (size_t)s * 64 + h * 8 + 2 * jj));
        uint2  vr = *(const uint2*)(g_vh + (size_t)s * 128 + ch);

        // logit: lane jj owns bond pair (2jj, 2jj+1); by.w = 1.0 (bias slot)
        float pb0 = (jj == 0) ? bx.x : (jj == 1) ? bx.z : (jj == 2) ? by.x : by.z;
        float pb1 = (jj == 0) ? bx.y : (jj == 1) ? bx.w : (jj == 2) ? by.y : by.w;
        float part = pb0 * (q.x + akp.x) + pb1 * (q.y + akp.y);
        part += __shfl_xor_sync(0xffffffffu, part, 1);
        part += __shfl_xor_sync(0xffffffffu, part, 2);
        float w = __expf(part);
        denom += w;

        // ef = bond @ Wefc + befc (packed channel pairs, FFMA2)
        u64t d0 = dup2(bx.x), d1 = dup2(bx.y), d2 = dup2(bx.z), d3 = dup2(bx.w);
        u64t d4 = dup2(by.x), d5 = dup2(by.y), d6 = dup2(by.z);
        u64t ef0 = wef2[7][0], ef1 = wef2[7][1];
        ef0 = ffma2(d0, wef2[0][0], ef0); ef1 = ffma2(d0, wef2[0][1], ef1);
        ef0 = ffma2(d1, wef2[1][0], ef0); ef1 = ffma2(d1, wef2[1][1], ef1);
        ef0 = ffma2(d2, wef2[2][0], ef0); ef1 = ffma2(d2, wef2[2][1], ef1);
        ef0 = ffma2(d3, wef2[3][0], ef0); ef1 = ffma2(d3, wef2[3][1], ef1);
        ef0 = ffma2(d4, wef2[4][0], ef0); ef1 = ffma2(d4, wef2[4][1], ef1);
        ef0 = ffma2(d5, wef2[5][0], ef0); ef1 = ffma2(d5, wef2[5][1], ef1);
        ef0 = ffma2(d6, wef2[6][0], ef0); ef1 = ffma2(d6, wef2[6][1], ef1);

        // acc += (w * v) * ef   (v fp16 -> fp32)
        float2 v01 = __half22float2(*(__half2*)&vr.x);
        float2 v23 = __half22float2(*(__half2*)&vr.y);
        u64t wd = dup2(w);
        a2[0] = ffma2(fmul2(wd, pk2(v01)), ef0, a2[0]);
        a2[1] = ffma2(fmul2(wd, pk2(v23)), ef1, a2[1]);
    }

    float4 b4 = *(const float4*)(&bias[ch]);
    float4 r;
    if (end > start) {
        float inv = 1.0f / denom;
        float2 lo = unpack2(a2[0]), hi = unpack2(a2[1]);
        r.x = fmaf(lo.x, inv, b4.x);
        r.y = fmaf(lo.y, inv, b4.y);
        r.z = fmaf(hi.x, inv, b4.z);
        r.w = fmaf(hi.y, inv, b4.w);
    } else {
        r = b4;
    }
    *(float4*)(&out[(size_t)warp * 128 + ch]) = r;
}

// ---------------- host launcher ----------------
extern "C" void kernel_launch(void* const* d_in, const int* in_sizes, int n_in,
                              void* d_out, int out_size)
{
    const float* feat = (const float*)d_in[0];
    const float* bond = (const float*)d_in[1];
    const int*   src  = (const int*)d_in[2];
    const int*   dst  = (const int*)d_in[3];
    const float* Wq   = (const float*)d_in[4];
    const float* Wk   = (const float*)d_in[5];
    const float* Wv   = (const float*)d_in[6];
    const float* Wek  = (const float*)d_in[7];
    const float* bek  = (const float*)d_in[8];
    const float* Wefc = (const float*)d_in[9];
    const float* befc = (const float*)d_in[10];
    const float* bias = (const float*)d_in[11];
    float* out = (float*)d_out;

    int N = in_sizes[0] / INF_DIM;   // 50000
    int E = in_sizes[2];             // 800000
    int nb = (N + 1023) / 1024;      // 49

    void* dcz_ptr = nullptr;
    cudaGetSymbolAddress(&dcz_ptr, g_dcz);

    cudaStream_t s1;
    cudaStreamCreateWithFlags(&s1, cudaStreamNonBlocking);
    cudaEvent_t evPrep, evJoin;
    cudaEventCreateWithFlags(&evPrep, cudaEventDisableTiming);
    cudaEventCreateWithFlags(&evJoin, cudaEventDisableTiming);

    // launch 1: one memset for deg + cnt + done
    cudaMemsetAsync(dcz_ptr, 0, (size_t)(2 * MAXN + 1) * sizeof(int), 0);
    // launch 2: degree atomics + wcat prep
    deg_prep_kernel<<<(E + 255) / 256, 256>>>(dst, E, Wq, Wk, Wv, Wek, bek);
    cudaEventRecord(evPrep, 0);
    cudaStreamWaitEvent(s1, evPrep, 0);
    // launch 3 (side stream): GEMM -> fp16 projections
    sgemm_kernel<<<2 * ((N + GBM - 1) / GBM), 256, 0, s1>>>(feat, N);
    cudaEventRecord(evJoin, s1);
    // launch 4: one-pass scan
    scan1p_kernel<<<nb, 1024>>>(N, nb);
    // launch 5: scatter
    scatter_kernel<<<(E + 255) / 256, 256>>>(src, dst, bond, E);
    cudaStreamWaitEvent(0, evJoin, 0);
    // launch 6: fused edge attention (profiled by ncu -s 5 -c 1)
    edge_attn_kernel<<<(N + 7) / 8, 256>>>(Wefc, befc, bias, out, N);

    cudaEventDestroy(evPrep);
    cudaEventDestroy(evJoin);
    cudaStreamDestroy(s1);
}

// round 9
// speedup vs baseline: 1.3940x; 1.0090x over previous
#include <cuda_runtime.h>
#include <cuda_fp16.h>
#include <math.h>

// N=50000, E=800000, IN=128, H=8, EMB=32, OUT=16, EF=7
#define MAXN 50000
#define MAXE 800000
#define INF_DIM 128
#define NCOLS 256          // wcat cols: WqA(64) | WkA(64) | Wv(128)

typedef unsigned long long u64t;

__device__ __forceinline__ u64t dup2(float x) {
    u64t r; asm("mov.b64 %0, {%1, %1};" : "=l"(r) : "f"(x)); return r;
}
__device__ __forceinline__ u64t pk2(float2 f) {
    u64t r; asm("mov.b64 %0, {%1, %2};" : "=l"(r) : "f"(f.x), "f"(f.y)); return r;
}
__device__ __forceinline__ u64t ffma2(u64t a, u64t b, u64t c) {
    u64t d; asm("fma.rn.f32x2 %0, %1, %2, %3;" : "=l"(d) : "l"(a), "l"(b), "l"(c)); return d;
}
__device__ __forceinline__ u64t fmul2(u64t a, u64t b) {
    u64t d; asm("mul.rn.f32x2 %0, %1, %2;" : "=l"(d) : "l"(a), "l"(b)); return d;
}
__device__ __forceinline__ float2 unpack2(u64t a) {
    float2 f; asm("mov.b64 {%0, %1}, %2;" : "=f"(f.x), "=f"(f.y) : "l"(a)); return f;
}

// -------- device scratch --------
// g_dcz: [0,MAXN)=deg, [MAXN,2MAXN)=cnt, [2MAXN]=done ctr, [2MAXN+1]=ready flag
__device__ int    g_dcz[2 * MAXN + 2];
__device__ int    g_offs[MAXN + 1];
__device__ int    g_bsum[256];
__device__ int    g_bbase[256];
__device__ int    g_ssrc[MAXE];                        // CSR-permuted src
__device__ float  g_ebond[(size_t)MAXE * 8];           // CSR-permuted bond(7)+1.0
__device__ __half g_aqh[(size_t)MAXN * 64];            // Aq fp16, head-major [N][H][8]
__device__ __half g_akh[(size_t)MAXN * 64];            // Ak fp16, head-major
__device__ __half g_vh [(size_t)MAXN * 128];           // v  fp16 [N][128]
__device__ float  g_wcat[INF_DIM * NCOLS];

// ---------------- kernel 1: degree count + wcat prep (fused, independent) ----------------
__global__ void deg_prep_kernel(const int* __restrict__ dst, int E,
                                const float* __restrict__ Wq, const float* __restrict__ Wk,
                                const float* __restrict__ Wv, const float* __restrict__ Wek,
                                const float* __restrict__ bek)
{
    int idx = blockIdx.x * blockDim.x + threadIdx.x;
    if (idx < E) atomicAdd(&g_dcz[dst[idx]], 1);

    if (idx < INF_DIM * NCOLS) {
        int i = idx >> 8;
        int c = idx & 255;
        float r;
        if (c < 128) {
            const float* Wx = (c < 64) ? Wq : Wk;
            int cc = c & 63;
            int h = cc >> 3, f = cc & 7;
            const float* ekrow = (f < 7) ? (Wek + f * 256) : bek;
            float acc = 0.f;
            #pragma unroll
            for (int m = 0; m < 32; ++m)
                acc = fmaf(Wx[i * 256 + h * 32 + m], ekrow[h * 32 + m], acc);
            r = acc;
        } else {
            r = Wv[i * 128 + (c - 128)];
        }
        g_wcat[idx] = r;
    }
}

// ---------------- kernel 2 (side stream): GEMM, fp16 epilogue ----------------
#define GBM 128
#define GBN 128
#define GBK 16
__global__ void __launch_bounds__(256) sgemm_kernel(const float* __restrict__ A, int M)
{
    __shared__ float As[GBK][GBM];
    __shared__ float Bs[GBK][GBN];
    int tid = threadIdx.x;
    int brow = (blockIdx.x >> 1) * GBM;
    int bcol = (blockIdx.x & 1) * GBN;
    int ty = tid >> 4, tx = tid & 15;
    u64t acc2[4][8];
    #pragma unroll
    for (int m = 0; m < 4; ++m)
        #pragma unroll
        for (int j = 0; j < 8; ++j) acc2[m][j] = 0ull;

    for (int k0 = 0; k0 < INF_DIM; k0 += GBK) {
        #pragma unroll
        for (int i = 0; i < 2; ++i) {
            int q = tid * 2 + i;
            int r = q >> 2;
            int kq = (q & 3) * 4;
            int gr = brow + r;
            float4 a4 = (gr < M) ? *(const float4*)(&A[(size_t)gr * INF_DIM + k0 + kq])
                                 : make_float4(0.f, 0.f, 0.f, 0.f);
            As[kq + 0][r] = a4.x; As[kq + 1][r] = a4.y;
            As[kq + 2][r] = a4.z; As[kq + 3][r] = a4.w;
        }
        #pragma unroll
        for (int i = 0; i < 2; ++i) {
            int q = tid + i * 256;
            int kk = q >> 5;
            int c = (q & 31) * 4;
            *(float4*)(&Bs[kk][c]) = *(const float4*)(&g_wcat[(k0 + kk) * NCOLS + bcol + c]);
        }
        __syncthreads();
        #pragma unroll
        for (int kk = 0; kk < GBK; ++kk) {
            u64t ar2[4];
            ulonglong2 au0 = *(ulonglong2*)&As[kk][ty * 8];
            ulonglong2 au1 = *(ulonglong2*)&As[kk][ty * 8 + 4];
            ar2[0] = au0.x; ar2[1] = au0.y; ar2[2] = au1.x; ar2[3] = au1.y;
            float br[8];
            *(float4*)&br[0] = *(float4*)&Bs[kk][tx * 8];
            *(float4*)&br[4] = *(float4*)&Bs[kk][tx * 8 + 4];
            u64t brd[8];
            #pragma unroll
            for (int j = 0; j < 8; ++j) brd[j] = dup2(br[j]);
            #pragma unroll
            for (int m = 0; m < 4; ++m)
                #pragma unroll
                for (int j = 0; j < 8; ++j)
                    acc2[m][j] = ffma2(ar2[m], brd[j], acc2[m][j]);
        }
        __syncthreads();
    }

    int gcol = bcol + tx * 8;
    __half* dsth; int cstart; int stride;
    if (gcol < 64)        { dsth = g_aqh; cstart = gcol;       stride = 64; }
    else if (gcol < 128)  { dsth = g_akh; cstart = gcol - 64;  stride = 64; }
    else                  { dsth = g_vh;  cstart = gcol - 128; stride = 128; }

    #pragma unroll
    for (int m = 0; m < 4; ++m) {
        int gr0 = brow + ty * 8 + 2 * m;
        float2 c0 = unpack2(acc2[m][0]), c1 = unpack2(acc2[m][1]);
        float2 c2 = unpack2(acc2[m][2]), c3 = unpack2(acc2[m][3]);
        float2 c4 = unpack2(acc2[m][4]), c5 = unpack2(acc2[m][5]);
        float2 c6 = unpack2(acc2[m][6]), c7 = unpack2(acc2[m][7]);
        if (gr0 < M) {
            __half2 h0 = __floats2half2_rn(c0.x, c1.x);
            __half2 h1 = __floats2half2_rn(c2.x, c3.x);
            __half2 h2 = __floats2half2_rn(c4.x, c5.x);
            __half2 h3 = __floats2half2_rn(c6.x, c7.x);
            uint4 o;
            o.x = *(unsigned*)&h0; o.y = *(unsigned*)&h1;
            o.z = *(unsigned*)&h2; o.w = *(unsigned*)&h3;
            *(uint4*)(dsth + (size_t)gr0 * stride + cstart) = o;
        }
        if (gr0 + 1 < M) {
            __half2 h0 = __floats2half2_rn(c0.y, c1.y);
            __half2 h1 = __floats2half2_rn(c2.y, c3.y);
            __half2 h2 = __floats2half2_rn(c4.y, c5.y);
            __half2 h3 = __floats2half2_rn(c6.y, c7.y);
            uint4 o;
            o.x = *(unsigned*)&h0; o.y = *(unsigned*)&h1;
            o.z = *(unsigned*)&h2; o.w = *(unsigned*)&h3;
            *(uint4*)(dsth + (size_t)(gr0 + 1) * stride + cstart) = o;
        }
    }
}

// ---------------- kernel 3: fused scan + scatter ----------------
// Blocks 0..nscanb-1: block-local scan of 256 degrees each -> g_offs, g_bsum.
// Block 0: waits for all publishes, scans block totals -> g_bbase, sets ready.
// All blocks: spin on ready, then scatter their 256 edges.
__global__ void __launch_bounds__(256) scan_scatter_kernel(
    const int* __restrict__ src, const int* __restrict__ dst,
    const float* __restrict__ bond, int n, int E, int nscanb)
{
    __shared__ int wsum[8];
    int t = threadIdx.x, lane = t & 31, wid = t >> 5;
    int b = blockIdx.x;

    if (b < nscanb) {
        int i = b * 256 + t;
        int v = (i < n) ? g_dcz[i] : 0;
        int x = v;
        #pragma unroll
        for (int d = 1; d < 32; d <<= 1) {
            int y = __shfl_up_sync(0xffffffffu, x, d);
            if (lane >= d) x += y;
        }
        if (lane == 31) wsum[wid] = x;
        __syncthreads();
        if (wid == 0 && lane < 8) {
            int y = wsum[lane];
            #pragma unroll
            for (int d = 1; d < 8; d <<= 1) {
                int z = __shfl_up_sync(0xffu, y, d);
                if (lane >= d) y += z;
            }
            wsum[lane] = y;
        }
        __syncthreads();
        int excl = ((wid > 0) ? wsum[wid - 1] : 0) + (x - v);
        if (i < n) g_offs[i] = excl;
        if (t == 255) {
            g_bsum[b] = wsum[7];
            __threadfence();
            atomicAdd(&g_dcz[2 * MAXN], 1);
        }
    }

    if (b == 0) {
        if (t == 0) {
            while (*(volatile int*)&g_dcz[2 * MAXN] < nscanb) { }
        }
        __syncthreads();
        __threadfence();
        // scan g_bsum[0..nscanb) with this 256-thread block
        int vv = (t < nscanb) ? g_bsum[t] : 0;
        int xx = vv;
        #pragma unroll
        for (int d = 1; d < 32; d <<= 1) {
            int y = __shfl_up_sync(0xffffffffu, xx, d);
            if (lane >= d) xx += y;
        }
        __syncthreads();           // wsum reuse barrier
        if (lane == 31) wsum[wid] = xx;
        __syncthreads();
        if (wid == 0 && lane < 8) {
            int y = wsum[lane];
            #pragma unroll
            for (int d = 1; d < 8; d <<= 1) {
                int z = __shfl_up_sync(0xffu, y, d);
                if (lane >= d) y += z;
            }
            wsum[lane] = y;
        }
        __syncthreads();
        int excl = ((wid > 0) ? wsum[wid - 1] : 0) + (xx - vv);
        if (t < nscanb) g_bbase[t] = excl;
        if (t == 0) {
            g_offs[n] = g_bsum[n >> 8];   // end(last node) = bsum + bbase = E
            __threadfence();
            atomicExch(&g_dcz[2 * MAXN + 1], 1);
        }
    }

    // global spin: wait for bbase ready
    if (t == 0) {
        while (*(volatile int*)&g_dcz[2 * MAXN + 1] == 0) { }
    }
    __syncthreads();
    __threadfence();

    // scatter
    int e = b * 256 + t;
    if (e >= E) return;
    int d = dst[e];
    int p = g_offs[d] + g_bbase[d >> 8] + atomicAdd(&g_dcz[MAXN + d], 1);
    g_ssrc[p] = src[e];
    const float* bp = bond + (size_t)e * 7;
    float b0 = __ldg(bp + 0), b1 = __ldg(bp + 1), b2 = __ldg(bp + 2), b3 = __ldg(bp + 3);
    float b4 = __ldg(bp + 4), b5 = __ldg(bp + 5), b6 = __ldg(bp + 6);
    *(float4*)&g_ebond[(size_t)p * 8]     = make_float4(b0, b1, b2, b3);
    *(float4*)&g_ebond[(size_t)p * 8 + 4] = make_float4(b4, b5, b6, 1.0f);
}

// ---------------- kernel 4: fused edge attention + aggregation ----------------
// One warp per dst node. Lane l: head h=l>>2, pair jj=l&3, channels ch=4l..4l+3.
// ssrc prefetched depth-1 (breaks the index->gather serial chain).
__global__ void __launch_bounds__(256, 4) edge_attn_kernel(
    const float* __restrict__ Wefc, const float* __restrict__ befc,
    const float* __restrict__ bias, float* __restrict__ out, int n)
{
    int warp = blockIdx.x * 8 + (threadIdx.x >> 5);
    if (warp >= n) return;
    int l = threadIdx.x & 31;
    int h = l >> 2, jj = l & 3;
    int ch = 4 * l;
    int start = g_offs[warp]     + g_bbase[warp >> 8];
    int end   = g_offs[warp + 1] + g_bbase[(warp + 1) >> 8];

    float2 akp = __half22float2(*(const __half2*)(g_akh + (size_t)warp * 64 + h * 8 + 2 * jj));

    u64t wef2[8][2];
    #pragma unroll
    for (int f = 0; f < 7; ++f) {
        ulonglong2 w = *(const ulonglong2*)(&Wefc[f * 128 + ch]);
        wef2[f][0] = w.x; wef2[f][1] = w.y;
    }
    {
        ulonglong2 w = *(const ulonglong2*)(&befc[ch]);
        wef2[7][0] = w.x; wef2[7][1] = w.y;
    }

    float denom = 0.f;
    u64t a2[2] = {0ull, 0ull};

    int s = (start < end) ? __ldg(&g_ssrc[start]) : 0;
    for (int p = start; p < end; ++p) {
        int cs = s;
        if (p + 1 < end) s = __ldg(&g_ssrc[p + 1]);

        float4 bx = *(const float4*)&g_ebond[(size_t)p * 8];
        float4 by = *(const float4*)&g_ebond[(size_t)p * 8 + 4];
        float2 q  = __half22float2(*(const __half2*)(g_aqh + (size_t)cs * 64 + h * 8 + 2 * jj));
        uint2  vr = *(const uint2*)(g_vh + (size_t)cs * 128 + ch);

        // logit: lane jj owns bond pair (2jj, 2jj+1); by.w = 1.0 (bias slot)
        float pb0 = (jj == 0) ? bx.x : (jj == 1) ? bx.z : (jj == 2) ? by.x : by.z;
        float pb1 = (jj == 0) ? bx.y : (jj == 1) ? bx.w : (jj == 2) ? by.y : by.w;
        float part = pb0 * (q.x + akp.x) + pb1 * (q.y + akp.y);
        part += __shfl_xor_sync(0xffffffffu, part, 1);
        part += __shfl_xor_sync(0xffffffffu, part, 2);
        float w = __expf(part);
        denom += w;

        // ef = bond @ Wefc + befc (packed channel pairs, FFMA2)
        u64t d0 = dup2(bx.x), d1 = dup2(bx.y), d2 = dup2(bx.z), d3 = dup2(bx.w);
        u64t d4 = dup2(by.x), d5 = dup2(by.y), d6 = dup2(by.z);
        u64t ef0 = wef2[7][0], ef1 = wef2[7][1];
        ef0 = ffma2(d0, wef2[0][0], ef0); ef1 = ffma2(d0, wef2[0][1], ef1);
        ef0 = ffma2(d1, wef2[1][0], ef0); ef1 = ffma2(d1, wef2[1][1], ef1);
        ef0 = ffma2(d2, wef2[2][0], ef0); ef1 = ffma2(d2, wef2[2][1], ef1);
        ef0 = ffma2(d3, wef2[3][0], ef0); ef1 = ffma2(d3, wef2[3][1], ef1);
        ef0 = ffma2(d4, wef2[4][0], ef0); ef1 = ffma2(d4, wef2[4][1], ef1);
        ef0 = ffma2(d5, wef2[5][0], ef0); ef1 = ffma2(d5, wef2[5][1], ef1);
        ef0 = ffma2(d6, wef2[6][0], ef0); ef1 = ffma2(d6, wef2[6][1], ef1);

        // acc += (w * v) * ef   (v fp16 -> fp32)
        float2 v01 = __half22float2(*(__half2*)&vr.x);
        float2 v23 = __half22float2(*(__half2*)&vr.y);
        u64t wd = dup2(w);
        a2[0] = ffma2(fmul2(wd, pk2(v01)), ef0, a2[0]);
        a2[1] = ffma2(fmul2(wd, pk2(v23)), ef1, a2[1]);
    }

    float4 b4 = *(const float4*)(&bias[ch]);
    float4 r;
    if (end > start) {
        float inv = 1.0f / denom;
        float2 lo = unpack2(a2[0]), hi = unpack2(a2[1]);
        r.x = fmaf(lo.x, inv, b4.x);
        r.y = fmaf(lo.y, inv, b4.y);
        r.z = fmaf(hi.x, inv, b4.z);
        r.w = fmaf(hi.y, inv, b4.w);
    } else {
        r = b4;
    }
    *(float4*)(&out[(size_t)warp * 128 + ch]) = r;
}

// ---------------- host launcher ----------------
extern "C" void kernel_launch(void* const* d_in, const int* in_sizes, int n_in,
                              void* d_out, int out_size)
{
    const float* feat = (const float*)d_in[0];
    const float* bond = (const float*)d_in[1];
    const int*   src  = (const int*)d_in[2];
    const int*   dst  = (const int*)d_in[3];
    const float* Wq   = (const float*)d_in[4];
    const float* Wk   = (const float*)d_in[5];
    const float* Wv   = (const float*)d_in[6];
    const float* Wek  = (const float*)d_in[7];
    const float* bek  = (const float*)d_in[8];
    const float* Wefc = (const float*)d_in[9];
    const float* befc = (const float*)d_in[10];
    const float* bias = (const float*)d_in[11];
    float* out = (float*)d_out;

    int N = in_sizes[0] / INF_DIM;   // 50000
    int E = in_sizes[2];             // 800000
    int nscanb = (N + 255) / 256;    // 196

    void* dcz_ptr = nullptr;
    cudaGetSymbolAddress(&dcz_ptr, g_dcz);

    cudaStream_t s1;
    cudaStreamCreateWithFlags(&s1, cudaStreamNonBlocking);
    cudaEvent_t evPrep, evJoin;
    cudaEventCreateWithFlags(&evPrep, cudaEventDisableTiming);
    cudaEventCreateWithFlags(&evJoin, cudaEventDisableTiming);

    // memset: deg + cnt + done + ready
    cudaMemsetAsync(dcz_ptr, 0, (size_t)(2 * MAXN + 2) * sizeof(int), 0);
    // kernel 1: degree atomics + wcat prep
    deg_prep_kernel<<<(E + 255) / 256, 256>>>(dst, E, Wq, Wk, Wv, Wek, bek);
    cudaEventRecord(evPrep, 0);
    cudaStreamWaitEvent(s1, evPrep, 0);
    // kernel 2 (side stream): GEMM -> fp16 projections
    sgemm_kernel<<<2 * ((N + GBM - 1) / GBM), 256, 0, s1>>>(feat, N);
    cudaEventRecord(evJoin, s1);
    // kernel 3: fused scan + scatter
    scan_scatter_kernel<<<(E + 255) / 256, 256>>>(src, dst, bond, N, E, nscanb);
    cudaStreamWaitEvent(0, evJoin, 0);
    // kernel 4: fused edge attention (4th kernel -> profiled by ncu)
    edge_attn_kernel<<<(N + 7) / 8, 256>>>(Wefc, befc, bias, out, N);

    cudaEventDestroy(evPrep);
    cudaEventDestroy(evJoin);
    cudaStreamDestroy(s1);
}

// round 10
// speedup vs baseline: 1.7271x; 1.2389x over previous
#include <cuda_runtime.h>
#include <cuda_fp16.h>
#include <math.h>

// N=50000, E=800000, IN=128, H=8, EMB=32, OUT=16, EF=7
#define MAXN 50000
#define MAXE 800000
#define INF_DIM 128
#define NCOLS 256          // wcat cols: WqA(64) | WkA(64) | Wv(128)

typedef unsigned long long u64t;

__device__ __forceinline__ u64t dup2(float x) {
    u64t r; asm("mov.b64 %0, {%1, %1};" : "=l"(r) : "f"(x)); return r;
}
__device__ __forceinline__ u64t pk2(float2 f) {
    u64t r; asm("mov.b64 %0, {%1, %2};" : "=l"(r) : "f"(f.x), "f"(f.y)); return r;
}
__device__ __forceinline__ u64t ffma2(u64t a, u64t b, u64t c) {
    u64t d; asm("fma.rn.f32x2 %0, %1, %2, %3;" : "=l"(d) : "l"(a), "l"(b), "l"(c)); return d;
}
__device__ __forceinline__ u64t fmul2(u64t a, u64t b) {
    u64t d; asm("mul.rn.f32x2 %0, %1, %2;" : "=l"(d) : "l"(a), "l"(b)); return d;
}
__device__ __forceinline__ float2 unpack2(u64t a) {
    float2 f; asm("mov.b64 {%0, %1}, %2;" : "=f"(f.x), "=f"(f.y) : "l"(a)); return f;
}

// -------- device scratch --------
// g_dcz: [0,MAXN)=deg, [MAXN,2MAXN)=cnt, [2MAXN]=done ctr, [2MAXN+1]=ready flag
__device__ int    g_dcz[2 * MAXN + 2];
__device__ int    g_offs[MAXN + 1];
__device__ int    g_bsum[256];
__device__ int    g_bbase[256];
__device__ int    g_ssrc[MAXE];
__device__ float  g_ebond[(size_t)MAXE * 8];
__device__ __half g_aqh[(size_t)MAXN * 64];            // Aq fp16, head-major [N][H][8]
__device__ __half g_akh[(size_t)MAXN * 64];            // Ak fp16, head-major
__device__ __half g_vh [(size_t)MAXN * 128];           // v  fp16 [N][128]
__device__ __half g_feath[(size_t)MAXN * 128];         // feat fp16
__device__ __half g_wcath[NCOLS * INF_DIM];            // wcat fp16, TRANSPOSED [n=256][k=128]

// ---------------- kernel 1: degrees + wcat^T fp16 + feat->fp16 ----------------
__global__ void deg_prep_kernel(const int* __restrict__ dst, int E, int nf8,
                                const float* __restrict__ feat,
                                const float* __restrict__ Wq, const float* __restrict__ Wk,
                                const float* __restrict__ Wv, const float* __restrict__ Wek,
                                const float* __restrict__ bek)
{
    int idx = blockIdx.x * blockDim.x + threadIdx.x;
    if (idx < E) atomicAdd(&g_dcz[dst[idx]], 1);

    // feat -> fp16 (8 elems per thread)
    if (idx < nf8) {
        float4 f0 = *(const float4*)(feat + (size_t)idx * 8);
        float4 f1 = *(const float4*)(feat + (size_t)idx * 8 + 4);
        __half2 h0 = __floats2half2_rn(f0.x, f0.y);
        __half2 h1 = __floats2half2_rn(f0.z, f0.w);
        __half2 h2 = __floats2half2_rn(f1.x, f1.y);
        __half2 h3 = __floats2half2_rn(f1.z, f1.w);
        uint4 o;
        o.x = *(unsigned*)&h0; o.y = *(unsigned*)&h1;
        o.z = *(unsigned*)&h2; o.w = *(unsigned*)&h3;
        *(uint4*)(g_feath + (size_t)idx * 8) = o;
    }

    // wcat^T fp16: [n=256][k=128]
    if (idx < INF_DIM * NCOLS) {
        int i = idx >> 8;        // k
        int c = idx & 255;       // n
        float r;
        if (c < 128) {
            const float* Wx = (c < 64) ? Wq : Wk;
            int cc = c & 63;
            int h = cc >> 3, f = cc & 7;
            const float* ekrow = (f < 7) ? (Wek + f * 256) : bek;
            float acc = 0.f;
            #pragma unroll
            for (int m = 0; m < 32; ++m)
                acc = fmaf(Wx[i * 256 + h * 32 + m], ekrow[h * 32 + m], acc);
            r = acc;
        } else {
            r = Wv[i * 128 + (c - 128)];
        }
        g_wcath[c * INF_DIM + i] = __float2half(r);
    }
}

// ---------------- kernel 2 (side stream): HMMA GEMM ----------------
// C[M,256] = feath[M,128] @ wcat[128,256], fp16 in, fp32 accum, fp16 out.
// Block tile 128x64, 8 warps (4m x 2n), warp tile 32x32, K split in 2 halves of 64.
__global__ void __launch_bounds__(256) hgemm_kernel(int M)
{
    __shared__ __half As[128][72];   // 64-k half, stride 72 (conflict-free LDSM)
    __shared__ __half Bs[64][72];    // [n][k]
    int tid = threadIdx.x;
    int wid = tid >> 5, lane = tid & 31;
    int brow = blockIdx.x * 128;
    int bcol = blockIdx.y * 64;
    int wm = wid >> 1, wn = wid & 1;

    float acc[2][4][4];
    #pragma unroll
    for (int mt = 0; mt < 2; ++mt)
        #pragma unroll
        for (int nt = 0; nt < 4; ++nt)
            #pragma unroll
            for (int r = 0; r < 4; ++r) acc[mt][nt][r] = 0.f;

    #pragma unroll
    for (int kh = 0; kh < 2; ++kh) {
        // load As: 128 rows x 64 halves (1024 uint4)
        #pragma unroll
        for (int it = 0; it < 4; ++it) {
            int q = tid + it * 256;
            int r = q >> 3;
            int c8 = (q & 7) * 8;
            int gr = brow + r;
            uint4 val = make_uint4(0, 0, 0, 0);
            if (gr < M) val = *(const uint4*)(g_feath + (size_t)gr * 128 + kh * 64 + c8);
            *(uint4*)&As[r][c8] = val;
        }
        // load Bs: 64 rows x 64 halves (512 uint4)
        #pragma unroll
        for (int it = 0; it < 2; ++it) {
            int q = tid + it * 256;
            int r = q >> 3;
            int c8 = (q & 7) * 8;
            *(uint4*)&Bs[r][c8] = *(const uint4*)(g_wcath + (size_t)(bcol + r) * 128 + kh * 64 + c8);
        }
        __syncthreads();

        #pragma unroll
        for (int ks = 0; ks < 4; ++ks) {
            int k0 = ks * 16;
            // A fragments: 2 m16 tiles
            unsigned a[2][4];
            #pragma unroll
            for (int mt = 0; mt < 2; ++mt) {
                int row = wm * 32 + mt * 16 + (lane & 15);
                int col = k0 + ((lane >> 4) << 3);
                unsigned addr = (unsigned)__cvta_generic_to_shared(&As[row][col]);
                asm volatile("ldmatrix.sync.aligned.m8n8.x4.shared.b16 {%0,%1,%2,%3}, [%4];"
                             : "=r"(a[mt][0]), "=r"(a[mt][1]), "=r"(a[mt][2]), "=r"(a[mt][3])
                             : "r"(addr));
            }
            // B fragments: 2 groups of 16 n (each group = 2 n8 tiles)
            unsigned b[2][4];
            #pragma unroll
            for (int g = 0; g < 2; ++g) {
                int nrow = wn * 32 + g * 16 + (lane & 7) + ((lane >> 4) << 3);
                int col = k0 + (lane & 8);
                unsigned addr = (unsigned)__cvta_generic_to_shared(&Bs[nrow][col]);
                asm volatile("ldmatrix.sync.aligned.m8n8.x4.shared.b16 {%0,%1,%2,%3}, [%4];"
                             : "=r"(b[g][0]), "=r"(b[g][1]), "=r"(b[g][2]), "=r"(b[g][3])
                             : "r"(addr));
            }
            #pragma unroll
            for (int mt = 0; mt < 2; ++mt)
                #pragma unroll
                for (int nt = 0; nt < 4; ++nt) {
                    unsigned b0 = b[nt >> 1][(nt & 1) * 2];
                    unsigned b1 = b[nt >> 1][(nt & 1) * 2 + 1];
                    asm volatile(
                        "mma.sync.aligned.m16n8k16.row.col.f32.f16.f16.f32 "
                        "{%0,%1,%2,%3}, {%4,%5,%6,%7}, {%8,%9}, {%0,%1,%2,%3};"
                        : "+f"(acc[mt][nt][0]), "+f"(acc[mt][nt][1]),
                          "+f"(acc[mt][nt][2]), "+f"(acc[mt][nt][3])
                        : "r"(a[mt][0]), "r"(a[mt][1]), "r"(a[mt][2]), "r"(a[mt][3]),
                          "r"(b0), "r"(b1));
                }
        }
        __syncthreads();
    }

    // epilogue: fp16, route by region (warp's 32 cols never straddle a boundary)
    int gcol0 = bcol + wn * 32;
    __half* dsth; int cstart; int stride;
    if (gcol0 < 64)        { dsth = g_aqh; cstart = gcol0;       stride = 64; }
    else if (gcol0 < 128)  { dsth = g_akh; cstart = gcol0 - 64;  stride = 64; }
    else                   { dsth = g_vh;  cstart = gcol0 - 128; stride = 128; }

    #pragma unroll
    for (int mt = 0; mt < 2; ++mt) {
        int row0 = brow + wm * 32 + mt * 16 + (lane >> 2);
        #pragma unroll
        for (int nt = 0; nt < 4; ++nt) {
            int cc = cstart + nt * 8 + (lane & 3) * 2;
            if (row0 < M) {
                __half2 hv = __floats2half2_rn(acc[mt][nt][0], acc[mt][nt][1]);
                *(__half2*)(dsth + (size_t)row0 * stride + cc) = hv;
            }
            if (row0 + 8 < M) {
                __half2 hv = __floats2half2_rn(acc[mt][nt][2], acc[mt][nt][3]);
                *(__half2*)(dsth + (size_t)(row0 + 8) * stride + cc) = hv;
            }
        }
    }
}

// ---------------- kernel 3: fused scan + scatter ----------------
__global__ void __launch_bounds__(256) scan_scatter_kernel(
    const int* __restrict__ src, const int* __restrict__ dst,
    const float* __restrict__ bond, int n, int E, int nscanb)
{
    __shared__ int wsum[8];
    int t = threadIdx.x, lane = t & 31, wid = t >> 5;
    int b = blockIdx.x;

    if (b < nscanb) {
        int i = b * 256 + t;
        int v = (i < n) ? g_dcz[i] : 0;
        int x = v;
        #pragma unroll
        for (int d = 1; d < 32; d <<= 1) {
            int y = __shfl_up_sync(0xffffffffu, x, d);
            if (lane >= d) x += y;
        }
        if (lane == 31) wsum[wid] = x;
        __syncthreads();
        if (wid == 0 && lane < 8) {
            int y = wsum[lane];
            #pragma unroll
            for (int d = 1; d < 8; d <<= 1) {
                int z = __shfl_up_sync(0xffu, y, d);
                if (lane >= d) y += z;
            }
            wsum[lane] = y;
        }
        __syncthreads();
        int excl = ((wid > 0) ? wsum[wid - 1] : 0) + (x - v);
        if (i < n) g_offs[i] = excl;
        if (t == 255) {
            g_bsum[b] = wsum[7];
            __threadfence();
            atomicAdd(&g_dcz[2 * MAXN], 1);
        }
    }

    if (b == 0) {
        if (t == 0) {
            while (*(volatile int*)&g_dcz[2 * MAXN] < nscanb) { }
        }
        __syncthreads();
        __threadfence();
        int vv = (t < nscanb) ? g_bsum[t] : 0;
        int xx = vv;
        #pragma unroll
        for (int d = 1; d < 32; d <<= 1) {
            int y = __shfl_up_sync(0xffffffffu, xx, d);
            if (lane >= d) xx += y;
        }
        __syncthreads();
        if (lane == 31) wsum[wid] = xx;
        __syncthreads();
        if (wid == 0 && lane < 8) {
            int y = wsum[lane];
            #pragma unroll
            for (int d = 1; d < 8; d <<= 1) {
                int z = __shfl_up_sync(0xffu, y, d);
                if (lane >= d) y += z;
            }
            wsum[lane] = y;
        }
        __syncthreads();
        int excl = ((wid > 0) ? wsum[wid - 1] : 0) + (xx - vv);
        if (t < nscanb) g_bbase[t] = excl;
        if (t == 0) {
            g_offs[n] = g_bsum[n >> 8];
            __threadfence();
            atomicExch(&g_dcz[2 * MAXN + 1], 1);
        }
    }

    if (t == 0) {
        while (*(volatile int*)&g_dcz[2 * MAXN + 1] == 0) { }
    }
    __syncthreads();
    __threadfence();

    int e = b * 256 + t;
    if (e >= E) return;
    int d = dst[e];
    int p = g_offs[d] + g_bbase[d >> 8] + atomicAdd(&g_dcz[MAXN + d], 1);
    g_ssrc[p] = src[e];
    const float* bp = bond + (size_t)e * 7;
    float b0 = __ldg(bp + 0), b1 = __ldg(bp + 1), b2 = __ldg(bp + 2), b3 = __ldg(bp + 3);
    float b4 = __ldg(bp + 4), b5 = __ldg(bp + 5), b6 = __ldg(bp + 6);
    *(float4*)&g_ebond[(size_t)p * 8]     = make_float4(b0, b1, b2, b3);
    *(float4*)&g_ebond[(size_t)p * 8 + 4] = make_float4(b4, b5, b6, 1.0f);
}

// ---------------- kernel 4: fused edge attention + aggregation (unchanged) ----------------
__global__ void __launch_bounds__(256, 4) edge_attn_kernel(
    const float* __restrict__ Wefc, const float* __restrict__ befc,
    const float* __restrict__ bias, float* __restrict__ out, int n)
{
    int warp = blockIdx.x * 8 + (threadIdx.x >> 5);
    if (warp >= n) return;
    int l = threadIdx.x & 31;
    int h = l >> 2, jj = l & 3;
    int ch = 4 * l;
    int start = g_offs[warp]     + g_bbase[warp >> 8];
    int end   = g_offs[warp + 1] + g_bbase[(warp + 1) >> 8];

    float2 akp = __half22float2(*(const __half2*)(g_akh + (size_t)warp * 64 + h * 8 + 2 * jj));

    u64t wef2[8][2];
    #pragma unroll
    for (int f = 0; f < 7; ++f) {
        ulonglong2 w = *(const ulonglong2*)(&Wefc[f * 128 + ch]);
        wef2[f][0] = w.x; wef2[f][1] = w.y;
    }
    {
        ulonglong2 w = *(const ulonglong2*)(&befc[ch]);
        wef2[7][0] = w.x; wef2[7][1] = w.y;
    }

    float denom = 0.f;
    u64t a2[2] = {0ull, 0ull};

    int s = (start < end) ? __ldg(&g_ssrc[start]) : 0;
    for (int p = start; p < end; ++p) {
        int cs = s;
        if (p + 1 < end) s = __ldg(&g_ssrc[p + 1]);

        float4 bx = *(const float4*)&g_ebond[(size_t)p * 8];
        float4 by = *(const float4*)&g_ebond[(size_t)p * 8 + 4];
        float2 q  = __half22float2(*(const __half2*)(g_aqh + (size_t)cs * 64 + h * 8 + 2 * jj));
        uint2  vr = *(const uint2*)(g_vh + (size_t)cs * 128 + ch);

        float pb0 = (jj == 0) ? bx.x : (jj == 1) ? bx.z : (jj == 2) ? by.x : by.z;
        float pb1 = (jj == 0) ? bx.y : (jj == 1) ? bx.w : (jj == 2) ? by.y : by.w;
        float part = pb0 * (q.x + akp.x) + pb1 * (q.y + akp.y);
        part += __shfl_xor_sync(0xffffffffu, part, 1);
        part += __shfl_xor_sync(0xffffffffu, part, 2);
        float w = __expf(part);
        denom += w;

        u64t d0 = dup2(bx.x), d1 = dup2(bx.y), d2 = dup2(bx.z), d3 = dup2(bx.w);
        u64t d4 = dup2(by.x), d5 = dup2(by.y), d6 = dup2(by.z);
        u64t ef0 = wef2[7][0], ef1 = wef2[7][1];
        ef0 = ffma2(d0, wef2[0][0], ef0); ef1 = ffma2(d0, wef2[0][1], ef1);
        ef0 = ffma2(d1, wef2[1][0], ef0); ef1 = ffma2(d1, wef2[1][1], ef1);
        ef0 = ffma2(d2, wef2[2][0], ef0); ef1 = ffma2(d2, wef2[2][1], ef1);
        ef0 = ffma2(d3, wef2[3][0], ef0); ef1 = ffma2(d3, wef2[3][1], ef1);
        ef0 = ffma2(d4, wef2[4][0], ef0); ef1 = ffma2(d4, wef2[4][1], ef1);
        ef0 = ffma2(d5, wef2[5][0], ef0); ef1 = ffma2(d5, wef2[5][1], ef1);
        ef0 = ffma2(d6, wef2[6][0], ef0); ef1 = ffma2(d6, wef2[6][1], ef1);

        float2 v01 = __half22float2(*(__half2*)&vr.x);
        float2 v23 = __half22float2(*(__half2*)&vr.y);
        u64t wd = dup2(w);
        a2[0] = ffma2(fmul2(wd, pk2(v01)), ef0, a2[0]);
        a2[1] = ffma2(fmul2(wd, pk2(v23)), ef1, a2[1]);
    }

    float4 b4 = *(const float4*)(&bias[ch]);
    float4 r;
    if (end > start) {
        float inv = 1.0f / denom;
        float2 lo = unpack2(a2[0]), hi = unpack2(a2[1]);
        r.x = fmaf(lo.x, inv, b4.x);
        r.y = fmaf(lo.y, inv, b4.y);
        r.z = fmaf(hi.x, inv, b4.z);
        r.w = fmaf(hi.y, inv, b4.w);
    } else {
        r = b4;
    }
    *(float4*)(&out[(size_t)warp * 128 + ch]) = r;
}

// ---------------- host launcher ----------------
extern "C" void kernel_launch(void* const* d_in, const int* in_sizes, int n_in,
                              void* d_out, int out_size)
{
    const float* feat = (const float*)d_in[0];
    const float* bond = (const float*)d_in[1];
    const int*   src  = (const int*)d_in[2];
    const int*   dst  = (const int*)d_in[3];
    const float* Wq   = (const float*)d_in[4];
    const float* Wk   = (const float*)d_in[5];
    const float* Wv   = (const float*)d_in[6];
    const float* Wek  = (const float*)d_in[7];
    const float* bek  = (const float*)d_in[8];
    const float* Wefc = (const float*)d_in[9];
    const float* befc = (const float*)d_in[10];
    const float* bias = (const float*)d_in[11];
    float* out = (float*)d_out;

    int N = in_sizes[0] / INF_DIM;   // 50000
    int E = in_sizes[2];             // 800000
    int nf8 = in_sizes[0] / 8;       // 800000
    int nscanb = (N + 255) / 256;    // 196
    int gridk1 = (max(E, nf8) + 255) / 256;

    void* dcz_ptr = nullptr;
    cudaGetSymbolAddress(&dcz_ptr, g_dcz);

    cudaStream_t s1;
    cudaStreamCreateWithFlags(&s1, cudaStreamNonBlocking);
    cudaEvent_t evPrep, evJoin;
    cudaEventCreateWithFlags(&evPrep, cudaEventDisableTiming);
    cudaEventCreateWithFlags(&evJoin, cudaEventDisableTiming);

    cudaMemsetAsync(dcz_ptr, 0, (size_t)(2 * MAXN + 2) * sizeof(int), 0);
    // kernel 1: degrees + wcat^T fp16 + feat fp16
    deg_prep_kernel<<<gridk1, 256>>>(dst, E, nf8, feat, Wq, Wk, Wv, Wek, bek);
    cudaEventRecord(evPrep, 0);
    cudaStreamWaitEvent(s1, evPrep, 0);
    // kernel 2 (side stream): tensor-core GEMM
    dim3 ggrid((N + 127) / 128, 4);
    hgemm_kernel<<<ggrid, 256, 0, s1>>>(N);
    cudaEventRecord(evJoin, s1);
    // kernel 3: fused scan + scatter
    scan_scatter_kernel<<<(E + 255) / 256, 256>>>(src, dst, bond, N, E, nscanb);
    cudaStreamWaitEvent(0, evJoin, 0);
    // kernel 4: edge attention (4th kernel -> profiled by ncu)
    edge_attn_kernel<<<(N + 7) / 8, 256>>>(Wefc, befc, bias, out, N);

    cudaEventDestroy(evPrep);
    cudaEventDestroy(evJoin);
    cudaStreamDestroy(s1);
}

// round 11
// speedup vs baseline: 1.7793x; 1.0302x over previous
#include <cuda_runtime.h>
#include <cuda_fp16.h>
#include <math.h>

// N=50000, E=800000, IN=128, H=8, EMB=32, OUT=16, EF=7
#define MAXN 50000
#define MAXE 800000
#define INF_DIM 128
#define NCOLS 256          // wcat cols: WqA(64) | WkA(64) | Wv(128)

typedef unsigned long long u64t;

__device__ __forceinline__ u64t dup2(float x) {
    u64t r; asm("mov.b64 %0, {%1, %1};" : "=l"(r) : "f"(x)); return r;
}
__device__ __forceinline__ u64t pk2(float2 f) {
    u64t r; asm("mov.b64 %0, {%1, %2};" : "=l"(r) : "f"(f.x), "f"(f.y)); return r;
}
__device__ __forceinline__ u64t ffma2(u64t a, u64t b, u64t c) {
    u64t d; asm("fma.rn.f32x2 %0, %1, %2, %3;" : "=l"(d) : "l"(a), "l"(b), "l"(c)); return d;
}
__device__ __forceinline__ float2 unpack2(u64t a) {
    float2 f; asm("mov.b64 {%0, %1}, %2;" : "=f"(f.x), "=f"(f.y) : "l"(a)); return f;
}

// -------- device scratch --------
// g_dcz: [0,MAXN)=deg, [MAXN,2MAXN)=cnt, [2MAXN]=done ctr, [2MAXN+1]=ready flag
__device__ int    g_dcz[2 * MAXN + 2];
__device__ int    g_offs[MAXN + 1];
__device__ int    g_bsum[256];
__device__ int    g_bbase[256];
__device__ int    g_ssrc[MAXE];
__device__ __half2 g_ebondh[(size_t)MAXE * 8];         // CSR-permuted, duplicated (b_f,b_f); f=7 -> (1,1)
__device__ __half g_aqh[(size_t)MAXN * 64];            // Aq fp16, head-major [N][H][8]
__device__ __half g_akh[(size_t)MAXN * 64];            // Ak fp16, head-major
__device__ __half g_vh [(size_t)MAXN * 128];           // v  fp16 [N][128]
__device__ __half g_wcath[NCOLS * INF_DIM];            // wcat fp16, TRANSPOSED [n=256][k=128]

// ---------------- kernel 1: degrees + wcat^T fp16 ----------------
__global__ void deg_prep_kernel(const int* __restrict__ dst, int E,
                                const float* __restrict__ Wq, const float* __restrict__ Wk,
                                const float* __restrict__ Wv, const float* __restrict__ Wek,
                                const float* __restrict__ bek)
{
    int idx = blockIdx.x * blockDim.x + threadIdx.x;
    if (idx < E) atomicAdd(&g_dcz[dst[idx]], 1);

    if (idx < INF_DIM * NCOLS) {
        int i = idx >> 8;        // k
        int c = idx & 255;       // n
        float r;
        if (c < 128) {
            const float* Wx = (c < 64) ? Wq : Wk;
            int cc = c & 63;
            int h = cc >> 3, f = cc & 7;
            const float* ekrow = (f < 7) ? (Wek + f * 256) : bek;
            float acc = 0.f;
            #pragma unroll
            for (int m = 0; m < 32; ++m)
                acc = fmaf(Wx[i * 256 + h * 32 + m], ekrow[h * 32 + m], acc);
            r = acc;
        } else {
            r = Wv[i * 128 + (c - 128)];
        }
        g_wcath[c * INF_DIM + i] = __float2half(r);
    }
}

// ---------------- kernel 2 (side stream): HMMA GEMM (feat fp32 loaded + cvt) ----------------
__global__ void __launch_bounds__(256) hgemm_kernel(const float* __restrict__ feat, int M)
{
    __shared__ __half As[128][72];
    __shared__ __half Bs[64][72];
    int tid = threadIdx.x;
    int wid = tid >> 5, lane = tid & 31;
    int brow = blockIdx.x * 128;
    int bcol = blockIdx.y * 64;
    int wm = wid >> 1, wn = wid & 1;

    float acc[2][4][4];
    #pragma unroll
    for (int mt = 0; mt < 2; ++mt)
        #pragma unroll
        for (int nt = 0; nt < 4; ++nt)
            #pragma unroll
            for (int r = 0; r < 4; ++r) acc[mt][nt][r] = 0.f;

    #pragma unroll
    for (int kh = 0; kh < 2; ++kh) {
        #pragma unroll
        for (int it = 0; it < 4; ++it) {
            int q = tid + it * 256;
            int r = q >> 3;
            int c8 = (q & 7) * 8;
            int gr = brow + r;
            uint4 val = make_uint4(0, 0, 0, 0);
            if (gr < M) {
                float4 f0 = *(const float4*)(feat + (size_t)gr * 128 + kh * 64 + c8);
                float4 f1 = *(const float4*)(feat + (size_t)gr * 128 + kh * 64 + c8 + 4);
                __half2 h0 = __floats2half2_rn(f0.x, f0.y);
                __half2 h1 = __floats2half2_rn(f0.z, f0.w);
                __half2 h2 = __floats2half2_rn(f1.x, f1.y);
                __half2 h3 = __floats2half2_rn(f1.z, f1.w);
                val.x = *(unsigned*)&h0; val.y = *(unsigned*)&h1;
                val.z = *(unsigned*)&h2; val.w = *(unsigned*)&h3;
            }
            *(uint4*)&As[r][c8] = val;
        }
        #pragma unroll
        for (int it = 0; it < 2; ++it) {
            int q = tid + it * 256;
            int r = q >> 3;
            int c8 = (q & 7) * 8;
            *(uint4*)&Bs[r][c8] = *(const uint4*)(g_wcath + (size_t)(bcol + r) * 128 + kh * 64 + c8);
        }
        __syncthreads();

        #pragma unroll
        for (int ks = 0; ks < 4; ++ks) {
            int k0 = ks * 16;
            unsigned a[2][4];
            #pragma unroll
            for (int mt = 0; mt < 2; ++mt) {
                int row = wm * 32 + mt * 16 + (lane & 15);
                int col = k0 + ((lane >> 4) << 3);
                unsigned addr = (unsigned)__cvta_generic_to_shared(&As[row][col]);
                asm volatile("ldmatrix.sync.aligned.m8n8.x4.shared.b16 {%0,%1,%2,%3}, [%4];"
                             : "=r"(a[mt][0]), "=r"(a[mt][1]), "=r"(a[mt][2]), "=r"(a[mt][3])
                             : "r"(addr));
            }
            unsigned b[2][4];
            #pragma unroll
            for (int g = 0; g < 2; ++g) {
                int nrow = wn * 32 + g * 16 + (lane & 7) + ((lane >> 4) << 3);
                int col = k0 + (lane & 8);
                unsigned addr = (unsigned)__cvta_generic_to_shared(&Bs[nrow][col]);
                asm volatile("ldmatrix.sync.aligned.m8n8.x4.shared.b16 {%0,%1,%2,%3}, [%4];"
                             : "=r"(b[g][0]), "=r"(b[g][1]), "=r"(b[g][2]), "=r"(b[g][3])
                             : "r"(addr));
            }
            #pragma unroll
            for (int mt = 0; mt < 2; ++mt)
                #pragma unroll
                for (int nt = 0; nt < 4; ++nt) {
                    unsigned b0 = b[nt >> 1][(nt & 1) * 2];
                    unsigned b1 = b[nt >> 1][(nt & 1) * 2 + 1];
                    asm volatile(
                        "mma.sync.aligned.m16n8k16.row.col.f32.f16.f16.f32 "
                        "{%0,%1,%2,%3}, {%4,%5,%6,%7}, {%8,%9}, {%0,%1,%2,%3};"
                        : "+f"(acc[mt][nt][0]), "+f"(acc[mt][nt][1]),
                          "+f"(acc[mt][nt][2]), "+f"(acc[mt][nt][3])
                        : "r"(a[mt][0]), "r"(a[mt][1]), "r"(a[mt][2]), "r"(a[mt][3]),
                          "r"(b0), "r"(b1));
                }
        }
        __syncthreads();
    }

    int gcol0 = bcol + wn * 32;
    __half* dsth; int cstart; int stride;
    if (gcol0 < 64)        { dsth = g_aqh; cstart = gcol0;       stride = 64; }
    else if (gcol0 < 128)  { dsth = g_akh; cstart = gcol0 - 64;  stride = 64; }
    else                   { dsth = g_vh;  cstart = gcol0 - 128; stride = 128; }

    #pragma unroll
    for (int mt = 0; mt < 2; ++mt) {
        int row0 = brow + wm * 32 + mt * 16 + (lane >> 2);
        #pragma unroll
        for (int nt = 0; nt < 4; ++nt) {
            int cc = cstart + nt * 8 + (lane & 3) * 2;
            if (row0 < M) {
                __half2 hv = __floats2half2_rn(acc[mt][nt][0], acc[mt][nt][1]);
                *(__half2*)(dsth + (size_t)row0 * stride + cc) = hv;
            }
            if (row0 + 8 < M) {
                __half2 hv = __floats2half2_rn(acc[mt][nt][2], acc[mt][nt][3]);
                *(__half2*)(dsth + (size_t)(row0 + 8) * stride + cc) = hv;
            }
        }
    }
}

// ---------------- kernel 3: fused scan + scatter ----------------
__global__ void __launch_bounds__(256) scan_scatter_kernel(
    const int* __restrict__ src, const int* __restrict__ dst,
    const float* __restrict__ bond, int n, int E, int nscanb)
{
    __shared__ int wsum[8];
    int t = threadIdx.x, lane = t & 31, wid = t >> 5;
    int b = blockIdx.x;

    if (b < nscanb) {
        int i = b * 256 + t;
        int v = (i < n) ? g_dcz[i] : 0;
        int x = v;
        #pragma unroll
        for (int d = 1; d < 32; d <<= 1) {
            int y = __shfl_up_sync(0xffffffffu, x, d);
            if (lane >= d) x += y;
        }
        if (lane == 31) wsum[wid] = x;
        __syncthreads();
        if (wid == 0 && lane < 8) {
            int y = wsum[lane];
            #pragma unroll
            for (int d = 1; d < 8; d <<= 1) {
                int z = __shfl_up_sync(0xffu, y, d);
                if (lane >= d) y += z;
            }
            wsum[lane] = y;
        }
        __syncthreads();
        int excl = ((wid > 0) ? wsum[wid - 1] : 0) + (x - v);
        if (i < n) g_offs[i] = excl;
        if (t == 255) {
            g_bsum[b] = wsum[7];
            __threadfence();
            atomicAdd(&g_dcz[2 * MAXN], 1);
        }
    }

    if (b == 0) {
        if (t == 0) {
            while (*(volatile int*)&g_dcz[2 * MAXN] < nscanb) { }
        }
        __syncthreads();
        __threadfence();
        int vv = (t < nscanb) ? g_bsum[t] : 0;
        int xx = vv;
        #pragma unroll
        for (int d = 1; d < 32; d <<= 1) {
            int y = __shfl_up_sync(0xffffffffu, xx, d);
            if (lane >= d) xx += y;
        }
        __syncthreads();
        if (lane == 31) wsum[wid] = xx;
        __syncthreads();
        if (wid == 0 && lane < 8) {
            int y = wsum[lane];
            #pragma unroll
            for (int d = 1; d < 8; d <<= 1) {
                int z = __shfl_up_sync(0xffu, y, d);
                if (lane >= d) y += z;
            }
            wsum[lane] = y;
        }
        __syncthreads();
        int excl = ((wid > 0) ? wsum[wid - 1] : 0) + (xx - vv);
        if (t < nscanb) g_bbase[t] = excl;
        if (t == 0) {
            g_offs[n] = g_bsum[n >> 8];
            __threadfence();
            atomicExch(&g_dcz[2 * MAXN + 1], 1);
        }
    }

    if (t == 0) {
        while (*(volatile int*)&g_dcz[2 * MAXN + 1] == 0) { }
    }
    __syncthreads();
    __threadfence();

    int e = b * 256 + t;
    if (e >= E) return;
    int d = dst[e];
    int p = g_offs[d] + g_bbase[d >> 8] + atomicAdd(&g_dcz[MAXN + d], 1);
    g_ssrc[p] = src[e];
    const float* bp = bond + (size_t)e * 7;
    float b0 = __ldg(bp + 0), b1 = __ldg(bp + 1), b2 = __ldg(bp + 2), b3 = __ldg(bp + 3);
    float b4 = __ldg(bp + 4), b5 = __ldg(bp + 5), b6 = __ldg(bp + 6);
    // duplicated half2 pairs, slot 7 = (1,1)
    __half2 h0 = __floats2half2_rn(b0, b0), h1 = __floats2half2_rn(b1, b1);
    __half2 h2 = __floats2half2_rn(b2, b2), h3 = __floats2half2_rn(b3, b3);
    __half2 h4 = __floats2half2_rn(b4, b4), h5 = __floats2half2_rn(b5, b5);
    __half2 h6 = __floats2half2_rn(b6, b6), h7 = __floats2half2_rn(1.f, 1.f);
    uint4 o0, o1;
    o0.x = *(unsigned*)&h0; o0.y = *(unsigned*)&h1; o0.z = *(unsigned*)&h2; o0.w = *(unsigned*)&h3;
    o1.x = *(unsigned*)&h4; o1.y = *(unsigned*)&h5; o1.z = *(unsigned*)&h6; o1.w = *(unsigned*)&h7;
    *(uint4*)&g_ebondh[(size_t)p * 8]     = o0;
    *(uint4*)&g_ebondh[(size_t)p * 8 + 4] = o1;
}

// ---------------- kernel 4: fused edge attention + aggregation ----------------
// One warp per dst node. Lane l: head h=l>>2, pair jj=l&3, channels ch=4l..4l+3.
// ef product chain in fp16 (HFMA2 on duplicated bond half2s), logit + accum fp32.
__global__ void __launch_bounds__(256, 5) edge_attn_kernel(
    const float* __restrict__ Wefc, const float* __restrict__ befc,
    const float* __restrict__ bias, float* __restrict__ out, int n)
{
    int warp = blockIdx.x * 8 + (threadIdx.x >> 5);
    if (warp >= n) return;
    int l = threadIdx.x & 31;
    int h = l >> 2, jj = l & 3;
    int ch = 4 * l;
    int start = g_offs[warp]     + g_bbase[warp >> 8];
    int end   = g_offs[warp + 1] + g_bbase[(warp + 1) >> 8];

    float2 akp = __half22float2(*(const __half2*)(g_akh + (size_t)warp * 64 + h * 8 + 2 * jj));

    // wef as half2 channel pairs: rows 0..6 = Wefc, row 7 = befc (ef init)
    __half2 wefh[8][2];
    #pragma unroll
    for (int f = 0; f < 7; ++f) {
        float4 w = *(const float4*)(&Wefc[f * 128 + ch]);
        wefh[f][0] = __floats2half2_rn(w.x, w.y);
        wefh[f][1] = __floats2half2_rn(w.z, w.w);
    }
    {
        float4 w = *(const float4*)(&befc[ch]);
        wefh[7][0] = __floats2half2_rn(w.x, w.y);
        wefh[7][1] = __floats2half2_rn(w.z, w.w);
    }

    float denom = 0.f;
    u64t a2[2] = {0ull, 0ull};

    int s = (start < end) ? __ldg(&g_ssrc[start]) : 0;
    for (int p = start; p < end; ++p) {
        int cs = s;
        if (p + 1 < end) s = __ldg(&g_ssrc[p + 1]);

        uint4 e0 = *(const uint4*)&g_ebondh[(size_t)p * 8];
        uint4 e1 = *(const uint4*)&g_ebondh[(size_t)p * 8 + 4];
        __half2 hb0 = *(__half2*)&e0.x, hb1 = *(__half2*)&e0.y;
        __half2 hb2 = *(__half2*)&e0.z, hb3 = *(__half2*)&e0.w;
        __half2 hb4 = *(__half2*)&e1.x, hb5 = *(__half2*)&e1.y;
        __half2 hb6 = *(__half2*)&e1.z, hb7 = *(__half2*)&e1.w;

        float2 q = __half22float2(*(const __half2*)(g_aqh + (size_t)cs * 64 + h * 8 + 2 * jj));
        uint2 vr = *(const uint2*)(g_vh + (size_t)cs * 128 + ch);

        // logit (fp32): lane jj owns bond pair (2jj, 2jj+1); slot 7 = 1.0
        __half2 c0 = (jj < 2) ? (jj ? hb2 : hb0) : ((jj == 2) ? hb4 : hb6);
        __half2 c1 = (jj < 2) ? (jj ? hb3 : hb1) : ((jj == 2) ? hb5 : hb7);
        float pb0 = __low2float(c0);
        float pb1 = __low2float(c1);
        float part = pb0 * (q.x + akp.x) + pb1 * (q.y + akp.y);
        part += __shfl_xor_sync(0xffffffffu, part, 1);
        part += __shfl_xor_sync(0xffffffffu, part, 2);
        float w = __expf(part);
        denom += w;

        // ef = bond @ Wefc + befc, fp16 HFMA2 on duplicated pairs (no dups needed)
        __half2 ef0 = wefh[7][0], ef1 = wefh[7][1];
        ef0 = __hfma2(hb0, wefh[0][0], ef0); ef1 = __hfma2(hb0, wefh[0][1], ef1);
        ef0 = __hfma2(hb1, wefh[1][0], ef0); ef1 = __hfma2(hb1, wefh[1][1], ef1);
        ef0 = __hfma2(hb2, wefh[2][0], ef0); ef1 = __hfma2(hb2, wefh[2][1], ef1);
        ef0 = __hfma2(hb3, wefh[3][0], ef0); ef1 = __hfma2(hb3, wefh[3][1], ef1);
        ef0 = __hfma2(hb4, wefh[4][0], ef0); ef1 = __hfma2(hb4, wefh[4][1], ef1);
        ef0 = __hfma2(hb5, wefh[5][0], ef0); ef1 = __hfma2(hb5, wefh[5][1], ef1);
        ef0 = __hfma2(hb6, wefh[6][0], ef0); ef1 = __hfma2(hb6, wefh[6][1], ef1);

        // m = v ⊙ ef (fp16), then fp32 accumulate a2 += w * m
        __half2 m0 = __hmul2(*(__half2*)&vr.x, ef0);
        __half2 m1 = __hmul2(*(__half2*)&vr.y, ef1);
        float2 mf0 = __half22float2(m0);
        float2 mf1 = __half22float2(m1);
        u64t wd = dup2(w);
        a2[0] = ffma2(wd, pk2(mf0), a2[0]);
        a2[1] = ffma2(wd, pk2(mf1), a2[1]);
    }

    float4 b4 = *(const float4*)(&bias[ch]);
    float4 r;
    if (end > start) {
        float inv = 1.0f / denom;
        float2 lo = unpack2(a2[0]), hi = unpack2(a2[1]);
        r.x = fmaf(lo.x, inv, b4.x);
        r.y = fmaf(lo.y, inv, b4.y);
        r.z = fmaf(hi.x, inv, b4.z);
        r.w = fmaf(hi.y, inv, b4.w);
    } else {
        r = b4;
    }
    *(float4*)(&out[(size_t)warp * 128 + ch]) = r;
}

// ---------------- host launcher ----------------
extern "C" void kernel_launch(void* const* d_in, const int* in_sizes, int n_in,
                              void* d_out, int out_size)
{
    const float* feat = (const float*)d_in[0];
    const float* bond = (const float*)d_in[1];
    const int*   src  = (const int*)d_in[2];
    const int*   dst  = (const int*)d_in[3];
    const float* Wq   = (const float*)d_in[4];
    const float* Wk   = (const float*)d_in[5];
    const float* Wv   = (const float*)d_in[6];
    const float* Wek  = (const float*)d_in[7];
    const float* bek  = (const float*)d_in[8];
    const float* Wefc = (const float*)d_in[9];
    const float* befc = (const float*)d_in[10];
    const float* bias = (const float*)d_in[11];
    float* out = (float*)d_out;

    int N = in_sizes[0] / INF_DIM;   // 50000
    int E = in_sizes[2];             // 800000
    int nscanb = (N + 255) / 256;    // 196

    void* dcz_ptr = nullptr;
    cudaGetSymbolAddress(&dcz_ptr, g_dcz);

    cudaStream_t s1;
    cudaStreamCreateWithFlags(&s1, cudaStreamNonBlocking);
    cudaEvent_t evPrep, evJoin;
    cudaEventCreateWithFlags(&evPrep, cudaEventDisableTiming);
    cudaEventCreateWithFlags(&evJoin, cudaEventDisableTiming);

    cudaMemsetAsync(dcz_ptr, 0, (size_t)(2 * MAXN + 2) * sizeof(int), 0);
    // kernel 1: degrees + wcat^T fp16
    deg_prep_kernel<<<(E + 255) / 256, 256>>>(dst, E, Wq, Wk, Wv, Wek, bek);
    cudaEventRecord(evPrep, 0);
    cudaStreamWaitEvent(s1, evPrep, 0);
    // kernel 2 (side stream): tensor-core GEMM (loads feat fp32 directly)
    dim3 ggrid((N + 127) / 128, 4);
    hgemm_kernel<<<ggrid, 256, 0, s1>>>(feat, N);
    cudaEventRecord(evJoin, s1);
    // kernel 3: fused scan + scatter
    scan_scatter_kernel<<<(E + 255) / 256, 256>>>(src, dst, bond, N, E, nscanb);
    cudaStreamWaitEvent(0, evJoin, 0);
    // kernel 4: edge attention (4th kernel -> profiled by ncu)
    edge_attn_kernel<<<(N + 7) / 8, 256>>>(Wefc, befc, bias, out, N);

    cudaEventDestroy(evPrep);
    cudaEventDestroy(evJoin);
    cudaStreamDestroy(s1);
}

// round 12
// speedup vs baseline: 1.8315x; 1.0294x over previous
#include <cuda_runtime.h>
#include <cuda_fp16.h>
#include <math.h>

// N=50000, E=800000, IN=128, H=8, EMB=32, OUT=16, EF=7
#define MAXN 50000
#define MAXE 800000
#define INF_DIM 128
#define NCOLS 256          // wcat cols: WqA(64) | WkA(64) | Wv(128)

typedef unsigned long long u64t;

__device__ __forceinline__ u64t dup2(float x) {
    u64t r; asm("mov.b64 %0, {%1, %1};" : "=l"(r) : "f"(x)); return r;
}
__device__ __forceinline__ u64t pk2(float2 f) {
    u64t r; asm("mov.b64 %0, {%1, %2};" : "=l"(r) : "f"(f.x), "f"(f.y)); return r;
}
__device__ __forceinline__ u64t ffma2(u64t a, u64t b, u64t c) {
    u64t d; asm("fma.rn.f32x2 %0, %1, %2, %3;" : "=l"(d) : "l"(a), "l"(b), "l"(c)); return d;
}
__device__ __forceinline__ float2 unpack2(u64t a) {
    float2 f; asm("mov.b64 {%0, %1}, %2;" : "=f"(f.x), "=f"(f.y) : "l"(a)); return f;
}

// -------- device scratch --------
// g_dcz: [0,MAXN)=deg, [MAXN,2MAXN)=cnt, [2MAXN]=done ctr, [2MAXN+1]=ready flag
__device__ int    g_dcz[2 * MAXN + 2];
__device__ int    g_offs[MAXN + 1];
__device__ int    g_bsum[256];
__device__ int    g_bbase[256];
__device__ int    g_ssrc[MAXE];
__device__ __half g_ebondp[(size_t)MAXE * 8];          // CSR-permuted packed bond: b0..b6, 1.0 (16B/edge)
__device__ __half g_aqh[(size_t)MAXN * 64];            // Aq fp16, head-major [N][H][8]
__device__ __half g_akh[(size_t)MAXN * 64];            // Ak fp16, head-major
__device__ __half g_vh [(size_t)MAXN * 128];           // v  fp16 [N][128]
__device__ __half g_wcath[NCOLS * INF_DIM];            // wcat fp16, TRANSPOSED [n=256][k=128]

// ---------------- kernel 1: degrees + wcat^T fp16 ----------------
__global__ void deg_prep_kernel(const int* __restrict__ dst, int E,
                                const float* __restrict__ Wq, const float* __restrict__ Wk,
                                const float* __restrict__ Wv, const float* __restrict__ Wek,
                                const float* __restrict__ bek)
{
    int idx = blockIdx.x * blockDim.x + threadIdx.x;
    if (idx < E) atomicAdd(&g_dcz[dst[idx]], 1);

    if (idx < INF_DIM * NCOLS) {
        int i = idx >> 8;        // k
        int c = idx & 255;       // n
        float r;
        if (c < 128) {
            const float* Wx = (c < 64) ? Wq : Wk;
            int cc = c & 63;
            int h = cc >> 3, f = cc & 7;
            const float* ekrow = (f < 7) ? (Wek + f * 256) : bek;
            float acc = 0.f;
            #pragma unroll
            for (int m = 0; m < 32; ++m)
                acc = fmaf(Wx[i * 256 + h * 32 + m], ekrow[h * 32 + m], acc);
            r = acc;
        } else {
            r = Wv[i * 128 + (c - 128)];
        }
        g_wcath[c * INF_DIM + i] = __float2half(r);
    }
}

// ---------------- kernel 2 (side stream): HMMA GEMM ----------------
__global__ void __launch_bounds__(256) hgemm_kernel(const float* __restrict__ feat, int M)
{
    __shared__ __half As[128][72];
    __shared__ __half Bs[64][72];
    int tid = threadIdx.x;
    int wid = tid >> 5, lane = tid & 31;
    int brow = blockIdx.x * 128;
    int bcol = blockIdx.y * 64;
    int wm = wid >> 1, wn = wid & 1;

    float acc[2][4][4];
    #pragma unroll
    for (int mt = 0; mt < 2; ++mt)
        #pragma unroll
        for (int nt = 0; nt < 4; ++nt)
            #pragma unroll
            for (int r = 0; r < 4; ++r) acc[mt][nt][r] = 0.f;

    #pragma unroll
    for (int kh = 0; kh < 2; ++kh) {
        #pragma unroll
        for (int it = 0; it < 4; ++it) {
            int q = tid + it * 256;
            int r = q >> 3;
            int c8 = (q & 7) * 8;
            int gr = brow + r;
            uint4 val = make_uint4(0, 0, 0, 0);
            if (gr < M) {
                float4 f0 = *(const float4*)(feat + (size_t)gr * 128 + kh * 64 + c8);
                float4 f1 = *(const float4*)(feat + (size_t)gr * 128 + kh * 64 + c8 + 4);
                __half2 h0 = __floats2half2_rn(f0.x, f0.y);
                __half2 h1 = __floats2half2_rn(f0.z, f0.w);
                __half2 h2 = __floats2half2_rn(f1.x, f1.y);
                __half2 h3 = __floats2half2_rn(f1.z, f1.w);
                val.x = *(unsigned*)&h0; val.y = *(unsigned*)&h1;
                val.z = *(unsigned*)&h2; val.w = *(unsigned*)&h3;
            }
            *(uint4*)&As[r][c8] = val;
        }
        #pragma unroll
        for (int it = 0; it < 2; ++it) {
            int q = tid + it * 256;
            int r = q >> 3;
            int c8 = (q & 7) * 8;
            *(uint4*)&Bs[r][c8] = *(const uint4*)(g_wcath + (size_t)(bcol + r) * 128 + kh * 64 + c8);
        }
        __syncthreads();

        #pragma unroll
        for (int ks = 0; ks < 4; ++ks) {
            int k0 = ks * 16;
            unsigned a[2][4];
            #pragma unroll
            for (int mt = 0; mt < 2; ++mt) {
                int row = wm * 32 + mt * 16 + (lane & 15);
                int col = k0 + ((lane >> 4) << 3);
                unsigned addr = (unsigned)__cvta_generic_to_shared(&As[row][col]);
                asm volatile("ldmatrix.sync.aligned.m8n8.x4.shared.b16 {%0,%1,%2,%3}, [%4];"
                             : "=r"(a[mt][0]), "=r"(a[mt][1]), "=r"(a[mt][2]), "=r"(a[mt][3])
                             : "r"(addr));
            }
            unsigned b[2][4];
            #pragma unroll
            for (int g = 0; g < 2; ++g) {
                int nrow = wn * 32 + g * 16 + (lane & 7) + ((lane >> 4) << 3);
                int col = k0 + (lane & 8);
                unsigned addr = (unsigned)__cvta_generic_to_shared(&Bs[nrow][col]);
                asm volatile("ldmatrix.sync.aligned.m8n8.x4.shared.b16 {%0,%1,%2,%3}, [%4];"
                             : "=r"(b[g][0]), "=r"(b[g][1]), "=r"(b[g][2]), "=r"(b[g][3])
                             : "r"(addr));
            }
            #pragma unroll
            for (int mt = 0; mt < 2; ++mt)
                #pragma unroll
                for (int nt = 0; nt < 4; ++nt) {
                    unsigned b0 = b[nt >> 1][(nt & 1) * 2];
                    unsigned b1 = b[nt >> 1][(nt & 1) * 2 + 1];
                    asm volatile(
                        "mma.sync.aligned.m16n8k16.row.col.f32.f16.f16.f32 "
                        "{%0,%1,%2,%3}, {%4,%5,%6,%7}, {%8,%9}, {%0,%1,%2,%3};"
                        : "+f"(acc[mt][nt][0]), "+f"(acc[mt][nt][1]),
                          "+f"(acc[mt][nt][2]), "+f"(acc[mt][nt][3])
                        : "r"(a[mt][0]), "r"(a[mt][1]), "r"(a[mt][2]), "r"(a[mt][3]),
                          "r"(b0), "r"(b1));
                }
        }
        __syncthreads();
    }

    int gcol0 = bcol + wn * 32;
    __half* dsth; int cstart; int stride;
    if (gcol0 < 64)        { dsth = g_aqh; cstart = gcol0;       stride = 64; }
    else if (gcol0 < 128)  { dsth = g_akh; cstart = gcol0 - 64;  stride = 64; }
    else                   { dsth = g_vh;  cstart = gcol0 - 128; stride = 128; }

    #pragma unroll
    for (int mt = 0; mt < 2; ++mt) {
        int row0 = brow + wm * 32 + mt * 16 + (lane >> 2);
        #pragma unroll
        for (int nt = 0; nt < 4; ++nt) {
            int cc = cstart + nt * 8 + (lane & 3) * 2;
            if (row0 < M) {
                __half2 hv = __floats2half2_rn(acc[mt][nt][0], acc[mt][nt][1]);
                *(__half2*)(dsth + (size_t)row0 * stride + cc) = hv;
            }
            if (row0 + 8 < M) {
                __half2 hv = __floats2half2_rn(acc[mt][nt][2], acc[mt][nt][3]);
                *(__half2*)(dsth + (size_t)(row0 + 8) * stride + cc) = hv;
            }
        }
    }
}

// ---------------- kernel 3: fused scan + scatter ----------------
__global__ void __launch_bounds__(256) scan_scatter_kernel(
    const int* __restrict__ src, const int* __restrict__ dst,
    const float* __restrict__ bond, int n, int E, int nscanb)
{
    __shared__ int wsum[8];
    int t = threadIdx.x, lane = t & 31, wid = t >> 5;
    int b = blockIdx.x;

    if (b < nscanb) {
        int i = b * 256 + t;
        int v = (i < n) ? g_dcz[i] : 0;
        int x = v;
        #pragma unroll
        for (int d = 1; d < 32; d <<= 1) {
            int y = __shfl_up_sync(0xffffffffu, x, d);
            if (lane >= d) x += y;
        }
        if (lane == 31) wsum[wid] = x;
        __syncthreads();
        if (wid == 0 && lane < 8) {
            int y = wsum[lane];
            #pragma unroll
            for (int d = 1; d < 8; d <<= 1) {
                int z = __shfl_up_sync(0xffu, y, d);
                if (lane >= d) y += z;
            }
            wsum[lane] = y;
        }
        __syncthreads();
        int excl = ((wid > 0) ? wsum[wid - 1] : 0) + (x - v);
        if (i < n) g_offs[i] = excl;
        if (t == 255) {
            g_bsum[b] = wsum[7];
            __threadfence();
            atomicAdd(&g_dcz[2 * MAXN], 1);
        }
    }

    if (b == 0) {
        if (t == 0) {
            while (*(volatile int*)&g_dcz[2 * MAXN] < nscanb) { }
        }
        __syncthreads();
        __threadfence();
        int vv = (t < nscanb) ? g_bsum[t] : 0;
        int xx = vv;
        #pragma unroll
        for (int d = 1; d < 32; d <<= 1) {
            int y = __shfl_up_sync(0xffffffffu, xx, d);
            if (lane >= d) xx += y;
        }
        __syncthreads();
        if (lane == 31) wsum[wid] = xx;
        __syncthreads();
        if (wid == 0 && lane < 8) {
            int y = wsum[lane];
            #pragma unroll
            for (int d = 1; d < 8; d <<= 1) {
                int z = __shfl_up_sync(0xffu, y, d);
                if (lane >= d) y += z;
            }
            wsum[lane] = y;
        }
        __syncthreads();
        int excl = ((wid > 0) ? wsum[wid - 1] : 0) + (xx - vv);
        if (t < nscanb) g_bbase[t] = excl;
        if (t == 0) {
            g_offs[n] = g_bsum[n >> 8];
            __threadfence();
            atomicExch(&g_dcz[2 * MAXN + 1], 1);
        }
    }

    if (t == 0) {
        while (*(volatile int*)&g_dcz[2 * MAXN + 1] == 0) { }
    }
    __syncthreads();
    __threadfence();

    int e = b * 256 + t;
    if (e >= E) return;
    int d = dst[e];
    int p = g_offs[d] + g_bbase[d >> 8] + atomicAdd(&g_dcz[MAXN + d], 1);
    g_ssrc[p] = src[e];
    const float* bp = bond + (size_t)e * 7;
    float b0 = __ldg(bp + 0), b1 = __ldg(bp + 1), b2 = __ldg(bp + 2), b3 = __ldg(bp + 3);
    float b4 = __ldg(bp + 4), b5 = __ldg(bp + 5), b6 = __ldg(bp + 6);
    // packed: (b0,b1),(b2,b3),(b4,b5),(b6,1.0)  -- 16B per edge
    __half2 h0 = __floats2half2_rn(b0, b1), h1 = __floats2half2_rn(b2, b3);
    __half2 h2 = __floats2half2_rn(b4, b5), h3 = __floats2half2_rn(b6, 1.f);
    uint4 o;
    o.x = *(unsigned*)&h0; o.y = *(unsigned*)&h1; o.z = *(unsigned*)&h2; o.w = *(unsigned*)&h3;
    *(uint4*)&g_ebondp[(size_t)p * 8] = o;
}

// ---------------- kernel 4: fused edge attention + aggregation ----------------
// One warp per dst node. Lane l: head h=l>>2, parity jl=l&1, channels ch=4l..4l+3.
// Logit: lane parity owns features 4jl..4jl+3 (fp32 math), ONE shfl.
// ef chain: HFMA2 with in-register half duplication (H0_H0/H1_H1 selectors).
__global__ void __launch_bounds__(256, 5) edge_attn_kernel(
    const float* __restrict__ Wefc, const float* __restrict__ befc,
    const float* __restrict__ bias, float* __restrict__ out, int n)
{
    int warp = blockIdx.x * 8 + (threadIdx.x >> 5);
    if (warp >= n) return;
    int l = threadIdx.x & 31;
    int h = l >> 2, jl = l & 1;
    int ch = 4 * l;
    int start = g_offs[warp]     + g_bbase[warp >> 8];
    int end   = g_offs[warp + 1] + g_bbase[(warp + 1) >> 8];

    // ak features 4jl..4jl+3 of head h (fp32)
    float2 akf01, akf23;
    {
        uint2 a = *(const uint2*)(g_akh + (size_t)warp * 64 + h * 8 + 4 * jl);
        akf01 = __half22float2(*(__half2*)&a.x);
        akf23 = __half22float2(*(__half2*)&a.y);
    }

    // wef as half2 channel pairs: rows 0..6 = Wefc, row 7 = befc (ef init)
    __half2 wefh[8][2];
    #pragma unroll
    for (int f = 0; f < 7; ++f) {
        float4 w = *(const float4*)(&Wefc[f * 128 + ch]);
        wefh[f][0] = __floats2half2_rn(w.x, w.y);
        wefh[f][1] = __floats2half2_rn(w.z, w.w);
    }
    {
        float4 w = *(const float4*)(&befc[ch]);
        wefh[7][0] = __floats2half2_rn(w.x, w.y);
        wefh[7][1] = __floats2half2_rn(w.z, w.w);
    }

    float denom = 0.f;
    u64t a2[2] = {0ull, 0ull};

    int s = (start < end) ? __ldg(&g_ssrc[start]) : 0;
    for (int p = start; p < end; ++p) {
        int cs = s;
        if (p + 1 < end) s = __ldg(&g_ssrc[p + 1]);

        uint4 eb = *(const uint4*)&g_ebondp[(size_t)p * 8];   // one 16B load
        __half2 hb01 = *(__half2*)&eb.x, hb23 = *(__half2*)&eb.y;
        __half2 hb45 = *(__half2*)&eb.z, hb67 = *(__half2*)&eb.w;  // .y of hb67 = 1.0

        uint2 aqr = *(const uint2*)(g_aqh + (size_t)cs * 64 + h * 8 + 4 * jl);
        uint2 vr  = *(const uint2*)(g_vh  + (size_t)cs * 128 + ch);

        // logit (fp32): this lane's 4 features
        float2 q01 = __half22float2(*(__half2*)&aqr.x);
        float2 q23 = __half22float2(*(__half2*)&aqr.y);
        float2 bb01 = __half22float2(jl ? hb45 : hb01);
        float2 bb23 = __half22float2(jl ? hb67 : hb23);
        float part = bb01.x * (q01.x + akf01.x);
        part = fmaf(bb01.y, q01.y + akf01.y, part);
        part = fmaf(bb23.x, q23.x + akf23.x, part);
        part = fmaf(bb23.y, q23.y + akf23.y, part);
        part += __shfl_xor_sync(0xffffffffu, part, 1);
        float w = __expf(part);
        denom += w;

        // ef = bond @ Wefc + befc (fp16, HFMA2 with half-duplication selectors)
        __half2 ef0 = wefh[7][0], ef1 = wefh[7][1];
        __half2 b0d = __low2half2(hb01),  b1d = __high2half2(hb01);
        __half2 b2d = __low2half2(hb23),  b3d = __high2half2(hb23);
        __half2 b4d = __low2half2(hb45),  b5d = __high2half2(hb45);
        __half2 b6d = __low2half2(hb67);
        ef0 = __hfma2(b0d, wefh[0][0], ef0); ef1 = __hfma2(b0d, wefh[0][1], ef1);
        ef0 = __hfma2(b1d, wefh[1][0], ef0); ef1 = __hfma2(b1d, wefh[1][1], ef1);
        ef0 = __hfma2(b2d, wefh[2][0], ef0); ef1 = __hfma2(b2d, wefh[2][1], ef1);
        ef0 = __hfma2(b3d, wefh[3][0], ef0); ef1 = __hfma2(b3d, wefh[3][1], ef1);
        ef0 = __hfma2(b4d, wefh[4][0], ef0); ef1 = __hfma2(b4d, wefh[4][1], ef1);
        ef0 = __hfma2(b5d, wefh[5][0], ef0); ef1 = __hfma2(b5d, wefh[5][1], ef1);
        ef0 = __hfma2(b6d, wefh[6][0], ef0); ef1 = __hfma2(b6d, wefh[6][1], ef1);

        // m = v ⊙ ef (fp16), then fp32 accumulate a2 += w * m
        __half2 m0 = __hmul2(*(__half2*)&vr.x, ef0);
        __half2 m1 = __hmul2(*(__half2*)&vr.y, ef1);
        float2 mf0 = __half22float2(m0);
        float2 mf1 = __half22float2(m1);
        u64t wd = dup2(w);
        a2[0] = ffma2(wd, pk2(mf0), a2[0]);
        a2[1] = ffma2(wd, pk2(mf1), a2[1]);
    }

    float4 b4 = *(const float4*)(&bias[ch]);
    float4 r;
    if (end > start) {
        float inv = 1.0f / denom;
        float2 lo = unpack2(a2[0]), hi = unpack2(a2[1]);
        r.x = fmaf(lo.x, inv, b4.x);
        r.y = fmaf(lo.y, inv, b4.y);
        r.z = fmaf(hi.x, inv, b4.z);
        r.w = fmaf(hi.y, inv, b4.w);
    } else {
        r = b4;
    }
    *(float4*)(&out[(size_t)warp * 128 + ch]) = r;
}

// ---------------- host launcher ----------------
extern "C" void kernel_launch(void* const* d_in, const int* in_sizes, int n_in,
                              void* d_out, int out_size)
{
    const float* feat = (const float*)d_in[0];
    const float* bond = (const float*)d_in[1];
    const int*   src  = (const int*)d_in[2];
    const int*   dst  = (const int*)d_in[3];
    const float* Wq   = (const float*)d_in[4];
    const float* Wk   = (const float*)d_in[5];
    const float* Wv   = (const float*)d_in[6];
    const float* Wek  = (const float*)d_in[7];
    const float* bek  = (const float*)d_in[8];
    const float* Wefc = (const float*)d_in[9];
    const float* befc = (const float*)d_in[10];
    const float* bias = (const float*)d_in[11];
    float* out = (float*)d_out;

    int N = in_sizes[0] / INF_DIM;   // 50000
    int E = in_sizes[2];             // 800000
    int nscanb = (N + 255) / 256;    // 196

    void* dcz_ptr = nullptr;
    cudaGetSymbolAddress(&dcz_ptr, g_dcz);

    cudaStream_t s1;
    cudaStreamCreateWithFlags(&s1, cudaStreamNonBlocking);
    cudaEvent_t evPrep, evJoin;
    cudaEventCreateWithFlags(&evPrep, cudaEventDisableTiming);
    cudaEventCreateWithFlags(&evJoin, cudaEventDisableTiming);

    cudaMemsetAsync(dcz_ptr, 0, (size_t)(2 * MAXN + 2) * sizeof(int), 0);
    // kernel 1: degrees + wcat^T fp16
    deg_prep_kernel<<<(E + 255) / 256, 256>>>(dst, E, Wq, Wk, Wv, Wek, bek);
    cudaEventRecord(evPrep, 0);
    cudaStreamWaitEvent(s1, evPrep, 0);
    // kernel 2 (side stream): tensor-core GEMM
    dim3 ggrid((N + 127) / 128, 4);
    hgemm_kernel<<<ggrid, 256, 0, s1>>>(feat, N);
    cudaEventRecord(evJoin, s1);
    // kernel 3: fused scan + scatter
    scan_scatter_kernel<<<(E + 255) / 256, 256>>>(src, dst, bond, N, E, nscanb);
    cudaStreamWaitEvent(0, evJoin, 0);
    // kernel 4: edge attention (profiled by ncu)
    edge_attn_kernel<<<(N + 7) / 8, 256>>>(Wefc, befc, bias, out, N);

    cudaEventDestroy(evPrep);
    cudaEventDestroy(evJoin);
    cudaStreamDestroy(s1);
}

// round 13
// speedup vs baseline: 1.9734x; 1.0775x over previous
#include <cuda_runtime.h>
#include <cuda_fp16.h>
#include <math.h>

// N=50000, E=800000, IN=128, H=8, EMB=32, OUT=16, EF=7
#define MAXN 50000
#define MAXE 800000
#define INF_DIM 128
#define NCOLS 256          // wcat cols: WqA(64) | WkA(64) | Wv(128)

typedef unsigned long long u64t;

__device__ __forceinline__ u64t dup2(float x) {
    u64t r; asm("mov.b64 %0, {%1, %1};" : "=l"(r) : "f"(x)); return r;
}
__device__ __forceinline__ u64t pk2(float2 f) {
    u64t r; asm("mov.b64 %0, {%1, %2};" : "=l"(r) : "f"(f.x), "f"(f.y)); return r;
}
__device__ __forceinline__ u64t ffma2(u64t a, u64t b, u64t c) {
    u64t d; asm("fma.rn.f32x2 %0, %1, %2, %3;" : "=l"(d) : "l"(a), "l"(b), "l"(c)); return d;
}
__device__ __forceinline__ float2 unpack2(u64t a) {
    float2 f; asm("mov.b64 {%0, %1}, %2;" : "=f"(f.x), "=f"(f.y) : "l"(a)); return f;
}

// -------- device scratch --------
// g_dcz: [0,MAXN)=deg, [MAXN,2MAXN)=cnt, [2MAXN]=done ctr, [2MAXN+1]=ready flag, [2MAXN+2]=work ctr
__device__ int    g_dcz[2 * MAXN + 3];
__device__ int    g_offs[MAXN + 1];
__device__ int    g_bsum[256];
__device__ int    g_bbase[256];
__device__ int    g_ssrc[MAXE];
__device__ __half g_ebondp[(size_t)MAXE * 8];          // CSR-permuted packed bond: b0..b6, 1.0 (16B/edge)
__device__ __half g_aqh[(size_t)MAXN * 64];            // Aq fp16, head-major [N][H][8]
__device__ __half g_akh[(size_t)MAXN * 64];            // Ak fp16, head-major
__device__ __half g_vh [(size_t)MAXN * 128];           // v  fp16 [N][128]
__device__ __half g_wcath[NCOLS * INF_DIM];            // wcat fp16, TRANSPOSED [n=256][k=128]

// ---------------- kernel 1: degrees + wcat^T fp16 ----------------
__global__ void deg_prep_kernel(const int* __restrict__ dst, int E,
                                const float* __restrict__ Wq, const float* __restrict__ Wk,
                                const float* __restrict__ Wv, const float* __restrict__ Wek,
                                const float* __restrict__ bek)
{
    int idx = blockIdx.x * blockDim.x + threadIdx.x;
    if (idx < E) atomicAdd(&g_dcz[dst[idx]], 1);

    if (idx < INF_DIM * NCOLS) {
        int i = idx >> 8;        // k
        int c = idx & 255;       // n
        float r;
        if (c < 128) {
            const float* Wx = (c < 64) ? Wq : Wk;
            int cc = c & 63;
            int h = cc >> 3, f = cc & 7;
            const float* ekrow = (f < 7) ? (Wek + f * 256) : bek;
            float acc = 0.f;
            #pragma unroll
            for (int m = 0; m < 32; ++m)
                acc = fmaf(Wx[i * 256 + h * 32 + m], ekrow[h * 32 + m], acc);
            r = acc;
        } else {
            r = Wv[i * 128 + (c - 128)];
        }
        g_wcath[c * INF_DIM + i] = __float2half(r);
    }
}

// ---------------- kernel 2 (side stream): HMMA GEMM ----------------
__global__ void __launch_bounds__(256) hgemm_kernel(const float* __restrict__ feat, int M)
{
    __shared__ __half As[128][72];
    __shared__ __half Bs[64][72];
    int tid = threadIdx.x;
    int wid = tid >> 5, lane = tid & 31;
    int brow = blockIdx.x * 128;
    int bcol = blockIdx.y * 64;
    int wm = wid >> 1, wn = wid & 1;

    float acc[2][4][4];
    #pragma unroll
    for (int mt = 0; mt < 2; ++mt)
        #pragma unroll
        for (int nt = 0; nt < 4; ++nt)
            #pragma unroll
            for (int r = 0; r < 4; ++r) acc[mt][nt][r] = 0.f;

    #pragma unroll
    for (int kh = 0; kh < 2; ++kh) {
        #pragma unroll
        for (int it = 0; it < 4; ++it) {
            int q = tid + it * 256;
            int r = q >> 3;
            int c8 = (q & 7) * 8;
            int gr = brow + r;
            uint4 val = make_uint4(0, 0, 0, 0);
            if (gr < M) {
                float4 f0 = *(const float4*)(feat + (size_t)gr * 128 + kh * 64 + c8);
                float4 f1 = *(const float4*)(feat + (size_t)gr * 128 + kh * 64 + c8 + 4);
                __half2 h0 = __floats2half2_rn(f0.x, f0.y);
                __half2 h1 = __floats2half2_rn(f0.z, f0.w);
                __half2 h2 = __floats2half2_rn(f1.x, f1.y);
                __half2 h3 = __floats2half2_rn(f1.z, f1.w);
                val.x = *(unsigned*)&h0; val.y = *(unsigned*)&h1;
                val.z = *(unsigned*)&h2; val.w = *(unsigned*)&h3;
            }
            *(uint4*)&As[r][c8] = val;
        }
        #pragma unroll
        for (int it = 0; it < 2; ++it) {
            int q = tid + it * 256;
            int r = q >> 3;
            int c8 = (q & 7) * 8;
            *(uint4*)&Bs[r][c8] = *(const uint4*)(g_wcath + (size_t)(bcol + r) * 128 + kh * 64 + c8);
        }
        __syncthreads();

        #pragma unroll
        for (int ks = 0; ks < 4; ++ks) {
            int k0 = ks * 16;
            unsigned a[2][4];
            #pragma unroll
            for (int mt = 0; mt < 2; ++mt) {
                int row = wm * 32 + mt * 16 + (lane & 15);
                int col = k0 + ((lane >> 4) << 3);
                unsigned addr = (unsigned)__cvta_generic_to_shared(&As[row][col]);
                asm volatile("ldmatrix.sync.aligned.m8n8.x4.shared.b16 {%0,%1,%2,%3}, [%4];"
                             : "=r"(a[mt][0]), "=r"(a[mt][1]), "=r"(a[mt][2]), "=r"(a[mt][3])
                             : "r"(addr));
            }
            unsigned b[2][4];
            #pragma unroll
            for (int g = 0; g < 2; ++g) {
                int nrow = wn * 32 + g * 16 + (lane & 7) + ((lane >> 4) << 3);
                int col = k0 + (lane & 8);
                unsigned addr = (unsigned)__cvta_generic_to_shared(&Bs[nrow][col]);
                asm volatile("ldmatrix.sync.aligned.m8n8.x4.shared.b16 {%0,%1,%2,%3}, [%4];"
                             : "=r"(b[g][0]), "=r"(b[g][1]), "=r"(b[g][2]), "=r"(b[g][3])
                             : "r"(addr));
            }
            #pragma unroll
            for (int mt = 0; mt < 2; ++mt)
                #pragma unroll
                for (int nt = 0; nt < 4; ++nt) {
                    unsigned b0 = b[nt >> 1][(nt & 1) * 2];
                    unsigned b1 = b[nt >> 1][(nt & 1) * 2 + 1];
                    asm volatile(
                        "mma.sync.aligned.m16n8k16.row.col.f32.f16.f16.f32 "
                        "{%0,%1,%2,%3}, {%4,%5,%6,%7}, {%8,%9}, {%0,%1,%2,%3};"
                        : "+f"(acc[mt][nt][0]), "+f"(acc[mt][nt][1]),
                          "+f"(acc[mt][nt][2]), "+f"(acc[mt][nt][3])
                        : "r"(a[mt][0]), "r"(a[mt][1]), "r"(a[mt][2]), "r"(a[mt][3]),
                          "r"(b0), "r"(b1));
                }
        }
        __syncthreads();
    }

    int gcol0 = bcol + wn * 32;
    __half* dsth; int cstart; int stride;
    if (gcol0 < 64)        { dsth = g_aqh; cstart = gcol0;       stride = 64; }
    else if (gcol0 < 128)  { dsth = g_akh; cstart = gcol0 - 64;  stride = 64; }
    else                   { dsth = g_vh;  cstart = gcol0 - 128; stride = 128; }

    #pragma unroll
    for (int mt = 0; mt < 2; ++mt) {
        int row0 = brow + wm * 32 + mt * 16 + (lane >> 2);
        #pragma unroll
        for (int nt = 0; nt < 4; ++nt) {
            int cc = cstart + nt * 8 + (lane & 3) * 2;
            if (row0 < M) {
                __half2 hv = __floats2half2_rn(acc[mt][nt][0], acc[mt][nt][1]);
                *(__half2*)(dsth + (size_t)row0 * stride + cc) = hv;
            }
            if (row0 + 8 < M) {
                __half2 hv = __floats2half2_rn(acc[mt][nt][2], acc[mt][nt][3]);
                *(__half2*)(dsth + (size_t)(row0 + 8) * stride + cc) = hv;
            }
        }
    }
}

// ---------------- kernel 3: fused scan + scatter ----------------
__global__ void __launch_bounds__(256) scan_scatter_kernel(
    const int* __restrict__ src, const int* __restrict__ dst,
    const float* __restrict__ bond, int n, int E, int nscanb)
{
    __shared__ int wsum[8];
    int t = threadIdx.x, lane = t & 31, wid = t >> 5;
    int b = blockIdx.x;

    if (b < nscanb) {
        int i = b * 256 + t;
        int v = (i < n) ? g_dcz[i] : 0;
        int x = v;
        #pragma unroll
        for (int d = 1; d < 32; d <<= 1) {
            int y = __shfl_up_sync(0xffffffffu, x, d);
            if (lane >= d) x += y;
        }
        if (lane == 31) wsum[wid] = x;
        __syncthreads();
        if (wid == 0 && lane < 8) {
            int y = wsum[lane];
            #pragma unroll
            for (int d = 1; d < 8; d <<= 1) {
                int z = __shfl_up_sync(0xffu, y, d);
                if (lane >= d) y += z;
            }
            wsum[lane] = y;
        }
        __syncthreads();
        int excl = ((wid > 0) ? wsum[wid - 1] : 0) + (x - v);
        if (i < n) g_offs[i] = excl;
        if (t == 255) {
            g_bsum[b] = wsum[7];
            __threadfence();
            atomicAdd(&g_dcz[2 * MAXN], 1);
        }
    }

    if (b == 0) {
        if (t == 0) {
            while (*(volatile int*)&g_dcz[2 * MAXN] < nscanb) { }
        }
        __syncthreads();
        __threadfence();
        int vv = (t < nscanb) ? g_bsum[t] : 0;
        int xx = vv;
        #pragma unroll
        for (int d = 1; d < 32; d <<= 1) {
            int y = __shfl_up_sync(0xffffffffu, xx, d);
            if (lane >= d) xx += y;
        }
        __syncthreads();
        if (lane == 31) wsum[wid] = xx;
        __syncthreads();
        if (wid == 0 && lane < 8) {
            int y = wsum[lane];
            #pragma unroll
            for (int d = 1; d < 8; d <<= 1) {
                int z = __shfl_up_sync(0xffu, y, d);
                if (lane >= d) y += z;
            }
            wsum[lane] = y;
        }
        __syncthreads();
        int excl = ((wid > 0) ? wsum[wid - 1] : 0) + (xx - vv);
        if (t < nscanb) g_bbase[t] = excl;
        if (t == 0) {
            g_offs[n] = g_bsum[n >> 8];
            __threadfence();
            atomicExch(&g_dcz[2 * MAXN + 1], 1);
        }
    }

    if (t == 0) {
        while (*(volatile int*)&g_dcz[2 * MAXN + 1] == 0) { }
    }
    __syncthreads();
    __threadfence();

    int e = b * 256 + t;
    if (e >= E) return;
    int d = dst[e];
    int p = g_offs[d] + g_bbase[d >> 8] + atomicAdd(&g_dcz[MAXN + d], 1);
    g_ssrc[p] = src[e];
    const float* bp = bond + (size_t)e * 7;
    float b0 = __ldg(bp + 0), b1 = __ldg(bp + 1), b2 = __ldg(bp + 2), b3 = __ldg(bp + 3);
    float b4 = __ldg(bp + 4), b5 = __ldg(bp + 5), b6 = __ldg(bp + 6);
    __half2 h0 = __floats2half2_rn(b0, b1), h1 = __floats2half2_rn(b2, b3);
    __half2 h2 = __floats2half2_rn(b4, b5), h3 = __floats2half2_rn(b6, 1.f);
    uint4 o;
    o.x = *(unsigned*)&h0; o.y = *(unsigned*)&h1; o.z = *(unsigned*)&h2; o.w = *(unsigned*)&h3;
    *(uint4*)&g_ebondp[(size_t)p * 8] = o;
}

// ---------------- kernel 4: persistent edge attention + aggregation ----------------
// Persistent warps pull node ids from a global work queue (no block-tail imbalance).
// Lane l: head h=l>>2, parity jl=l&1, channels ch=4l..4l+3.
__global__ void __launch_bounds__(256, 5) edge_attn_kernel(
    const float* __restrict__ Wefc, const float* __restrict__ befc,
    const float* __restrict__ bias, float* __restrict__ out, int n)
{
    int l = threadIdx.x & 31;
    int h = l >> 2, jl = l & 1;
    int ch = 4 * l;

    // lane-only-dependent state: loaded ONCE per warp
    __half2 wefh[8][2];
    #pragma unroll
    for (int f = 0; f < 7; ++f) {
        float4 w = *(const float4*)(&Wefc[f * 128 + ch]);
        wefh[f][0] = __floats2half2_rn(w.x, w.y);
        wefh[f][1] = __floats2half2_rn(w.z, w.w);
    }
    {
        float4 w = *(const float4*)(&befc[ch]);
        wefh[7][0] = __floats2half2_rn(w.x, w.y);
        wefh[7][1] = __floats2half2_rn(w.z, w.w);
    }
    float4 b4 = *(const float4*)(&bias[ch]);

    for (;;) {
        int node;
        if (l == 0) node = atomicAdd(&g_dcz[2 * MAXN + 2], 1);
        node = __shfl_sync(0xffffffffu, node, 0);
        if (node >= n) break;

        int start = g_offs[node]     + g_bbase[node >> 8];
        int end   = g_offs[node + 1] + g_bbase[(node + 1) >> 8];

        float2 akf01, akf23;
        {
            uint2 a = *(const uint2*)(g_akh + (size_t)node * 64 + h * 8 + 4 * jl);
            akf01 = __half22float2(*(__half2*)&a.x);
            akf23 = __half22float2(*(__half2*)&a.y);
        }

        float denom = 0.f;
        u64t a2[2] = {0ull, 0ull};

        int s = (start < end) ? __ldg(&g_ssrc[start]) : 0;
        for (int p = start; p < end; ++p) {
            int cs = s;
            if (p + 1 < end) s = __ldg(&g_ssrc[p + 1]);

            uint4 eb = *(const uint4*)&g_ebondp[(size_t)p * 8];
            __half2 hb01 = *(__half2*)&eb.x, hb23 = *(__half2*)&eb.y;
            __half2 hb45 = *(__half2*)&eb.z, hb67 = *(__half2*)&eb.w;  // .y of hb67 = 1.0

            uint2 aqr = *(const uint2*)(g_aqh + (size_t)cs * 64 + h * 8 + 4 * jl);
            uint2 vr  = *(const uint2*)(g_vh  + (size_t)cs * 128 + ch);

            // logit (fp32): lane parity owns features 4jl..4jl+3; ONE shfl
            float2 q01 = __half22float2(*(__half2*)&aqr.x);
            float2 q23 = __half22float2(*(__half2*)&aqr.y);
            float2 bb01 = __half22float2(jl ? hb45 : hb01);
            float2 bb23 = __half22float2(jl ? hb67 : hb23);
            float part = bb01.x * (q01.x + akf01.x);
            part = fmaf(bb01.y, q01.y + akf01.y, part);
            part = fmaf(bb23.x, q23.x + akf23.x, part);
            part = fmaf(bb23.y, q23.y + akf23.y, part);
            part += __shfl_xor_sync(0xffffffffu, part, 1);
            float w = __expf(part);
            denom += w;

            // ef = bond @ Wefc + befc (fp16, HFMA2 with half-dup selectors)
            __half2 ef0 = wefh[7][0], ef1 = wefh[7][1];
            __half2 b0d = __low2half2(hb01),  b1d = __high2half2(hb01);
            __half2 b2d = __low2half2(hb23),  b3d = __high2half2(hb23);
            __half2 b4d = __low2half2(hb45),  b5d = __high2half2(hb45);
            __half2 b6d = __low2half2(hb67);
            ef0 = __hfma2(b0d, wefh[0][0], ef0); ef1 = __hfma2(b0d, wefh[0][1], ef1);
            ef0 = __hfma2(b1d, wefh[1][0], ef0); ef1 = __hfma2(b1d, wefh[1][1], ef1);
            ef0 = __hfma2(b2d, wefh[2][0], ef0); ef1 = __hfma2(b2d, wefh[2][1], ef1);
            ef0 = __hfma2(b3d, wefh[3][0], ef0); ef1 = __hfma2(b3d, wefh[3][1], ef1);
            ef0 = __hfma2(b4d, wefh[4][0], ef0); ef1 = __hfma2(b4d, wefh[4][1], ef1);
            ef0 = __hfma2(b5d, wefh[5][0], ef0); ef1 = __hfma2(b5d, wefh[5][1], ef1);
            ef0 = __hfma2(b6d, wefh[6][0], ef0); ef1 = __hfma2(b6d, wefh[6][1], ef1);

            // m = v ⊙ ef (fp16), then fp32 accumulate a2 += w * m
            __half2 m0 = __hmul2(*(__half2*)&vr.x, ef0);
            __half2 m1 = __hmul2(*(__half2*)&vr.y, ef1);
            float2 mf0 = __half22float2(m0);
            float2 mf1 = __half22float2(m1);
            u64t wd = dup2(w);
            a2[0] = ffma2(wd, pk2(mf0), a2[0]);
            a2[1] = ffma2(wd, pk2(mf1), a2[1]);
        }

        float4 r;
        if (end > start) {
            float inv = 1.0f / denom;
            float2 lo = unpack2(a2[0]), hi = unpack2(a2[1]);
            r.x = fmaf(lo.x, inv, b4.x);
            r.y = fmaf(lo.y, inv, b4.y);
            r.z = fmaf(hi.x, inv, b4.z);
            r.w = fmaf(hi.y, inv, b4.w);
        } else {
            r = b4;
        }
        *(float4*)(&out[(size_t)node * 128 + ch]) = r;
    }
}

// ---------------- host launcher ----------------
extern "C" void kernel_launch(void* const* d_in, const int* in_sizes, int n_in,
                              void* d_out, int out_size)
{
    const float* feat = (const float*)d_in[0];
    const float* bond = (const float*)d_in[1];
    const int*   src  = (const int*)d_in[2];
    const int*   dst  = (const int*)d_in[3];
    const float* Wq   = (const float*)d_in[4];
    const float* Wk   = (const float*)d_in[5];
    const float* Wv   = (const float*)d_in[6];
    const float* Wek  = (const float*)d_in[7];
    const float* bek  = (const float*)d_in[8];
    const float* Wefc = (const float*)d_in[9];
    const float* befc = (const float*)d_in[10];
    const float* bias = (const float*)d_in[11];
    float* out = (float*)d_out;

    int N = in_sizes[0] / INF_DIM;   // 50000
    int E = in_sizes[2];             // 800000
    int nscanb = (N + 255) / 256;    // 196

    void* dcz_ptr = nullptr;
    cudaGetSymbolAddress(&dcz_ptr, g_dcz);

    cudaStream_t s1;
    cudaStreamCreateWithFlags(&s1, cudaStreamNonBlocking);
    cudaEvent_t evPrep, evJoin;
    cudaEventCreateWithFlags(&evPrep, cudaEventDisableTiming);
    cudaEventCreateWithFlags(&evJoin, cudaEventDisableTiming);

    cudaMemsetAsync(dcz_ptr, 0, (size_t)(2 * MAXN + 3) * sizeof(int), 0);
    // kernel 1: degrees + wcat^T fp16
    deg_prep_kernel<<<(E + 255) / 256, 256>>>(dst, E, Wq, Wk, Wv, Wek, bek);
    cudaEventRecord(evPrep, 0);
    cudaStreamWaitEvent(s1, evPrep, 0);
    // kernel 2 (side stream): tensor-core GEMM
    dim3 ggrid((N + 127) / 128, 4);
    hgemm_kernel<<<ggrid, 256, 0, s1>>>(feat, N);
    cudaEventRecord(evJoin, s1);
    // kernel 3: fused scan + scatter
    scan_scatter_kernel<<<(E + 255) / 256, 256>>>(src, dst, bond, N, E, nscanb);
    cudaStreamWaitEvent(0, evJoin, 0);
    // kernel 4: persistent edge attention (profiled by ncu)
    edge_attn_kernel<<<148 * 5, 256>>>(Wefc, befc, bias, out, N);

    cudaEventDestroy(evPrep);
    cudaEventDestroy(evJoin);
    cudaStreamDestroy(s1);
}

// round 14
// speedup vs baseline: 1.9994x; 1.0132x over previous
#include <cuda_runtime.h>
#include <cuda_fp16.h>
#include <math.h>

// N=50000, E=800000, IN=128, H=8, EMB=32, OUT=16, EF=7
#define MAXN 50000
#define MAXE 800000
#define INF_DIM 128
#define NCOLS 256          // wcat cols: WqA(64) | WkA(64) | Wv(128)

typedef unsigned long long u64t;

__device__ __forceinline__ u64t dup2(float x) {
    u64t r; asm("mov.b64 %0, {%1, %1};" : "=l"(r) : "f"(x)); return r;
}
__device__ __forceinline__ u64t pk2(float2 f) {
    u64t r; asm("mov.b64 %0, {%1, %2};" : "=l"(r) : "f"(f.x), "f"(f.y)); return r;
}
__device__ __forceinline__ u64t ffma2(u64t a, u64t b, u64t c) {
    u64t d; asm("fma.rn.f32x2 %0, %1, %2, %3;" : "=l"(d) : "l"(a), "l"(b), "l"(c)); return d;
}
__device__ __forceinline__ float2 unpack2(u64t a) {
    float2 f; asm("mov.b64 {%0, %1}, %2;" : "=f"(f.x), "=f"(f.y) : "l"(a)); return f;
}

// -------- device scratch --------
// g_dcz: [0,MAXN)=deg, [MAXN,2MAXN)=cnt, [2MAXN]=done ctr, [2MAXN+1]=ready flag, [2MAXN+2]=work ctr
__device__ int    g_dcz[2 * MAXN + 3];
__device__ int    g_offs[MAXN + 1];
__device__ int    g_bsum[256];
__device__ int    g_bbase[256];
__device__ int    g_ssrc[MAXE + 1];                    // +1 pad: branch-free prefetch of ssrc[p+1]
__device__ __half g_ebondp[(size_t)MAXE * 8];          // CSR-permuted packed bond: b0..b6, 1.0 (16B/edge)
__device__ __half g_aqh[(size_t)MAXN * 64];            // Aq fp16, head-major [N][H][8]
__device__ __half g_akh[(size_t)MAXN * 64];            // Ak fp16, head-major
__device__ __half g_vh [(size_t)MAXN * 128];           // v  fp16 [N][128]
__device__ __half g_wcath[NCOLS * INF_DIM];            // wcat fp16, TRANSPOSED [n=256][k=128]

// ---------------- kernel 1: degrees + wcat^T fp16 ----------------
__global__ void deg_prep_kernel(const int* __restrict__ dst, int E,
                                const float* __restrict__ Wq, const float* __restrict__ Wk,
                                const float* __restrict__ Wv, const float* __restrict__ Wek,
                                const float* __restrict__ bek)
{
    int idx = blockIdx.x * blockDim.x + threadIdx.x;
    if (idx < E) atomicAdd(&g_dcz[dst[idx]], 1);

    if (idx < INF_DIM * NCOLS) {
        int i = idx >> 8;        // k
        int c = idx & 255;       // n
        float r;
        if (c < 128) {
            const float* Wx = (c < 64) ? Wq : Wk;
            int cc = c & 63;
            int h = cc >> 3, f = cc & 7;
            const float* ekrow = (f < 7) ? (Wek + f * 256) : bek;
            float acc = 0.f;
            #pragma unroll
            for (int m = 0; m < 32; ++m)
                acc = fmaf(Wx[i * 256 + h * 32 + m], ekrow[h * 32 + m], acc);
            r = acc;
        } else {
            r = Wv[i * 128 + (c - 128)];
        }
        g_wcath[c * INF_DIM + i] = __float2half(r);
    }
}

// ---------------- kernel 2 (side stream): HMMA GEMM ----------------
__global__ void __launch_bounds__(256) hgemm_kernel(const float* __restrict__ feat, int M)
{
    __shared__ __half As[128][72];
    __shared__ __half Bs[64][72];
    int tid = threadIdx.x;
    int wid = tid >> 5, lane = tid & 31;
    int brow = blockIdx.x * 128;
    int bcol = blockIdx.y * 64;
    int wm = wid >> 1, wn = wid & 1;

    float acc[2][4][4];
    #pragma unroll
    for (int mt = 0; mt < 2; ++mt)
        #pragma unroll
        for (int nt = 0; nt < 4; ++nt)
            #pragma unroll
            for (int r = 0; r < 4; ++r) acc[mt][nt][r] = 0.f;

    #pragma unroll
    for (int kh = 0; kh < 2; ++kh) {
        #pragma unroll
        for (int it = 0; it < 4; ++it) {
            int q = tid + it * 256;
            int r = q >> 3;
            int c8 = (q & 7) * 8;
            int gr = brow + r;
            uint4 val = make_uint4(0, 0, 0, 0);
            if (gr < M) {
                float4 f0 = *(const float4*)(feat + (size_t)gr * 128 + kh * 64 + c8);
                float4 f1 = *(const float4*)(feat + (size_t)gr * 128 + kh * 64 + c8 + 4);
                __half2 h0 = __floats2half2_rn(f0.x, f0.y);
                __half2 h1 = __floats2half2_rn(f0.z, f0.w);
                __half2 h2 = __floats2half2_rn(f1.x, f1.y);
                __half2 h3 = __floats2half2_rn(f1.z, f1.w);
                val.x = *(unsigned*)&h0; val.y = *(unsigned*)&h1;
                val.z = *(unsigned*)&h2; val.w = *(unsigned*)&h3;
            }
            *(uint4*)&As[r][c8] = val;
        }
        #pragma unroll
        for (int it = 0; it < 2; ++it) {
            int q = tid + it * 256;
            int r = q >> 3;
            int c8 = (q & 7) * 8;
            *(uint4*)&Bs[r][c8] = *(const uint4*)(g_wcath + (size_t)(bcol + r) * 128 + kh * 64 + c8);
        }
        __syncthreads();

        #pragma unroll
        for (int ks = 0; ks < 4; ++ks) {
            int k0 = ks * 16;
            unsigned a[2][4];
            #pragma unroll
            for (int mt = 0; mt < 2; ++mt) {
                int row = wm * 32 + mt * 16 + (lane & 15);
                int col = k0 + ((lane >> 4) << 3);
                unsigned addr = (unsigned)__cvta_generic_to_shared(&As[row][col]);
                asm volatile("ldmatrix.sync.aligned.m8n8.x4.shared.b16 {%0,%1,%2,%3}, [%4];"
                             : "=r"(a[mt][0]), "=r"(a[mt][1]), "=r"(a[mt][2]), "=r"(a[mt][3])
                             : "r"(addr));
            }
            unsigned b[2][4];
            #pragma unroll
            for (int g = 0; g < 2; ++g) {
                int nrow = wn * 32 + g * 16 + (lane & 7) + ((lane >> 4) << 3);
                int col = k0 + (lane & 8);
                unsigned addr = (unsigned)__cvta_generic_to_shared(&Bs[nrow][col]);
                asm volatile("ldmatrix.sync.aligned.m8n8.x4.shared.b16 {%0,%1,%2,%3}, [%4];"
                             : "=r"(b[g][0]), "=r"(b[g][1]), "=r"(b[g][2]), "=r"(b[g][3])
                             : "r"(addr));
            }
            #pragma unroll
            for (int mt = 0; mt < 2; ++mt)
                #pragma unroll
                for (int nt = 0; nt < 4; ++nt) {
                    unsigned b0 = b[nt >> 1][(nt & 1) * 2];
                    unsigned b1 = b[nt >> 1][(nt & 1) * 2 + 1];
                    asm volatile(
                        "mma.sync.aligned.m16n8k16.row.col.f32.f16.f16.f32 "
                        "{%0,%1,%2,%3}, {%4,%5,%6,%7}, {%8,%9}, {%0,%1,%2,%3};"
                        : "+f"(acc[mt][nt][0]), "+f"(acc[mt][nt][1]),
                          "+f"(acc[mt][nt][2]), "+f"(acc[mt][nt][3])
                        : "r"(a[mt][0]), "r"(a[mt][1]), "r"(a[mt][2]), "r"(a[mt][3]),
                          "r"(b0), "r"(b1));
                }
        }
        __syncthreads();
    }

    int gcol0 = bcol + wn * 32;
    __half* dsth; int cstart; int stride;
    if (gcol0 < 64)        { dsth = g_aqh; cstart = gcol0;       stride = 64; }
    else if (gcol0 < 128)  { dsth = g_akh; cstart = gcol0 - 64;  stride = 64; }
    else                   { dsth = g_vh;  cstart = gcol0 - 128; stride = 128; }

    #pragma unroll
    for (int mt = 0; mt < 2; ++mt) {
        int row0 = brow + wm * 32 + mt * 16 + (lane >> 2);
        #pragma unroll
        for (int nt = 0; nt < 4; ++nt) {
            int cc = cstart + nt * 8 + (lane & 3) * 2;
            if (row0 < M) {
                __half2 hv = __floats2half2_rn(acc[mt][nt][0], acc[mt][nt][1]);
                *(__half2*)(dsth + (size_t)row0 * stride + cc) = hv;
            }
            if (row0 + 8 < M) {
                __half2 hv = __floats2half2_rn(acc[mt][nt][2], acc[mt][nt][3]);
                *(__half2*)(dsth + (size_t)(row0 + 8) * stride + cc) = hv;
            }
        }
    }
}

// ---------------- kernel 3: fused scan + scatter ----------------
__global__ void __launch_bounds__(256) scan_scatter_kernel(
    const int* __restrict__ src, const int* __restrict__ dst,
    const float* __restrict__ bond, int n, int E, int nscanb)
{
    __shared__ int wsum[8];
    int t = threadIdx.x, lane = t & 31, wid = t >> 5;
    int b = blockIdx.x;

    if (b < nscanb) {
        int i = b * 256 + t;
        int v = (i < n) ? g_dcz[i] : 0;
        int x = v;
        #pragma unroll
        for (int d = 1; d < 32; d <<= 1) {
            int y = __shfl_up_sync(0xffffffffu, x, d);
            if (lane >= d) x += y;
        }
        if (lane == 31) wsum[wid] = x;
        __syncthreads();
        if (wid == 0 && lane < 8) {
            int y = wsum[lane];
            #pragma unroll
            for (int d = 1; d < 8; d <<= 1) {
                int z = __shfl_up_sync(0xffu, y, d);
                if (lane >= d) y += z;
            }
            wsum[lane] = y;
        }
        __syncthreads();
        int excl = ((wid > 0) ? wsum[wid - 1] : 0) + (x - v);
        if (i < n) g_offs[i] = excl;
        if (t == 255) {
            g_bsum[b] = wsum[7];
            __threadfence();
            atomicAdd(&g_dcz[2 * MAXN], 1);
        }
    }

    if (b == 0) {
        if (t == 0) {
            while (*(volatile int*)&g_dcz[2 * MAXN] < nscanb) { }
        }
        __syncthreads();
        __threadfence();
        int vv = (t < nscanb) ? g_bsum[t] : 0;
        int xx = vv;
        #pragma unroll
        for (int d = 1; d < 32; d <<= 1) {
            int y = __shfl_up_sync(0xffffffffu, xx, d);
            if (lane >= d) xx += y;
        }
        __syncthreads();
        if (lane == 31) wsum[wid] = xx;
        __syncthreads();
        if (wid == 0 && lane < 8) {
            int y = wsum[lane];
            #pragma unroll
            for (int d = 1; d < 8; d <<= 1) {
                int z = __shfl_up_sync(0xffu, y, d);
                if (lane >= d) y += z;
            }
            wsum[lane] = y;
        }
        __syncthreads();
        int excl = ((wid > 0) ? wsum[wid - 1] : 0) + (xx - vv);
        if (t < nscanb) g_bbase[t] = excl;
        if (t == 0) {
            g_offs[n] = g_bsum[n >> 8];
            __threadfence();
            atomicExch(&g_dcz[2 * MAXN + 1], 1);
        }
    }

    if (t == 0) {
        while (*(volatile int*)&g_dcz[2 * MAXN + 1] == 0) { }
    }
    __syncthreads();
    __threadfence();

    int e = b * 256 + t;
    if (e >= E) return;
    int d = dst[e];
    int p = g_offs[d] + g_bbase[d >> 8] + atomicAdd(&g_dcz[MAXN + d], 1);
    g_ssrc[p] = src[e];
    const float* bp = bond + (size_t)e * 7;
    float b0 = __ldg(bp + 0), b1 = __ldg(bp + 1), b2 = __ldg(bp + 2), b3 = __ldg(bp + 3);
    float b4 = __ldg(bp + 4), b5 = __ldg(bp + 5), b6 = __ldg(bp + 6);
    __half2 h0 = __floats2half2_rn(b0, b1), h1 = __floats2half2_rn(b2, b3);
    __half2 h2 = __floats2half2_rn(b4, b5), h3 = __floats2half2_rn(b6, 1.f);
    uint4 o;
    o.x = *(unsigned*)&h0; o.y = *(unsigned*)&h1; o.z = *(unsigned*)&h2; o.w = *(unsigned*)&h3;
    *(uint4*)&g_ebondp[(size_t)p * 8] = o;
}

// ---------------- kernel 4: persistent edge attention + aggregation ----------------
// Persistent warps pop 2 nodes per atomic from a global work queue.
// Lane l: head h=l>>2, parity jl=l&1, channels ch=4l..4l+3.
__global__ void __launch_bounds__(256, 5) edge_attn_kernel(
    const float* __restrict__ Wefc, const float* __restrict__ befc,
    const float* __restrict__ bias, float* __restrict__ out, int n)
{
    int l = threadIdx.x & 31;
    int h = l >> 2, jl = l & 1;
    int ch = 4 * l;

    // lane-only-dependent state: loaded ONCE per warp
    __half2 wefh[8][2];
    #pragma unroll
    for (int f = 0; f < 7; ++f) {
        float4 w = *(const float4*)(&Wefc[f * 128 + ch]);
        wefh[f][0] = __floats2half2_rn(w.x, w.y);
        wefh[f][1] = __floats2half2_rn(w.z, w.w);
    }
    {
        float4 w = *(const float4*)(&befc[ch]);
        wefh[7][0] = __floats2half2_rn(w.x, w.y);
        wefh[7][1] = __floats2half2_rn(w.z, w.w);
    }
    float4 b4 = *(const float4*)(&bias[ch]);

    for (;;) {
        int nbase;
        if (l == 0) nbase = atomicAdd(&g_dcz[2 * MAXN + 2], 2);
        nbase = __shfl_sync(0xffffffffu, nbase, 0);
        if (nbase >= n) break;
        int nend = min(nbase + 2, n);

        for (int node = nbase; node < nend; ++node) {
            int start = g_offs[node]     + g_bbase[node >> 8];
            int end   = g_offs[node + 1] + g_bbase[(node + 1) >> 8];

            float2 akf01, akf23;
            {
                uint2 a = *(const uint2*)(g_akh + (size_t)node * 64 + h * 8 + 4 * jl);
                akf01 = __half22float2(*(__half2*)&a.x);
                akf23 = __half22float2(*(__half2*)&a.y);
            }

            float denom = 0.f;
            u64t a2[2] = {0ull, 0ull};

            int s = (start < end) ? __ldg(&g_ssrc[start]) : 0;
            for (int p = start; p < end; ++p) {
                int cs = s;
                s = __ldg(&g_ssrc[p + 1]);   // branch-free: g_ssrc padded by 1

                uint4 eb = *(const uint4*)&g_ebondp[(size_t)p * 8];
                __half2 hb01 = *(__half2*)&eb.x, hb23 = *(__half2*)&eb.y;
                __half2 hb45 = *(__half2*)&eb.z, hb67 = *(__half2*)&eb.w;  // .y of hb67 = 1.0

                uint2 aqr = *(const uint2*)(g_aqh + (size_t)cs * 64 + h * 8 + 4 * jl);
                uint2 vr  = *(const uint2*)(g_vh  + (size_t)cs * 128 + ch);

                // logit (fp32): lane parity owns features 4jl..4jl+3; ONE shfl
                float2 q01 = __half22float2(*(__half2*)&aqr.x);
                float2 q23 = __half22float2(*(__half2*)&aqr.y);
                float2 bb01 = __half22float2(jl ? hb45 : hb01);
                float2 bb23 = __half22float2(jl ? hb67 : hb23);
                float part = bb01.x * (q01.x + akf01.x);
                part = fmaf(bb01.y, q01.y + akf01.y, part);
                part = fmaf(bb23.x, q23.x + akf23.x, part);
                part = fmaf(bb23.y, q23.y + akf23.y, part);
                part += __shfl_xor_sync(0xffffffffu, part, 1);
                float w = __expf(part);
                denom += w;

                // ef = bond @ Wefc + befc (fp16, HFMA2 with half-dup selectors)
                __half2 ef0 = wefh[7][0], ef1 = wefh[7][1];
                __half2 b0d = __low2half2(hb01),  b1d = __high2half2(hb01);
                __half2 b2d = __low2half2(hb23),  b3d = __high2half2(hb23);
                __half2 b4d = __low2half2(hb45),  b5d = __high2half2(hb45);
                __half2 b6d = __low2half2(hb67);
                ef0 = __hfma2(b0d, wefh[0][0], ef0); ef1 = __hfma2(b0d, wefh[0][1], ef1);
                ef0 = __hfma2(b1d, wefh[1][0], ef0); ef1 = __hfma2(b1d, wefh[1][1], ef1);
                ef0 = __hfma2(b2d, wefh[2][0], ef0); ef1 = __hfma2(b2d, wefh[2][1], ef1);
                ef0 = __hfma2(b3d, wefh[3][0], ef0); ef1 = __hfma2(b3d, wefh[3][1], ef1);
                ef0 = __hfma2(b4d, wefh[4][0], ef0); ef1 = __hfma2(b4d, wefh[4][1], ef1);
                ef0 = __hfma2(b5d, wefh[5][0], ef0); ef1 = __hfma2(b5d, wefh[5][1], ef1);
                ef0 = __hfma2(b6d, wefh[6][0], ef0); ef1 = __hfma2(b6d, wefh[6][1], ef1);

                // m = v ⊙ ef (fp16), then fp32 accumulate a2 += w * m
                __half2 m0 = __hmul2(*(__half2*)&vr.x, ef0);
                __half2 m1 = __hmul2(*(__half2*)&vr.y, ef1);
                float2 mf0 = __half22float2(m0);
                float2 mf1 = __half22float2(m1);
                u64t wd = dup2(w);
                a2[0] = ffma2(wd, pk2(mf0), a2[0]);
                a2[1] = ffma2(wd, pk2(mf1), a2[1]);
            }

            float4 r;
            if (end > start) {
                float inv = 1.0f / denom;
                float2 lo = unpack2(a2[0]), hi = unpack2(a2[1]);
                r.x = fmaf(lo.x, inv, b4.x);
                r.y = fmaf(lo.y, inv, b4.y);
                r.z = fmaf(hi.x, inv, b4.z);
                r.w = fmaf(hi.y, inv, b4.w);
            } else {
                r = b4;
            }
            *(float4*)(&out[(size_t)node * 128 + ch]) = r;
        }
    }
}

// ---------------- host launcher ----------------
extern "C" void kernel_launch(void* const* d_in, const int* in_sizes, int n_in,
                              void* d_out, int out_size)
{
    const float* feat = (const float*)d_in[0];
    const float* bond = (const float*)d_in[1];
    const int*   src  = (const int*)d_in[2];
    const int*   dst  = (const int*)d_in[3];
    const float* Wq   = (const float*)d_in[4];
    const float* Wk   = (const float*)d_in[5];
    const float* Wv   = (const float*)d_in[6];
    const float* Wek  = (const float*)d_in[7];
    const float* bek  = (const float*)d_in[8];
    const float* Wefc = (const float*)d_in[9];
    const float* befc = (const float*)d_in[10];
    const float* bias = (const float*)d_in[11];
    float* out = (float*)d_out;

    int N = in_sizes[0] / INF_DIM;   // 50000
    int E = in_sizes[2];             // 800000
    int nscanb = (N + 255) / 256;    // 196

    void* dcz_ptr = nullptr;
    cudaGetSymbolAddress(&dcz_ptr, g_dcz);

    cudaStream_t s1;
    cudaStreamCreateWithFlags(&s1, cudaStreamNonBlocking);
    cudaEvent_t evPrep, evJoin;
    cudaEventCreateWithFlags(&evPrep, cudaEventDisableTiming);
    cudaEventCreateWithFlags(&evJoin, cudaEventDisableTiming);

    cudaMemsetAsync(dcz_ptr, 0, (size_t)(2 * MAXN + 3) * sizeof(int), 0);
    // kernel 1: degrees + wcat^T fp16
    deg_prep_kernel<<<(E + 255) / 256, 256>>>(dst, E, Wq, Wk, Wv, Wek, bek);
    cudaEventRecord(evPrep, 0);
    cudaStreamWaitEvent(s1, evPrep, 0);
    // kernel 2 (side stream): tensor-core GEMM
    dim3 ggrid((N + 127) / 128, 4);
    hgemm_kernel<<<ggrid, 256, 0, s1>>>(feat, N);
    cudaEventRecord(evJoin, s1);
    // kernel 3: fused scan + scatter
    scan_scatter_kernel<<<(E + 255) / 256, 256>>>(src, dst, bond, N, E, nscanb);
    cudaStreamWaitEvent(0, evJoin, 0);
    // kernel 4: persistent edge attention (profiled by ncu)
    edge_attn_kernel<<<148 * 5, 256>>>(Wefc, befc, bias, out, N);

    cudaEventDestroy(evPrep);
    cudaEventDestroy(evJoin);
    cudaStreamDestroy(s1);
}

// round 15
// speedup vs baseline: 2.0435x; 1.0221x over previous
#include <cuda_runtime.h>
#include <cuda_fp16.h>
#include <math.h>

// N=50000, E=800000, IN=128, H=8, EMB=32, OUT=16, EF=7
#define MAXN 50000
#define MAXE 800000
#define INF_DIM 128
#define NCOLS 256          // wcat cols: WqA(64) | WkA(64) | Wv(128)

typedef unsigned long long u64t;

__device__ __forceinline__ u64t dup2(float x) {
    u64t r; asm("mov.b64 %0, {%1, %1};" : "=l"(r) : "f"(x)); return r;
}
__device__ __forceinline__ u64t pk2(float2 f) {
    u64t r; asm("mov.b64 %0, {%1, %2};" : "=l"(r) : "f"(f.x), "f"(f.y)); return r;
}
__device__ __forceinline__ u64t ffma2(u64t a, u64t b, u64t c) {
    u64t d; asm("fma.rn.f32x2 %0, %1, %2, %3;" : "=l"(d) : "l"(a), "l"(b), "l"(c)); return d;
}
__device__ __forceinline__ float2 unpack2(u64t a) {
    float2 f; asm("mov.b64 {%0, %1}, %2;" : "=f"(f.x), "=f"(f.y) : "l"(a)); return f;
}

// -------- device scratch --------
// g_dcz: [0,MAXN)=deg, [MAXN,2MAXN)=cnt, [2MAXN]=done ctr, [2MAXN+1]=ready flag, [2MAXN+2]=work ctr
__device__ int    g_dcz[2 * MAXN + 3];
__device__ int    g_offs[MAXN + 1];
__device__ int    g_bsum[256];
__device__ int    g_bbase[256];
__device__ int    g_ssrc[MAXE + 1];                    // +1 pad: branch-free prefetch of ssrc[p+1]
__device__ __half g_ebondp[(size_t)MAXE * 8];          // CSR-permuted packed bond: b0..b6, 1.0 (16B/edge)
__device__ __half g_aqh[(size_t)MAXN * 64];            // Aq fp16, head-major [N][H][8]
__device__ __half g_akh[(size_t)MAXN * 64];            // Ak fp16, head-major
__device__ __half g_vh [(size_t)MAXN * 128];           // v  fp16 [N][128]
__device__ __half g_wcath[NCOLS * INF_DIM];            // wcat fp16, TRANSPOSED [n=256][k=128]

// ---------------- kernel A (side stream): wcat^T fp16 only (tiny) ----------------
__global__ void wcat_prep_kernel(const float* __restrict__ Wq, const float* __restrict__ Wk,
                                 const float* __restrict__ Wv, const float* __restrict__ Wek,
                                 const float* __restrict__ bek)
{
    int idx = blockIdx.x * blockDim.x + threadIdx.x;
    if (idx < INF_DIM * NCOLS) {
        int i = idx >> 8;        // k
        int c = idx & 255;       // n
        float r;
        if (c < 128) {
            const float* Wx = (c < 64) ? Wq : Wk;
            int cc = c & 63;
            int h = cc >> 3, f = cc & 7;
            const float* ekrow = (f < 7) ? (Wek + f * 256) : bek;
            float acc = 0.f;
            #pragma unroll
            for (int m = 0; m < 32; ++m)
                acc = fmaf(Wx[i * 256 + h * 32 + m], ekrow[h * 32 + m], acc);
            r = acc;
        } else {
            r = Wv[i * 128 + (c - 128)];
        }
        g_wcath[c * INF_DIM + i] = __float2half(r);
    }
}

// ---------------- kernel B (main stream): degree atomics only ----------------
__global__ void deg_kernel(const int* __restrict__ dst, int E)
{
    int idx = blockIdx.x * blockDim.x + threadIdx.x;
    if (idx < E) atomicAdd(&g_dcz[dst[idx]], 1);
}

// ---------------- kernel C (side stream): HMMA GEMM ----------------
__global__ void __launch_bounds__(256) hgemm_kernel(const float* __restrict__ feat, int M)
{
    __shared__ __half As[128][72];
    __shared__ __half Bs[64][72];
    int tid = threadIdx.x;
    int wid = tid >> 5, lane = tid & 31;
    int brow = blockIdx.x * 128;
    int bcol = blockIdx.y * 64;
    int wm = wid >> 1, wn = wid & 1;

    float acc[2][4][4];
    #pragma unroll
    for (int mt = 0; mt < 2; ++mt)
        #pragma unroll
        for (int nt = 0; nt < 4; ++nt)
            #pragma unroll
            for (int r = 0; r < 4; ++r) acc[mt][nt][r] = 0.f;

    #pragma unroll
    for (int kh = 0; kh < 2; ++kh) {
        #pragma unroll
        for (int it = 0; it < 4; ++it) {
            int q = tid + it * 256;
            int r = q >> 3;
            int c8 = (q & 7) * 8;
            int gr = brow + r;
            uint4 val = make_uint4(0, 0, 0, 0);
            if (gr < M) {
                float4 f0 = *(const float4*)(feat + (size_t)gr * 128 + kh * 64 + c8);
                float4 f1 = *(const float4*)(feat + (size_t)gr * 128 + kh * 64 + c8 + 4);
                __half2 h0 = __floats2half2_rn(f0.x, f0.y);
                __half2 h1 = __floats2half2_rn(f0.z, f0.w);
                __half2 h2 = __floats2half2_rn(f1.x, f1.y);
                __half2 h3 = __floats2half2_rn(f1.z, f1.w);
                val.x = *(unsigned*)&h0; val.y = *(unsigned*)&h1;
                val.z = *(unsigned*)&h2; val.w = *(unsigned*)&h3;
            }
            *(uint4*)&As[r][c8] = val;
        }
        #pragma unroll
        for (int it = 0; it < 2; ++it) {
            int q = tid + it * 256;
            int r = q >> 3;
            int c8 = (q & 7) * 8;
            *(uint4*)&Bs[r][c8] = *(const uint4*)(g_wcath + (size_t)(bcol + r) * 128 + kh * 64 + c8);
        }
        __syncthreads();

        #pragma unroll
        for (int ks = 0; ks < 4; ++ks) {
            int k0 = ks * 16;
            unsigned a[2][4];
            #pragma unroll
            for (int mt = 0; mt < 2; ++mt) {
                int row = wm * 32 + mt * 16 + (lane & 15);
                int col = k0 + ((lane >> 4) << 3);
                unsigned addr = (unsigned)__cvta_generic_to_shared(&As[row][col]);
                asm volatile("ldmatrix.sync.aligned.m8n8.x4.shared.b16 {%0,%1,%2,%3}, [%4];"
                             : "=r"(a[mt][0]), "=r"(a[mt][1]), "=r"(a[mt][2]), "=r"(a[mt][3])
                             : "r"(addr));
            }
            unsigned b[2][4];
            #pragma unroll
            for (int g = 0; g < 2; ++g) {
                int nrow = wn * 32 + g * 16 + (lane & 7) + ((lane >> 4) << 3);
                int col = k0 + (lane & 8);
                unsigned addr = (unsigned)__cvta_generic_to_shared(&Bs[nrow][col]);
                asm volatile("ldmatrix.sync.aligned.m8n8.x4.shared.b16 {%0,%1,%2,%3}, [%4];"
                             : "=r"(b[g][0]), "=r"(b[g][1]), "=r"(b[g][2]), "=r"(b[g][3])
                             : "r"(addr));
            }
            #pragma unroll
            for (int mt = 0; mt < 2; ++mt)
                #pragma unroll
                for (int nt = 0; nt < 4; ++nt) {
                    unsigned b0 = b[nt >> 1][(nt & 1) * 2];
                    unsigned b1 = b[nt >> 1][(nt & 1) * 2 + 1];
                    asm volatile(
                        "mma.sync.aligned.m16n8k16.row.col.f32.f16.f16.f32 "
                        "{%0,%1,%2,%3}, {%4,%5,%6,%7}, {%8,%9}, {%0,%1,%2,%3};"
                        : "+f"(acc[mt][nt][0]), "+f"(acc[mt][nt][1]),
                          "+f"(acc[mt][nt][2]), "+f"(acc[mt][nt][3])
                        : "r"(a[mt][0]), "r"(a[mt][1]), "r"(a[mt][2]), "r"(a[mt][3]),
                          "r"(b0), "r"(b1));
                }
        }
        __syncthreads();
    }

    int gcol0 = bcol + wn * 32;
    __half* dsth; int cstart; int stride;
    if (gcol0 < 64)        { dsth = g_aqh; cstart = gcol0;       stride = 64; }
    else if (gcol0 < 128)  { dsth = g_akh; cstart = gcol0 - 64;  stride = 64; }
    else                   { dsth = g_vh;  cstart = gcol0 - 128; stride = 128; }

    #pragma unroll
    for (int mt = 0; mt < 2; ++mt) {
        int row0 = brow + wm * 32 + mt * 16 + (lane >> 2);
        #pragma unroll
        for (int nt = 0; nt < 4; ++nt) {
            int cc = cstart + nt * 8 + (lane & 3) * 2;
            if (row0 < M) {
                __half2 hv = __floats2half2_rn(acc[mt][nt][0], acc[mt][nt][1]);
                *(__half2*)(dsth + (size_t)row0 * stride + cc) = hv;
            }
            if (row0 + 8 < M) {
                __half2 hv = __floats2half2_rn(acc[mt][nt][2], acc[mt][nt][3]);
                *(__half2*)(dsth + (size_t)(row0 + 8) * stride + cc) = hv;
            }
        }
    }
}

// ---------------- kernel D: fused scan + scatter ----------------
__global__ void __launch_bounds__(256) scan_scatter_kernel(
    const int* __restrict__ src, const int* __restrict__ dst,
    const float* __restrict__ bond, int n, int E, int nscanb)
{
    __shared__ int wsum[8];
    int t = threadIdx.x, lane = t & 31, wid = t >> 5;
    int b = blockIdx.x;

    if (b < nscanb) {
        int i = b * 256 + t;
        int v = (i < n) ? g_dcz[i] : 0;
        int x = v;
        #pragma unroll
        for (int d = 1; d < 32; d <<= 1) {
            int y = __shfl_up_sync(0xffffffffu, x, d);
            if (lane >= d) x += y;
        }
        if (lane == 31) wsum[wid] = x;
        __syncthreads();
        if (wid == 0 && lane < 8) {
            int y = wsum[lane];
            #pragma unroll
            for (int d = 1; d < 8; d <<= 1) {
                int z = __shfl_up_sync(0xffu, y, d);
                if (lane >= d) y += z;
            }
            wsum[lane] = y;
        }
        __syncthreads();
        int excl = ((wid > 0) ? wsum[wid - 1] : 0) + (x - v);
        if (i < n) g_offs[i] = excl;
        if (t == 255) {
            g_bsum[b] = wsum[7];
            __threadfence();
            atomicAdd(&g_dcz[2 * MAXN], 1);
        }
    }

    if (b == 0) {
        if (t == 0) {
            while (*(volatile int*)&g_dcz[2 * MAXN] < nscanb) { }
        }
        __syncthreads();
        __threadfence();
        int vv = (t < nscanb) ? g_bsum[t] : 0;
        int xx = vv;
        #pragma unroll
        for (int d = 1; d < 32; d <<= 1) {
            int y = __shfl_up_sync(0xffffffffu, xx, d);
            if (lane >= d) xx += y;
        }
        __syncthreads();
        if (lane == 31) wsum[wid] = xx;
        __syncthreads();
        if (wid == 0 && lane < 8) {
            int y = wsum[lane];
            #pragma unroll
            for (int d = 1; d < 8; d <<= 1) {
                int z = __shfl_up_sync(0xffu, y, d);
                if (lane >= d) y += z;
            }
            wsum[lane] = y;
        }
        __syncthreads();
        int excl = ((wid > 0) ? wsum[wid - 1] : 0) + (xx - vv);
        if (t < nscanb) g_bbase[t] = excl;
        if (t == 0) {
            g_offs[n] = g_bsum[n >> 8];
            __threadfence();
            atomicExch(&g_dcz[2 * MAXN + 1], 1);
        }
    }

    if (t == 0) {
        while (*(volatile int*)&g_dcz[2 * MAXN + 1] == 0) { }
    }
    __syncthreads();
    __threadfence();

    int e = b * 256 + t;
    if (e >= E) return;
    int d = dst[e];
    int p = g_offs[d] + g_bbase[d >> 8] + atomicAdd(&g_dcz[MAXN + d], 1);
    g_ssrc[p] = src[e];
    const float* bp = bond + (size_t)e * 7;
    float b0 = __ldg(bp + 0), b1 = __ldg(bp + 1), b2 = __ldg(bp + 2), b3 = __ldg(bp + 3);
    float b4 = __ldg(bp + 4), b5 = __ldg(bp + 5), b6 = __ldg(bp + 6);
    __half2 h0 = __floats2half2_rn(b0, b1), h1 = __floats2half2_rn(b2, b3);
    __half2 h2 = __floats2half2_rn(b4, b5), h3 = __floats2half2_rn(b6, 1.f);
    uint4 o;
    o.x = *(unsigned*)&h0; o.y = *(unsigned*)&h1; o.z = *(unsigned*)&h2; o.w = *(unsigned*)&h3;
    *(uint4*)&g_ebondp[(size_t)p * 8] = o;
}

// ---------------- kernel E: persistent edge attention + aggregation (FROZEN) ----------------
__global__ void __launch_bounds__(256, 5) edge_attn_kernel(
    const float* __restrict__ Wefc, const float* __restrict__ befc,
    const float* __restrict__ bias, float* __restrict__ out, int n)
{
    int l = threadIdx.x & 31;
    int h = l >> 2, jl = l & 1;
    int ch = 4 * l;

    __half2 wefh[8][2];
    #pragma unroll
    for (int f = 0; f < 7; ++f) {
        float4 w = *(const float4*)(&Wefc[f * 128 + ch]);
        wefh[f][0] = __floats2half2_rn(w.x, w.y);
        wefh[f][1] = __floats2half2_rn(w.z, w.w);
    }
    {
        float4 w = *(const float4*)(&befc[ch]);
        wefh[7][0] = __floats2half2_rn(w.x, w.y);
        wefh[7][1] = __floats2half2_rn(w.z, w.w);
    }
    float4 b4 = *(const float4*)(&bias[ch]);

    for (;;) {
        int nbase;
        if (l == 0) nbase = atomicAdd(&g_dcz[2 * MAXN + 2], 2);
        nbase = __shfl_sync(0xffffffffu, nbase, 0);
        if (nbase >= n) break;
        int nend = min(nbase + 2, n);

        for (int node = nbase; node < nend; ++node) {
            int start = g_offs[node]     + g_bbase[node >> 8];
            int end   = g_offs[node + 1] + g_bbase[(node + 1) >> 8];

            float2 akf01, akf23;
            {
                uint2 a = *(const uint2*)(g_akh + (size_t)node * 64 + h * 8 + 4 * jl);
                akf01 = __half22float2(*(__half2*)&a.x);
                akf23 = __half22float2(*(__half2*)&a.y);
            }

            float denom = 0.f;
            u64t a2[2] = {0ull, 0ull};

            int s = (start < end) ? __ldg(&g_ssrc[start]) : 0;
            for (int p = start; p < end; ++p) {
                int cs = s;
                s = __ldg(&g_ssrc[p + 1]);

                uint4 eb = *(const uint4*)&g_ebondp[(size_t)p * 8];
                __half2 hb01 = *(__half2*)&eb.x, hb23 = *(__half2*)&eb.y;
                __half2 hb45 = *(__half2*)&eb.z, hb67 = *(__half2*)&eb.w;

                uint2 aqr = *(const uint2*)(g_aqh + (size_t)cs * 64 + h * 8 + 4 * jl);
                uint2 vr  = *(const uint2*)(g_vh  + (size_t)cs * 128 + ch);

                float2 q01 = __half22float2(*(__half2*)&aqr.x);
                float2 q23 = __half22float2(*(__half2*)&aqr.y);
                float2 bb01 = __half22float2(jl ? hb45 : hb01);
                float2 bb23 = __half22float2(jl ? hb67 : hb23);
                float part = bb01.x * (q01.x + akf01.x);
                part = fmaf(bb01.y, q01.y + akf01.y, part);
                part = fmaf(bb23.x, q23.x + akf23.x, part);
                part = fmaf(bb23.y, q23.y + akf23.y, part);
                part += __shfl_xor_sync(0xffffffffu, part, 1);
                float w = __expf(part);
                denom += w;

                __half2 ef0 = wefh[7][0], ef1 = wefh[7][1];
                __half2 b0d = __low2half2(hb01),  b1d = __high2half2(hb01);
                __half2 b2d = __low2half2(hb23),  b3d = __high2half2(hb23);
                __half2 b4d = __low2half2(hb45),  b5d = __high2half2(hb45);
                __half2 b6d = __low2half2(hb67);
                ef0 = __hfma2(b0d, wefh[0][0], ef0); ef1 = __hfma2(b0d, wefh[0][1], ef1);
                ef0 = __hfma2(b1d, wefh[1][0], ef0); ef1 = __hfma2(b1d, wefh[1][1], ef1);
                ef0 = __hfma2(b2d, wefh[2][0], ef0); ef1 = __hfma2(b2d, wefh[2][1], ef1);
                ef0 = __hfma2(b3d, wefh[3][0], ef0); ef1 = __hfma2(b3d, wefh[3][1], ef1);
                ef0 = __hfma2(b4d, wefh[4][0], ef0); ef1 = __hfma2(b4d, wefh[4][1], ef1);
                ef0 = __hfma2(b5d, wefh[5][0], ef0); ef1 = __hfma2(b5d, wefh[5][1], ef1);
                ef0 = __hfma2(b6d, wefh[6][0], ef0); ef1 = __hfma2(b6d, wefh[6][1], ef1);

                __half2 m0 = __hmul2(*(__half2*)&vr.x, ef0);
                __half2 m1 = __hmul2(*(__half2*)&vr.y, ef1);
                float2 mf0 = __half22float2(m0);
                float2 mf1 = __half22float2(m1);
                u64t wd = dup2(w);
                a2[0] = ffma2(wd, pk2(mf0), a2[0]);
                a2[1] = ffma2(wd, pk2(mf1), a2[1]);
            }

            float4 r;
            if (end > start) {
                float inv = 1.0f / denom;
                float2 lo = unpack2(a2[0]), hi = unpack2(a2[1]);
                r.x = fmaf(lo.x, inv, b4.x);
                r.y = fmaf(lo.y, inv, b4.y);
                r.z = fmaf(hi.x, inv, b4.z);
                r.w = fmaf(hi.y, inv, b4.w);
            } else {
                r = b4;
            }
            *(float4*)(&out[(size_t)node * 128 + ch]) = r;
        }
    }
}

// ---------------- host launcher ----------------
extern "C" void kernel_launch(void* const* d_in, const int* in_sizes, int n_in,
                              void* d_out, int out_size)
{
    const float* feat = (const float*)d_in[0];
    const float* bond = (const float*)d_in[1];
    const int*   src  = (const int*)d_in[2];
    const int*   dst  = (const int*)d_in[3];
    const float* Wq   = (const float*)d_in[4];
    const float* Wk   = (const float*)d_in[5];
    const float* Wv   = (const float*)d_in[6];
    const float* Wek  = (const float*)d_in[7];
    const float* bek  = (const float*)d_in[8];
    const float* Wefc = (const float*)d_in[9];
    const float* befc = (const float*)d_in[10];
    const float* bias = (const float*)d_in[11];
    float* out = (float*)d_out;

    int N = in_sizes[0] / INF_DIM;   // 50000
    int E = in_sizes[2];             // 800000
    int nscanb = (N + 255) / 256;    // 196

    void* dcz_ptr = nullptr;
    cudaGetSymbolAddress(&dcz_ptr, g_dcz);

    cudaStream_t s1;
    cudaStreamCreateWithFlags(&s1, cudaStreamNonBlocking);
    cudaEvent_t evZero, evJoin;
    cudaEventCreateWithFlags(&evZero, cudaEventDisableTiming);
    cudaEventCreateWithFlags(&evJoin, cudaEventDisableTiming);

    // #1: memset (main)
    cudaMemsetAsync(dcz_ptr, 0, (size_t)(2 * MAXN + 3) * sizeof(int), 0);
    cudaEventRecord(evZero, 0);
    cudaStreamWaitEvent(s1, evZero, 0);
    // #2 (side): tiny wcat prep — no dependency on edges
    wcat_prep_kernel<<<(INF_DIM * NCOLS + 255) / 256, 256, 0, s1>>>(Wq, Wk, Wv, Wek, bek);
    // #3 (side): tensor-core GEMM — overlaps the whole CSR chain below
    dim3 ggrid((N + 127) / 128, 4);
    hgemm_kernel<<<ggrid, 256, 0, s1>>>(feat, N);
    cudaEventRecord(evJoin, s1);
    // #4 (main): degree atomics
    deg_kernel<<<(E + 255) / 256, 256>>>(dst, E);
    // #5 (main): fused scan + scatter  (ncu profiles this submission)
    scan_scatter_kernel<<<(E + 255) / 256, 256>>>(src, dst, bond, N, E, nscanb);
    cudaStreamWaitEvent(0, evJoin, 0);
    // #6 (main): persistent edge attention (frozen)
    edge_attn_kernel<<<148 * 5, 256>>>(Wefc, befc, bias, out, N);

    cudaEventDestroy(evZero);
    cudaEventDestroy(evJoin);
    cudaStreamDestroy(s1);
}

// round 16
// speedup vs baseline: 2.0538x; 1.0051x over previous
#include <cuda_runtime.h>
#include <cuda_fp16.h>
#include <math.h>

// N=50000, E=800000, IN=128, H=8, EMB=32, OUT=16, EF=7
#define MAXN 50000
#define MAXE 800000
#define INF_DIM 128
#define NCOLS 256          // wcat cols: WqA(64) | WkA(64) | Wv(128)
#define CSRB 592           // persistent CSR blocks (148 SM x 4, guaranteed resident)

typedef unsigned long long u64t;

__device__ __forceinline__ u64t dup2(float x) {
    u64t r; asm("mov.b64 %0, {%1, %1};" : "=l"(r) : "f"(x)); return r;
}
__device__ __forceinline__ u64t pk2(float2 f) {
    u64t r; asm("mov.b64 %0, {%1, %2};" : "=l"(r) : "f"(f.x), "f"(f.y)); return r;
}
__device__ __forceinline__ u64t ffma2(u64t a, u64t b, u64t c) {
    u64t d; asm("fma.rn.f32x2 %0, %1, %2, %3;" : "=l"(d) : "l"(a), "l"(b), "l"(c)); return d;
}
__device__ __forceinline__ float2 unpack2(u64t a) {
    float2 f; asm("mov.b64 {%0, %1}, %2;" : "=f"(f.x), "=f"(f.y) : "l"(a)); return f;
}

// -------- device scratch --------
// g_dcz: [0,MAXN)=deg, [MAXN,2MAXN)=cnt, [2MAXN]=bar1 ctr, [2MAXN+1]=scan-done ctr,
//        [2MAXN+2]=ready flag, [2MAXN+3]=edge work ctr
__device__ int    g_dcz[2 * MAXN + 4];
__device__ int    g_offs[MAXN + 1];
__device__ int    g_bsum[256];
__device__ int    g_bbase[256];
__device__ int    g_ssrc[MAXE + 1];                    // +1 pad: branch-free prefetch
__device__ __half g_ebondp[(size_t)MAXE * 8];          // CSR-permuted packed bond: b0..b6, 1.0
__device__ __half g_aqh[(size_t)MAXN * 64];            // Aq fp16, head-major [N][H][8]
__device__ __half g_akh[(size_t)MAXN * 64];            // Ak fp16, head-major
__device__ __half g_vh [(size_t)MAXN * 128];           // v  fp16 [N][128]
__device__ __half g_wcath[NCOLS * INF_DIM];            // wcat fp16, TRANSPOSED [n=256][k=128]

// ---------------- kernel 1 (side): wcat^T fp16 ----------------
__global__ void wcat_prep_kernel(const float* __restrict__ Wq, const float* __restrict__ Wk,
                                 const float* __restrict__ Wv, const float* __restrict__ Wek,
                                 const float* __restrict__ bek)
{
    int idx = blockIdx.x * blockDim.x + threadIdx.x;
    if (idx < INF_DIM * NCOLS) {
        int i = idx >> 8;        // k
        int c = idx & 255;       // n
        float r;
        if (c < 128) {
            const float* Wx = (c < 64) ? Wq : Wk;
            int cc = c & 63;
            int h = cc >> 3, f = cc & 7;
            const float* ekrow = (f < 7) ? (Wek + f * 256) : bek;
            float acc = 0.f;
            #pragma unroll
            for (int m = 0; m < 32; ++m)
                acc = fmaf(Wx[i * 256 + h * 32 + m], ekrow[h * 32 + m], acc);
            r = acc;
        } else {
            r = Wv[i * 128 + (c - 128)];
        }
        g_wcath[c * INF_DIM + i] = __float2half(r);
    }
}

// ---------------- kernel 2 (side): HMMA GEMM ----------------
__global__ void __launch_bounds__(256) hgemm_kernel(const float* __restrict__ feat, int M)
{
    __shared__ __half As[128][72];
    __shared__ __half Bs[64][72];
    int tid = threadIdx.x;
    int wid = tid >> 5, lane = tid & 31;
    int brow = blockIdx.x * 128;
    int bcol = blockIdx.y * 64;
    int wm = wid >> 1, wn = wid & 1;

    float acc[2][4][4];
    #pragma unroll
    for (int mt = 0; mt < 2; ++mt)
        #pragma unroll
        for (int nt = 0; nt < 4; ++nt)
            #pragma unroll
            for (int r = 0; r < 4; ++r) acc[mt][nt][r] = 0.f;

    #pragma unroll
    for (int kh = 0; kh < 2; ++kh) {
        #pragma unroll
        for (int it = 0; it < 4; ++it) {
            int q = tid + it * 256;
            int r = q >> 3;
            int c8 = (q & 7) * 8;
            int gr = brow + r;
            uint4 val = make_uint4(0, 0, 0, 0);
            if (gr < M) {
                float4 f0 = *(const float4*)(feat + (size_t)gr * 128 + kh * 64 + c8);
                float4 f1 = *(const float4*)(feat + (size_t)gr * 128 + kh * 64 + c8 + 4);
                __half2 h0 = __floats2half2_rn(f0.x, f0.y);
                __half2 h1 = __floats2half2_rn(f0.z, f0.w);
                __half2 h2 = __floats2half2_rn(f1.x, f1.y);
                __half2 h3 = __floats2half2_rn(f1.z, f1.w);
                val.x = *(unsigned*)&h0; val.y = *(unsigned*)&h1;
                val.z = *(unsigned*)&h2; val.w = *(unsigned*)&h3;
            }
            *(uint4*)&As[r][c8] = val;
        }
        #pragma unroll
        for (int it = 0; it < 2; ++it) {
            int q = tid + it * 256;
            int r = q >> 3;
            int c8 = (q & 7) * 8;
            *(uint4*)&Bs[r][c8] = *(const uint4*)(g_wcath + (size_t)(bcol + r) * 128 + kh * 64 + c8);
        }
        __syncthreads();

        #pragma unroll
        for (int ks = 0; ks < 4; ++ks) {
            int k0 = ks * 16;
            unsigned a[2][4];
            #pragma unroll
            for (int mt = 0; mt < 2; ++mt) {
                int row = wm * 32 + mt * 16 + (lane & 15);
                int col = k0 + ((lane >> 4) << 3);
                unsigned addr = (unsigned)__cvta_generic_to_shared(&As[row][col]);
                asm volatile("ldmatrix.sync.aligned.m8n8.x4.shared.b16 {%0,%1,%2,%3}, [%4];"
                             : "=r"(a[mt][0]), "=r"(a[mt][1]), "=r"(a[mt][2]), "=r"(a[mt][3])
                             : "r"(addr));
            }
            unsigned b[2][4];
            #pragma unroll
            for (int g = 0; g < 2; ++g) {
                int nrow = wn * 32 + g * 16 + (lane & 7) + ((lane >> 4) << 3);
                int col = k0 + (lane & 8);
                unsigned addr = (unsigned)__cvta_generic_to_shared(&Bs[nrow][col]);
                asm volatile("ldmatrix.sync.aligned.m8n8.x4.shared.b16 {%0,%1,%2,%3}, [%4];"
                             : "=r"(b[g][0]), "=r"(b[g][1]), "=r"(b[g][2]), "=r"(b[g][3])
                             : "r"(addr));
            }
            #pragma unroll
            for (int mt = 0; mt < 2; ++mt)
                #pragma unroll
                for (int nt = 0; nt < 4; ++nt) {
                    unsigned b0 = b[nt >> 1][(nt & 1) * 2];
                    unsigned b1 = b[nt >> 1][(nt & 1) * 2 + 1];
                    asm volatile(
                        "mma.sync.aligned.m16n8k16.row.col.f32.f16.f16.f32 "
                        "{%0,%1,%2,%3}, {%4,%5,%6,%7}, {%8,%9}, {%0,%1,%2,%3};"
                        : "+f"(acc[mt][nt][0]), "+f"(acc[mt][nt][1]),
                          "+f"(acc[mt][nt][2]), "+f"(acc[mt][nt][3])
                        : "r"(a[mt][0]), "r"(a[mt][1]), "r"(a[mt][2]), "r"(a[mt][3]),
                          "r"(b0), "r"(b1));
                }
        }
        __syncthreads();
    }

    int gcol0 = bcol + wn * 32;
    __half* dsth; int cstart; int stride;
    if (gcol0 < 64)        { dsth = g_aqh; cstart = gcol0;       stride = 64; }
    else if (gcol0 < 128)  { dsth = g_akh; cstart = gcol0 - 64;  stride = 64; }
    else                   { dsth = g_vh;  cstart = gcol0 - 128; stride = 128; }

    #pragma unroll
    for (int mt = 0; mt < 2; ++mt) {
        int row0 = brow + wm * 32 + mt * 16 + (lane >> 2);
        #pragma unroll
        for (int nt = 0; nt < 4; ++nt) {
            int cc = cstart + nt * 8 + (lane & 3) * 2;
            if (row0 < M) {
                __half2 hv = __floats2half2_rn(acc[mt][nt][0], acc[mt][nt][1]);
                *(__half2*)(dsth + (size_t)row0 * stride + cc) = hv;
            }
            if (row0 + 8 < M) {
                __half2 hv = __floats2half2_rn(acc[mt][nt][2], acc[mt][nt][3]);
                *(__half2*)(dsth + (size_t)(row0 + 8) * stride + cc) = hv;
            }
        }
    }
}

// ---------------- kernel 3: persistent CSR build (deg -> scan -> scatter) ----------------
// CSRB resident blocks; grid barriers via global counters (all blocks resident by
// construction: 256 thr, <=64 regs, 4 blocks/SM).
__global__ void __launch_bounds__(256, 4) csr_kernel(
    const int* __restrict__ src, const int* __restrict__ dst,
    const float* __restrict__ bond, int n, int E, int nscanb)
{
    __shared__ int wsum[8];
    int t = threadIdx.x, lane = t & 31, wid = t >> 5;
    int b = blockIdx.x;

    // ---- phase 1: degree atomics (grid-stride) ----
    for (int e = b * 256 + t; e < E; e += CSRB * 256)
        atomicAdd(&g_dcz[dst[e]], 1);

    // grid barrier 1
    __syncthreads();
    if (t == 0) {
        __threadfence();
        atomicAdd(&g_dcz[2 * MAXN], 1);
        while (*(volatile int*)&g_dcz[2 * MAXN] < CSRB) { }
    }
    __syncthreads();
    __threadfence();

    // ---- phase 2: scan (blocks 0..nscanb-1), block 0 finishes bases ----
    if (b < nscanb) {
        int i = b * 256 + t;
        int v = (i < n) ? g_dcz[i] : 0;
        int x = v;
        #pragma unroll
        for (int d = 1; d < 32; d <<= 1) {
            int y = __shfl_up_sync(0xffffffffu, x, d);
            if (lane >= d) x += y;
        }
        if (lane == 31) wsum[wid] = x;
        __syncthreads();
        if (wid == 0 && lane < 8) {
            int y = wsum[lane];
            #pragma unroll
            for (int d = 1; d < 8; d <<= 1) {
                int z = __shfl_up_sync(0xffu, y, d);
                if (lane >= d) y += z;
            }
            wsum[lane] = y;
        }
        __syncthreads();
        int excl = ((wid > 0) ? wsum[wid - 1] : 0) + (x - v);
        if (i < n) g_offs[i] = excl;
        if (t == 255) {
            g_bsum[b] = wsum[7];
            __threadfence();
            atomicAdd(&g_dcz[2 * MAXN + 1], 1);
        }
        __syncthreads();   // wsum reuse safety for block 0
    }

    if (b == 0) {
        if (t == 0) {
            while (*(volatile int*)&g_dcz[2 * MAXN + 1] < nscanb) { }
        }
        __syncthreads();
        __threadfence();
        int vv = (t < nscanb) ? g_bsum[t] : 0;
        int xx = vv;
        #pragma unroll
        for (int d = 1; d < 32; d <<= 1) {
            int y = __shfl_up_sync(0xffffffffu, xx, d);
            if (lane >= d) xx += y;
        }
        if (lane == 31) wsum[wid] = xx;
        __syncthreads();
        if (wid == 0 && lane < 8) {
            int y = wsum[lane];
            #pragma unroll
            for (int d = 1; d < 8; d <<= 1) {
                int z = __shfl_up_sync(0xffu, y, d);
                if (lane >= d) y += z;
            }
            wsum[lane] = y;
        }
        __syncthreads();
        int excl = ((wid > 0) ? wsum[wid - 1] : 0) + (xx - vv);
        if (t < nscanb) g_bbase[t] = excl;
        if (t == 0) {
            g_offs[n] = g_bsum[n >> 8];
            __threadfence();
            atomicExch(&g_dcz[2 * MAXN + 2], 1);
        }
    }

    // grid barrier 2: wait for bases
    if (t == 0) {
        while (*(volatile int*)&g_dcz[2 * MAXN + 2] == 0) { }
    }
    __syncthreads();
    __threadfence();

    // ---- phase 3: scatter (grid-stride; independent chains per iteration) ----
    for (int e = b * 256 + t; e < E; e += CSRB * 256) {
        int d = dst[e];
        int p = g_offs[d] + g_bbase[d >> 8] + atomicAdd(&g_dcz[MAXN + d], 1);
        g_ssrc[p] = src[e];
        const float* bp = bond + (size_t)e * 7;
        float b0 = __ldg(bp + 0), b1 = __ldg(bp + 1), b2 = __ldg(bp + 2), b3 = __ldg(bp + 3);
        float b4 = __ldg(bp + 4), b5 = __ldg(bp + 5), b6 = __ldg(bp + 6);
        __half2 h0 = __floats2half2_rn(b0, b1), h1 = __floats2half2_rn(b2, b3);
        __half2 h2 = __floats2half2_rn(b4, b5), h3 = __floats2half2_rn(b6, 1.f);
        uint4 o;
        o.x = *(unsigned*)&h0; o.y = *(unsigned*)&h1; o.z = *(unsigned*)&h2; o.w = *(unsigned*)&h3;
        *(uint4*)&g_ebondp[(size_t)p * 8] = o;
    }
}

// ---------------- kernel 4: persistent edge attention + aggregation (FROZEN) ----------------
__global__ void __launch_bounds__(256, 5) edge_attn_kernel(
    const float* __restrict__ Wefc, const float* __restrict__ befc,
    const float* __restrict__ bias, float* __restrict__ out, int n)
{
    int l = threadIdx.x & 31;
    int h = l >> 2, jl = l & 1;
    int ch = 4 * l;

    __half2 wefh[8][2];
    #pragma unroll
    for (int f = 0; f < 7; ++f) {
        float4 w = *(const float4*)(&Wefc[f * 128 + ch]);
        wefh[f][0] = __floats2half2_rn(w.x, w.y);
        wefh[f][1] = __floats2half2_rn(w.z, w.w);
    }
    {
        float4 w = *(const float4*)(&befc[ch]);
        wefh[7][0] = __floats2half2_rn(w.x, w.y);
        wefh[7][1] = __floats2half2_rn(w.z, w.w);
    }
    float4 b4 = *(const float4*)(&bias[ch]);

    for (;;) {
        int nbase;
        if (l == 0) nbase = atomicAdd(&g_dcz[2 * MAXN + 3], 2);
        nbase = __shfl_sync(0xffffffffu, nbase, 0);
        if (nbase >= n) break;
        int nend = min(nbase + 2, n);

        for (int node = nbase; node < nend; ++node) {
            int start = g_offs[node]     + g_bbase[node >> 8];
            int end   = g_offs[node + 1] + g_bbase[(node + 1) >> 8];

            float2 akf01, akf23;
            {
                uint2 a = *(const uint2*)(g_akh + (size_t)node * 64 + h * 8 + 4 * jl);
                akf01 = __half22float2(*(__half2*)&a.x);
                akf23 = __half22float2(*(__half2*)&a.y);
            }

            float denom = 0.f;
            u64t a2[2] = {0ull, 0ull};

            int s = (start < end) ? __ldg(&g_ssrc[start]) : 0;
            for (int p = start; p < end; ++p) {
                int cs = s;
                s = __ldg(&g_ssrc[p + 1]);

                uint4 eb = *(const uint4*)&g_ebondp[(size_t)p * 8];
                __half2 hb01 = *(__half2*)&eb.x, hb23 = *(__half2*)&eb.y;
                __half2 hb45 = *(__half2*)&eb.z, hb67 = *(__half2*)&eb.w;

                uint2 aqr = *(const uint2*)(g_aqh + (size_t)cs * 64 + h * 8 + 4 * jl);
                uint2 vr  = *(const uint2*)(g_vh  + (size_t)cs * 128 + ch);

                float2 q01 = __half22float2(*(__half2*)&aqr.x);
                float2 q23 = __half22float2(*(__half2*)&aqr.y);
                float2 bb01 = __half22float2(jl ? hb45 : hb01);
                float2 bb23 = __half22float2(jl ? hb67 : hb23);
                float part = bb01.x * (q01.x + akf01.x);
                part = fmaf(bb01.y, q01.y + akf01.y, part);
                part = fmaf(bb23.x, q23.x + akf23.x, part);
                part = fmaf(bb23.y, q23.y + akf23.y, part);
                part += __shfl_xor_sync(0xffffffffu, part, 1);
                float w = __expf(part);
                denom += w;

                __half2 ef0 = wefh[7][0], ef1 = wefh[7][1];
                __half2 b0d = __low2half2(hb01),  b1d = __high2half2(hb01);
                __half2 b2d = __low2half2(hb23),  b3d = __high2half2(hb23);
                __half2 b4d = __low2half2(hb45),  b5d = __high2half2(hb45);
                __half2 b6d = __low2half2(hb67);
                ef0 = __hfma2(b0d, wefh[0][0], ef0); ef1 = __hfma2(b0d, wefh[0][1], ef1);
                ef0 = __hfma2(b1d, wefh[1][0], ef0); ef1 = __hfma2(b1d, wefh[1][1], ef1);
                ef0 = __hfma2(b2d, wefh[2][0], ef0); ef1 = __hfma2(b2d, wefh[2][1], ef1);
                ef0 = __hfma2(b3d, wefh[3][0], ef0); ef1 = __hfma2(b3d, wefh[3][1], ef1);
                ef0 = __hfma2(b4d, wefh[4][0], ef0); ef1 = __hfma2(b4d, wefh[4][1], ef1);
                ef0 = __hfma2(b5d, wefh[5][0], ef0); ef1 = __hfma2(b5d, wefh[5][1], ef1);
                ef0 = __hfma2(b6d, wefh[6][0], ef0); ef1 = __hfma2(b6d, wefh[6][1], ef1);

                __half2 m0 = __hmul2(*(__half2*)&vr.x, ef0);
                __half2 m1 = __hmul2(*(__half2*)&vr.y, ef1);
                float2 mf0 = __half22float2(m0);
                float2 mf1 = __half22float2(m1);
                u64t wd = dup2(w);
                a2[0] = ffma2(wd, pk2(mf0), a2[0]);
                a2[1] = ffma2(wd, pk2(mf1), a2[1]);
            }

            float4 r;
            if (end > start) {
                float inv = 1.0f / denom;
                float2 lo = unpack2(a2[0]), hi = unpack2(a2[1]);
                r.x = fmaf(lo.x, inv, b4.x);
                r.y = fmaf(lo.y, inv, b4.y);
                r.z = fmaf(hi.x, inv, b4.z);
                r.w = fmaf(hi.y, inv, b4.w);
            } else {
                r = b4;
            }
            *(float4*)(&out[(size_t)node * 128 + ch]) = r;
        }
    }
}

// ---------------- host launcher ----------------
extern "C" void kernel_launch(void* const* d_in, const int* in_sizes, int n_in,
                              void* d_out, int out_size)
{
    const float* feat = (const float*)d_in[0];
    const float* bond = (const float*)d_in[1];
    const int*   src  = (const int*)d_in[2];
    const int*   dst  = (const int*)d_in[3];
    const float* Wq   = (const float*)d_in[4];
    const float* Wk   = (const float*)d_in[5];
    const float* Wv   = (const float*)d_in[6];
    const float* Wek  = (const float*)d_in[7];
    const float* bek  = (const float*)d_in[8];
    const float* Wefc = (const float*)d_in[9];
    const float* befc = (const float*)d_in[10];
    const float* bias = (const float*)d_in[11];
    float* out = (float*)d_out;

    int N = in_sizes[0] / INF_DIM;   // 50000
    int E = in_sizes[2];             // 800000
    int nscanb = (N + 255) / 256;    // 196

    void* dcz_ptr = nullptr;
    cudaGetSymbolAddress(&dcz_ptr, g_dcz);

    cudaStream_t s1;
    cudaStreamCreateWithFlags(&s1, cudaStreamNonBlocking);
    cudaEvent_t evZero, evJoin;
    cudaEventCreateWithFlags(&evZero, cudaEventDisableTiming);
    cudaEventCreateWithFlags(&evJoin, cudaEventDisableTiming);

    // memset: deg + cnt + barriers + work ctr
    cudaMemsetAsync(dcz_ptr, 0, (size_t)(2 * MAXN + 4) * sizeof(int), 0);
    cudaEventRecord(evZero, 0);
    cudaStreamWaitEvent(s1, evZero, 0);
    // #1 (side): wcat prep
    wcat_prep_kernel<<<(INF_DIM * NCOLS + 255) / 256, 256, 0, s1>>>(Wq, Wk, Wv, Wek, bek);
    // #2 (side): tensor-core GEMM — overlaps the whole CSR build
    dim3 ggrid((N + 127) / 128, 4);
    hgemm_kernel<<<ggrid, 256, 0, s1>>>(feat, N);
    cudaEventRecord(evJoin, s1);
    // #3 (main): persistent CSR build (deg -> scan -> scatter)
    csr_kernel<<<CSRB, 256>>>(src, dst, bond, N, E, nscanb);
    cudaStreamWaitEvent(0, evJoin, 0);
    // #4 (main): persistent edge attention (profiled by ncu; frozen)
    edge_attn_kernel<<<148 * 5, 256>>>(Wefc, befc, bias, out, N);

    cudaEventDestroy(evZero);
    cudaEventDestroy(evJoin);
    cudaStreamDestroy(s1);
}